// round 11
// baseline (speedup 1.0000x reference)
#include <cuda_runtime.h>
#include <cuda_bf16.h>
#include <math.h>
#include <stdint.h>

#define BATCH 16
#define CCH   256
#define NSP   4096   // 64*64
#define CSP   32     // C/8
#define NPOOL 1024   // 32*32

// ---------------- scratch ----------------
__device__ float g_kT[BATCH * NSP * CSP];                    //  8 MB tf32 (B, n, 32)
__device__ float g_qT[BATCH * NPOOL * CSP];                  //  2 MB tf32 (B, np, 32)
__device__ float g_wor[CCH * CCH];                           // 256 KB tf32-RN wo
__device__ float g_vpool[BATCH * CCH * NPOOL];               // 16 MB (tf32-RN values)
__device__ float g_vprime[BATCH * CCH * NPOOL];              // 16 MB
__device__ float g_part[BATCH * 32 * NPOOL];                 //  2 MB
__device__ float g_invden[BATCH * NPOOL];                    // 64 KB
__device__ __nv_bfloat16 g_attnh[(size_t)BATCH * NSP * NPOOL]; // 128 MB
__device__ __nv_bfloat16 g_vppb[BATCH * CCH * NPOOL];        //  8 MB

// ---------------- helpers ----------------
__device__ __forceinline__ float tf32_rn(float v) {
    uint32_t u;
    asm("cvt.rna.tf32.f32 %0, %1;" : "=r"(u) : "f"(v));
    return __uint_as_float(u);
}
__device__ __forceinline__ void mma_tf32(float* c, const uint32_t* a, const uint32_t* b) {
    asm volatile(
        "mma.sync.aligned.m16n8k8.row.col.f32.tf32.tf32.f32 "
        "{%0,%1,%2,%3}, {%4,%5,%6,%7}, {%8,%9}, {%0,%1,%2,%3};"
        : "+f"(c[0]), "+f"(c[1]), "+f"(c[2]), "+f"(c[3])
        : "r"(a[0]), "r"(a[1]), "r"(a[2]), "r"(a[3]), "r"(b[0]), "r"(b[1]));
}
__device__ __forceinline__ void mma_bf16(float* c, const uint32_t* a, const uint32_t* b) {
    asm volatile(
        "mma.sync.aligned.m16n8k16.row.col.f32.bf16.bf16.f32 "
        "{%0,%1,%2,%3}, {%4,%5,%6,%7}, {%8,%9}, {%0,%1,%2,%3};"
        : "+f"(c[0]), "+f"(c[1]), "+f"(c[2]), "+f"(c[3])
        : "r"(a[0]), "r"(a[1]), "r"(a[2]), "r"(a[3]), "r"(b[0]), "r"(b[1]));
}
__device__ __forceinline__ void cpa16(uint32_t dst, const void* src) {
    asm volatile("cp.async.cg.shared.global [%0], [%1], 16;" :: "r"(dst), "l"(src));
}

// ---------------- pre-round wo to tf32-RN (tiny; feeds vprime cp.async path) --
__global__ void round_wo_k(const float* __restrict__ wo, float* __restrict__ wor)
{
    int i = (blockIdx.x * 256 + threadIdx.x) * 4;
    float4 b = *(const float4*)&wo[i];
    b.x = tf32_rn(b.x); b.y = tf32_rn(b.y); b.z = tf32_rn(b.z); b.w = tf32_rn(b.w);
    *(float4*)&wor[i] = b;
}

// ============ fused conv_q + conv_k + conv_v via tf32 mma ============
// grid (NSP/128, 3, BATCH)
// y=0 : kT (B,n,32) + pooled qT (B,np,32)            [conv_qk body]
// y=1,2: vpool rows (y-1)*128..  (maxpool epilogue)  [conv_v body]
__global__ __launch_bounds__(256)
void conv_qkv_mma(const float* __restrict__ wk, const float* __restrict__ bk,
                  const float* __restrict__ wq, const float* __restrict__ bq,
                  const float* __restrict__ wv, const float* __restrict__ bv,
                  const float* __restrict__ x,
                  float* __restrict__ kT, float* __restrict__ qT,
                  float* __restrict__ vpool)
{
    __shared__ union {
        struct { float sA[64 * 20];  float sB[128 * 20]; } l0;   // y=0 loader
        struct { float sA[128 * 20]; float sB[16 * 136]; } l1;   // y>0 loader
        float sOut[64 * 132];                                    // y=0 epilogue
        float sX[32 * 132];                                      // y>0 pool staging
    } sh;

    const int b    = blockIdx.z;
    const int y    = blockIdx.y;
    const int col0 = blockIdx.x * 128;
    const float* xb = x + (size_t)b * CCH * NSP;
    const int tid = threadIdx.x, lane = tid & 31, wid = tid >> 5;
    const int wr = wid >> 2, wc = wid & 3;
    const int g = lane >> 2, tk = lane & 3;

    if (y == 0) {
        // ---------------- conv_qk (proven body) ----------------
        float cf[2][4][4] = {};

        for (int k0 = 0; k0 < CCH; k0 += 16) {
            {
                int r = tid >> 2, kq = (tid & 3) * 4;
                const float* wrow = (r < 32) ? (wk + r * CCH) : (wq + (r - 32) * CCH);
                float4 v = *(const float4*)&wrow[k0 + kq];
                v.x = tf32_rn(v.x); v.y = tf32_rn(v.y);
                v.z = tf32_rn(v.z); v.w = tf32_rn(v.w);
                *(float4*)&sh.l0.sA[r * 20 + kq] = v;
            }
#pragma unroll
            for (int u = 0; u < 2; u++) {
                int idx = tid + u * 256;
                int kr = idx >> 5, nc = (idx & 31) * 4;
                float4 v = *(const float4*)&xb[(size_t)(k0 + kr) * NSP + col0 + nc];
                sh.l0.sB[(nc + 0) * 20 + kr] = tf32_rn(v.x);
                sh.l0.sB[(nc + 1) * 20 + kr] = tf32_rn(v.y);
                sh.l0.sB[(nc + 2) * 20 + kr] = tf32_rn(v.z);
                sh.l0.sB[(nc + 3) * 20 + kr] = tf32_rn(v.w);
            }
            __syncthreads();
#pragma unroll
            for (int ks = 0; ks < 2; ks++) {
                const int ko = ks * 8;
                uint32_t a[2][4], bf[4][2];
#pragma unroll
                for (int i = 0; i < 2; i++) {
                    const int ra = (wr * 32 + i * 16 + g) * 20 + ko + tk;
                    a[i][0] = __float_as_uint(sh.l0.sA[ra]);
                    a[i][1] = __float_as_uint(sh.l0.sA[ra + 8 * 20]);
                    a[i][2] = __float_as_uint(sh.l0.sA[ra + 4]);
                    a[i][3] = __float_as_uint(sh.l0.sA[ra + 8 * 20 + 4]);
                }
#pragma unroll
                for (int j = 0; j < 4; j++) {
                    const int rb = (wc * 32 + j * 8 + g) * 20 + ko + tk;
                    bf[j][0] = __float_as_uint(sh.l0.sB[rb]);
                    bf[j][1] = __float_as_uint(sh.l0.sB[rb + 4]);
                }
#pragma unroll
                for (int i = 0; i < 2; i++)
#pragma unroll
                    for (int j = 0; j < 4; j++) mma_tf32(cf[i][j], a[i], bf[j]);
            }
            __syncthreads();
        }

#pragma unroll
        for (int i = 0; i < 2; i++)
#pragma unroll
            for (int half = 0; half < 2; half++) {
                const int r = wr * 32 + i * 16 + half * 8 + g;
#pragma unroll
                for (int j = 0; j < 4; j++) {
                    const int c = wc * 32 + j * 8 + 2 * tk;
                    sh.sOut[r * 132 + c]     = cf[i][j][half * 2 + 0];
                    sh.sOut[r * 132 + c + 1] = cf[i][j][half * 2 + 1];
                }
            }
        __syncthreads();

        float* kTb = kT + (size_t)b * NSP * CSP;
#pragma unroll
        for (int u = 0; u < 4; u++) {
            int idx = tid + u * 256;
            int nn = idx >> 3, csq = (idx & 7) * 4;
            float4 o;
            o.x = tf32_rn(sh.sOut[(csq + 0) * 132 + nn] + bk[csq + 0]);
            o.y = tf32_rn(sh.sOut[(csq + 1) * 132 + nn] + bk[csq + 1]);
            o.z = tf32_rn(sh.sOut[(csq + 2) * 132 + nn] + bk[csq + 2]);
            o.w = tf32_rn(sh.sOut[(csq + 3) * 132 + nn] + bk[csq + 3]);
            *(float4*)&kTb[(size_t)(col0 + nn) * CSP + csq] = o;
        }

        float* qTb = qT + (size_t)b * NPOOL * CSP;
        const int hp = col0 >> 7;
        {
            int wp = tid >> 3, csq = (tid & 7) * 4;
            float4 o;
            float* oc = &o.x;
#pragma unroll
            for (int t = 0; t < 4; t++) {
                const int cs = csq + t;
                const float* r = &sh.sOut[(32 + cs) * 132];
                float v = fmaxf(fmaxf(r[2 * wp], r[2 * wp + 1]),
                                fmaxf(r[64 + 2 * wp], r[64 + 2 * wp + 1]));
                oc[t] = tf32_rn(v + bq[cs]);
            }
            *(float4*)&qTb[(size_t)(hp * 32 + wp) * CSP + csq] = o;
        }
    } else {
        // ---------------- conv_v slice: rows r0..r0+127 of wv ----------------
        const int r0 = (y - 1) * 128;
        float cf[4][4][4] = {};

        for (int k0 = 0; k0 < CCH; k0 += 16) {
            {   // A: 128 rows x 16 k from wv (RN-rounded)
                int r = tid >> 1, kq = (tid & 1) * 8;
#pragma unroll
                for (int q = 0; q < 2; q++) {
                    float4 v = *(const float4*)&wv[(size_t)(r0 + r) * CCH + k0 + kq + q * 4];
                    v.x = tf32_rn(v.x); v.y = tf32_rn(v.y);
                    v.z = tf32_rn(v.z); v.w = tf32_rn(v.w);
                    *(float4*)&sh.l1.sA[r * 20 + kq + q * 4] = v;
                }
            }
#pragma unroll
            for (int u = 0; u < 2; u++) {   // B: 16 k x 128 n natural layout (RN-rounded)
                int idx = tid + u * 256;
                int kr = idx >> 5, nc = (idx & 31) * 4;
                float4 v = *(const float4*)&xb[(size_t)(k0 + kr) * NSP + col0 + nc];
                v.x = tf32_rn(v.x); v.y = tf32_rn(v.y);
                v.z = tf32_rn(v.z); v.w = tf32_rn(v.w);
                *(float4*)&sh.l1.sB[kr * 136 + nc] = v;
            }
            __syncthreads();
#pragma unroll
            for (int ks = 0; ks < 2; ks++) {
                const int ko = ks * 8;
                uint32_t a[4][4], bf[4][2];
#pragma unroll
                for (int i = 0; i < 4; i++) {
                    const int ra = (wr * 64 + i * 16 + g) * 20 + ko + tk;
                    a[i][0] = __float_as_uint(sh.l1.sA[ra]);
                    a[i][1] = __float_as_uint(sh.l1.sA[ra + 8 * 20]);
                    a[i][2] = __float_as_uint(sh.l1.sA[ra + 4]);
                    a[i][3] = __float_as_uint(sh.l1.sA[ra + 8 * 20 + 4]);
                }
#pragma unroll
                for (int j = 0; j < 4; j++) {
                    const int nn = wc * 32 + j * 8 + g;
                    bf[j][0] = __float_as_uint(sh.l1.sB[(ko + tk) * 136 + nn]);
                    bf[j][1] = __float_as_uint(sh.l1.sB[(ko + tk + 4) * 136 + nn]);
                }
#pragma unroll
                for (int i = 0; i < 4; i++)
#pragma unroll
                    for (int j = 0; j < 4; j++) mma_tf32(cf[i][j], a[i], bf[j]);
            }
            __syncthreads();
        }

        // maxpool epilogue -> vpool (B, C, Np), tf32-RN (feeds vprime)
        float* Cp = vpool + (size_t)b * CCH * NPOOL;
        const int pcb = col0 >> 2;
#pragma unroll 1
        for (int s = 0; s < 4; s++) {
            if (wr == (s >> 1)) {
#pragma unroll
                for (int ii = 0; ii < 2; ii++) {
                    const int i = (s & 1) * 2 + ii;
#pragma unroll
                    for (int half = 0; half < 2; half++) {
                        const int lr = ii * 16 + half * 8 + g;
#pragma unroll
                        for (int j = 0; j < 4; j++) {
                            const int col = wc * 32 + j * 8 + 2 * tk;
                            sh.sX[lr * 132 + col]     = cf[i][j][half * 2 + 0];
                            sh.sX[lr * 132 + col + 1] = cf[i][j][half * 2 + 1];
                        }
                    }
                }
            }
            __syncthreads();
#pragma unroll
            for (int u = 0; u < 4; u++) {
                int po = tid + u * 256;
                int rr = po >> 5, pc = po & 31;
                float v = fmaxf(fmaxf(sh.sX[rr * 132 + 2 * pc], sh.sX[rr * 132 + 2 * pc + 1]),
                                fmaxf(sh.sX[rr * 132 + 64 + 2 * pc], sh.sX[rr * 132 + 64 + 2 * pc + 1]));
                const int r = r0 + s * 32 + rr;
                Cp[(size_t)r * NPOOL + pcb + pc] = tf32_rn(v + bv[r]);
            }
            __syncthreads();
        }
    }
}

// ============ energy via tf32 mma + exp -> bf16 + partials ====
__global__ __launch_bounds__(256)
void energy_mma(const float* __restrict__ kTg, const float* __restrict__ qTg,
                __nv_bfloat16* __restrict__ attnh, float* __restrict__ part)
{
    __shared__ float sA[128 * 36];
    __shared__ float sB[128 * 36];
    __shared__ float sX[16 * 132];

    const int b  = blockIdx.z;
    const int m0 = blockIdx.y * 128;
    const int n0 = blockIdx.x * 128;
    const float* Ab = kTg + ((size_t)b * NSP + m0) * CSP;
    const float* Bb = qTg + ((size_t)b * NPOOL + n0) * CSP;

    const int tid = threadIdx.x, lane = tid & 31, wid = tid >> 5;
    const int wr = wid >> 2, wc = wid & 3;
    const int g = lane >> 2, tk = lane & 3;

#pragma unroll
    for (int u = 0; u < 4; u++) {
        int idx = tid + u * 256;
        int r = idx >> 3, kq = (idx & 7) * 4;
        *(float4*)&sA[r * 36 + kq] = *(const float4*)&Ab[(size_t)r * CSP + kq];
        *(float4*)&sB[r * 36 + kq] = *(const float4*)&Bb[(size_t)r * CSP + kq];
    }
    __syncthreads();

    float cf[4][4][4] = {};
#pragma unroll
    for (int ks = 0; ks < 4; ks++) {
        const int ko = ks * 8;
        uint32_t a[4][4], bf[4][2];
#pragma unroll
        for (int i = 0; i < 4; i++) {
            const int ra = (wr * 64 + i * 16 + g) * 36 + ko + tk;
            a[i][0] = __float_as_uint(sA[ra]);
            a[i][1] = __float_as_uint(sA[ra + 8 * 36]);
            a[i][2] = __float_as_uint(sA[ra + 4]);
            a[i][3] = __float_as_uint(sA[ra + 8 * 36 + 4]);
        }
#pragma unroll
        for (int j = 0; j < 4; j++) {
            const int rb = (wc * 32 + j * 8 + g) * 36 + ko + tk;
            bf[j][0] = __float_as_uint(sB[rb]);
            bf[j][1] = __float_as_uint(sB[rb + 4]);
        }
#pragma unroll
        for (int i = 0; i < 4; i++)
#pragma unroll
            for (int j = 0; j < 4; j++) mma_tf32(cf[i][j], a[i], bf[j]);
    }

    __nv_bfloat16* Cb = attnh + (size_t)b * NSP * NPOOL;
    float colsum[4][2] = {};
#pragma unroll
    for (int i = 0; i < 4; i++) {
#pragma unroll
        for (int half = 0; half < 2; half++) {
            const int r = m0 + wr * 64 + i * 16 + g + half * 8;
            const size_t ro = (size_t)r * NPOOL;
#pragma unroll
            for (int j = 0; j < 4; j++) {
                const int c = n0 + wc * 32 + j * 8 + 2 * tk;
                float e0 = __expf(cf[i][j][half * 2 + 0]);
                float e1 = __expf(cf[i][j][half * 2 + 1]);
                colsum[j][0] += e0;
                colsum[j][1] += e1;
                *(__nv_bfloat162*)&Cb[ro + c] = __floats2bfloat162_rn(e0, e1);
            }
        }
    }
#pragma unroll
    for (int j = 0; j < 4; j++) {
        const int col = wc * 32 + j * 8 + 2 * tk;
        sX[(wr * 8 + g) * 132 + col]     = colsum[j][0];
        sX[(wr * 8 + g) * 132 + col + 1] = colsum[j][1];
    }
    __syncthreads();
    if (tid < 128) {
        float t = 0.f;
#pragma unroll
        for (int k = 0; k < 16; k++) t += sX[k * 132 + tid];
        part[((size_t)b * 32 + blockIdx.y) * NPOOL + n0 + tid] = t;
    }
}

// ================= vprime GEMM (inputs pre-rounded tf32-RN) ============
#define GV_SA 2560
#define GV_SB 2176
__global__ __launch_bounds__(256)
void gemm_v2(const float* __restrict__ A,
             const float* __restrict__ B,
             float* __restrict__ C,
             int M, int N, int K)
{
    __shared__ float sm[2 * GV_SA + 2 * GV_SB];

    const int b  = blockIdx.z;
    const int r0 = blockIdx.y * 128;
    const int n0 = blockIdx.x * 128;
    const float* Ab = A;
    const float* Bb = B + (size_t)b * K * N;

    const int tid = threadIdx.x, lane = tid & 31, wid = tid >> 5;
    const int wr = wid >> 2, wc = wid & 3;
    const int g = lane >> 2, tk = lane & 3;

    const int a_r = tid >> 1, a_q = (tid & 1) * 2;
    const uint32_t smBase = (uint32_t)__cvta_generic_to_shared(sm);

    auto issue = [&](int k0, int s) {
#pragma unroll
        for (int u = 0; u < 2; u++) {
            int q = a_q + u;
            cpa16(smBase + (s * GV_SA + a_r * 20 + q * 4) * 4,
                  &Ab[(size_t)(r0 + a_r) * K + k0 + q * 4]);
        }
#pragma unroll
        for (int u = 0; u < 2; u++) {
            int idx = tid + u * 256;
            int kr = idx >> 5, nc = (idx & 31) * 4;
            cpa16(smBase + (2 * GV_SA + s * GV_SB + kr * 136 + nc) * 4,
                  &Bb[(size_t)(k0 + kr) * N + n0 + nc]);
        }
        asm volatile("cp.async.commit_group;");
    };

    float cf[4][4][4] = {};
    const int NIT = K / 16;

    issue(0, 0);
    for (int kt = 0; kt < NIT; kt++) {
        const int cur = kt & 1;
        if (kt < NIT - 1) {
            issue((kt + 1) * 16, cur ^ 1);
            asm volatile("cp.async.wait_group 1;");
        } else {
            asm volatile("cp.async.wait_group 0;");
        }
        __syncthreads();

        const float* cA = sm + cur * GV_SA;
        const float* cB = sm + 2 * GV_SA + cur * GV_SB;
#pragma unroll
        for (int ks = 0; ks < 2; ks++) {
            const int ko = ks * 8;
            uint32_t a[4][4], bf[4][2];
#pragma unroll
            for (int i = 0; i < 4; i++) {
                const int ra = (wr * 64 + i * 16 + g) * 20 + ko + tk;
                a[i][0] = __float_as_uint(cA[ra]);
                a[i][1] = __float_as_uint(cA[ra + 8 * 20]);
                a[i][2] = __float_as_uint(cA[ra + 4]);
                a[i][3] = __float_as_uint(cA[ra + 8 * 20 + 4]);
            }
#pragma unroll
            for (int j = 0; j < 4; j++) {
                const int nn = wc * 32 + j * 8 + g;
                bf[j][0] = __float_as_uint(cB[(ko + tk) * 136 + nn]);
                bf[j][1] = __float_as_uint(cB[(ko + tk + 4) * 136 + nn]);
            }
#pragma unroll
            for (int i = 0; i < 4; i++)
#pragma unroll
                for (int j = 0; j < 4; j++) mma_tf32(cf[i][j], a[i], bf[j]);
        }
        __syncthreads();
    }

    float* Cb = C + (size_t)b * M * N;
#pragma unroll
    for (int i = 0; i < 4; i++)
#pragma unroll
        for (int half = 0; half < 2; half++) {
            const int r = r0 + wr * 64 + i * 16 + g + half * 8;
            const size_t ro = (size_t)r * N;
#pragma unroll
            for (int j = 0; j < 4; j++) {
                const int c = n0 + wc * 32 + j * 8 + 2 * tk;
                float2 o;
                o.x = cf[i][j][half * 2 + 0];
                o.y = cf[i][j][half * 2 + 1];
                *(float2*)&Cb[ro + c] = o;
            }
        }
}

// ---------------- denominator + v'' ----------------
__global__ void invden_k(const float* __restrict__ part, float* __restrict__ invden)
{
    int idx = blockIdx.x * 256 + threadIdx.x;
    int b  = idx >> 10;
    int np = idx & 1023;
    const float* p = part + (size_t)b * 32 * NPOOL + np;
    float s = 0.f;
#pragma unroll
    for (int i = 0; i < 32; i++) s += p[(size_t)i * NPOOL];
    invden[idx] = 1.f / s;
}

__global__ void scale_v_k(const float* __restrict__ vpr,
                          const float* __restrict__ invden,
                          __nv_bfloat16* __restrict__ vppb)
{
    int idx = blockIdx.x * 256 + threadIdx.x;
    int np = idx & 1023;
    int b  = idx >> 18;
    vppb[idx] = __float2bfloat16_rn(vpr[idx] * invden[b * NPOOL + np]);
}

// ============ final bf16 mma: full-C tile 256x128, cp.async =====
#define FSTRIDE 12
__global__ __launch_bounds__(256)
void final2_k(const __nv_bfloat16* __restrict__ vpp,
              const __nv_bfloat16* __restrict__ pm,
              const float* __restrict__ bo,
              const float* __restrict__ gamma,
              const float* __restrict__ xres,
              float* __restrict__ out)
{
    __shared__ uint32_t uA[2][256 * FSTRIDE];
    __shared__ uint32_t uB[2][128 * FSTRIDE];

    const int tid = threadIdx.x, lane = tid & 31, wid = tid >> 5;
    const int b  = blockIdx.z;
    const int m0 = blockIdx.x * 128;
    const int wr = wid >> 1;
    const int wc = wid & 1;
    const int g = lane >> 2, tk = lane & 3;

    const __nv_bfloat16* Ab = vpp + (size_t)b * CCH * NPOOL;
    const __nv_bfloat16* Bb = pm + ((size_t)b * NSP + m0) * NPOOL;

    const int ar = tid >> 1, acq = tid & 1;
    const int br = tid >> 1;
    uint32_t aDst0 = (uint32_t)__cvta_generic_to_shared(&uA[0][ar * FSTRIDE + acq * 4]);
    uint32_t aDst1 = (uint32_t)__cvta_generic_to_shared(&uA[0][(ar + 128) * FSTRIDE + acq * 4]);
    uint32_t bDst  = (uint32_t)__cvta_generic_to_shared(&uB[0][br * FSTRIDE + (tid & 1) * 4]);
    const uint32_t bufStepA = 256 * FSTRIDE * 4;
    const uint32_t bufStepB = 128 * FSTRIDE * 4;

    float cf[4][8][4] = {};

    auto issue = [&](int kt, int s) {
        const int kb = kt * 16;
        cpa16(aDst0 + s * bufStepA, &Ab[(size_t)ar * NPOOL + kb + acq * 8]);
        cpa16(aDst1 + s * bufStepA, &Ab[(size_t)(ar + 128) * NPOOL + kb + acq * 8]);
        cpa16(bDst + s * bufStepB, &Bb[(size_t)br * NPOOL + kb + (tid & 1) * 8]);
        asm volatile("cp.async.commit_group;");
    };

    issue(0, 0);
    for (int kt = 0; kt < NPOOL / 16; kt++) {
        const int cur = kt & 1;
        if (kt < NPOOL / 16 - 1) {
            issue(kt + 1, cur ^ 1);
            asm volatile("cp.async.wait_group 1;");
        } else {
            asm volatile("cp.async.wait_group 0;");
        }
        __syncthreads();

        uint32_t a[4][4], bf[8][2];
#pragma unroll
        for (int i = 0; i < 4; i++) {
            const int ra = (wr * 64 + i * 16 + g) * FSTRIDE + tk;
            a[i][0] = uA[cur][ra];
            a[i][1] = uA[cur][ra + 8 * FSTRIDE];
            a[i][2] = uA[cur][ra + 4];
            a[i][3] = uA[cur][ra + 8 * FSTRIDE + 4];
        }
#pragma unroll
        for (int j = 0; j < 8; j++) {
            const int rb = (wc * 64 + j * 8 + g) * FSTRIDE + tk;
            bf[j][0] = uB[cur][rb];
            bf[j][1] = uB[cur][rb + 4];
        }
#pragma unroll
        for (int i = 0; i < 4; i++)
#pragma unroll
            for (int j = 0; j < 8; j++) mma_bf16(cf[i][j], a[i], bf[j]);
        __syncthreads();
    }

    const float gm = gamma[0];
#pragma unroll
    for (int i = 0; i < 4; i++) {
#pragma unroll
        for (int half = 0; half < 2; half++) {
            const int c = wr * 64 + i * 16 + g + half * 8;
            const float bc = bo[c];
            const size_t ro = ((size_t)b * CCH + c) * NSP;
#pragma unroll
            for (int j = 0; j < 8; j++) {
                const int m = m0 + wc * 64 + j * 8 + 2 * tk;
                float2 xr = *(const float2*)&xres[ro + m];
                float2 o;
                o.x = gm * (cf[i][j][half * 2 + 0] + bc) + xr.x;
                o.y = gm * (cf[i][j][half * 2 + 1] + bc) + xr.y;
                *(float2*)&out[ro + m] = o;
            }
        }
    }
}

// ---------------- launch ----------------
extern "C" void kernel_launch(void* const* d_in, const int* in_sizes, int n_in,
                              void* d_out, int out_size)
{
    const float* x     = (const float*)d_in[0];
    const float* wq    = (const float*)d_in[1];
    const float* bq    = (const float*)d_in[2];
    const float* wk    = (const float*)d_in[3];
    const float* bk    = (const float*)d_in[4];
    const float* wv    = (const float*)d_in[5];
    const float* bv    = (const float*)d_in[6];
    const float* wo    = (const float*)d_in[7];
    const float* bo    = (const float*)d_in[8];
    const float* gamma = (const float*)d_in[9];
    float* out = (float*)d_out;

    float *pkT, *pqT, *pwor, *pvp, *pvpr, *ppart, *pinv;
    __nv_bfloat16 *pattnh, *pvppb;
    cudaGetSymbolAddress((void**)&pkT,    g_kT);
    cudaGetSymbolAddress((void**)&pqT,    g_qT);
    cudaGetSymbolAddress((void**)&pwor,   g_wor);
    cudaGetSymbolAddress((void**)&pvp,    g_vpool);
    cudaGetSymbolAddress((void**)&pvpr,   g_vprime);
    cudaGetSymbolAddress((void**)&ppart,  g_part);
    cudaGetSymbolAddress((void**)&pinv,   g_invden);
    cudaGetSymbolAddress((void**)&pattnh, g_attnh);
    cudaGetSymbolAddress((void**)&pvppb,  g_vppb);

    static cudaStream_t s1 = nullptr;
    static cudaEvent_t evFork = nullptr, evQKV = nullptr, evJoin = nullptr;
    if (s1 == nullptr) {
        cudaStreamCreateWithFlags(&s1, cudaStreamNonBlocking);
        cudaEventCreateWithFlags(&evFork, cudaEventDisableTiming);
        cudaEventCreateWithFlags(&evQKV,  cudaEventDisableTiming);
        cudaEventCreateWithFlags(&evJoin, cudaEventDisableTiming);
    }

    cudaEventRecord(evFork, 0);
    cudaStreamWaitEvent(s1, evFork, 0);

    // s1: tiny wo rounding (independent)
    round_wo_k<<<(CCH * CCH) / 1024, 256, 0, s1>>>(wo, pwor);

    // main: fused conv_qkv (kT, qT, vpool in one pass over x)
    {
        dim3 g(NSP / 128, 3, BATCH);
        conv_qkv_mma<<<g, 256>>>(wk, bk, wq, bq, wv, bv, x, pkT, pqT, pvp);
    }
    cudaEventRecord(evQKV, 0);
    cudaStreamWaitEvent(s1, evQKV, 0);

    // s1: vprime (overlaps energy on main)
    {
        dim3 g(NPOOL / 128, CCH / 128, BATCH);
        gemm_v2<<<g, 256, 0, s1>>>(pwor, pvp, pvpr, CCH, NPOOL, CCH);
    }
    cudaEventRecord(evJoin, s1);

    // main: energy -> invden
    {
        dim3 g(NPOOL / 128, NSP / 128, BATCH);
        energy_mma<<<g, 256>>>(pkT, pqT, pattnh, ppart);
    }
    invden_k<<<BATCH * NPOOL / 256, 256>>>(ppart, pinv);

    cudaStreamWaitEvent(0, evJoin, 0);
    scale_v_k<<<BATCH * CCH * NPOOL / 256, 256>>>(pvpr, pinv, pvppb);
    {
        dim3 g(NSP / 128, 1, BATCH);
        final2_k<<<g, 256>>>(pvppb, pattnh, bo, gamma, x, out);
    }
}

// round 12
// speedup vs baseline: 1.0514x; 1.0514x over previous
#include <cuda_runtime.h>
#include <cuda_bf16.h>
#include <math.h>
#include <stdint.h>

#define BATCH 16
#define CCH   256
#define NSP   4096   // 64*64
#define CSP   32     // C/8
#define NPOOL 1024   // 32*32

// ---------------- scratch ----------------
__device__ float g_kT[BATCH * NSP * CSP];                    //  8 MB tf32 (B, n, 32)
__device__ float g_qT[BATCH * NPOOL * CSP];                  //  2 MB tf32 (B, np, 32)
__device__ float g_wor[CCH * CCH];                           // 256 KB tf32-RN wo
__device__ float g_vpool[BATCH * CCH * NPOOL];               // 16 MB (tf32-RN values)
__device__ float g_vprime[BATCH * CCH * NPOOL];              // 16 MB
__device__ float g_part[BATCH * 32 * NPOOL];                 //  2 MB
__device__ __nv_bfloat16 g_attnh[(size_t)BATCH * NSP * NPOOL]; // 128 MB
__device__ __nv_bfloat16 g_vppb[BATCH * CCH * NPOOL];        //  8 MB

// ---------------- helpers ----------------
__device__ __forceinline__ float tf32_rn(float v) {
    uint32_t u;
    asm("cvt.rna.tf32.f32 %0, %1;" : "=r"(u) : "f"(v));
    return __uint_as_float(u);
}
__device__ __forceinline__ void mma_tf32(float* c, const uint32_t* a, const uint32_t* b) {
    asm volatile(
        "mma.sync.aligned.m16n8k8.row.col.f32.tf32.tf32.f32 "
        "{%0,%1,%2,%3}, {%4,%5,%6,%7}, {%8,%9}, {%0,%1,%2,%3};"
        : "+f"(c[0]), "+f"(c[1]), "+f"(c[2]), "+f"(c[3])
        : "r"(a[0]), "r"(a[1]), "r"(a[2]), "r"(a[3]), "r"(b[0]), "r"(b[1]));
}
__device__ __forceinline__ void mma_bf16(float* c, const uint32_t* a, const uint32_t* b) {
    asm volatile(
        "mma.sync.aligned.m16n8k16.row.col.f32.bf16.bf16.f32 "
        "{%0,%1,%2,%3}, {%4,%5,%6,%7}, {%8,%9}, {%0,%1,%2,%3};"
        : "+f"(c[0]), "+f"(c[1]), "+f"(c[2]), "+f"(c[3])
        : "r"(a[0]), "r"(a[1]), "r"(a[2]), "r"(a[3]), "r"(b[0]), "r"(b[1]));
}
__device__ __forceinline__ void cpa16(uint32_t dst, const void* src) {
    asm volatile("cp.async.cg.shared.global [%0], [%1], 16;" :: "r"(dst), "l"(src));
}

// ---------------- pre-round wo to tf32-RN ----------------
__global__ void round_wo_k(const float* __restrict__ wo, float* __restrict__ wor)
{
    int i = (blockIdx.x * 256 + threadIdx.x) * 4;
    float4 b = *(const float4*)&wo[i];
    b.x = tf32_rn(b.x); b.y = tf32_rn(b.y); b.z = tf32_rn(b.z); b.w = tf32_rn(b.w);
    *(float4*)&wor[i] = b;
}

// ============ fused conv_q + conv_k + conv_v via tf32 mma (proven, R11) ======
__global__ __launch_bounds__(256)
void conv_qkv_mma(const float* __restrict__ wk, const float* __restrict__ bk,
                  const float* __restrict__ wq, const float* __restrict__ bq,
                  const float* __restrict__ wv, const float* __restrict__ bv,
                  const float* __restrict__ x,
                  float* __restrict__ kT, float* __restrict__ qT,
                  float* __restrict__ vpool)
{
    __shared__ union {
        struct { float sA[64 * 20];  float sB[128 * 20]; } l0;
        struct { float sA[128 * 20]; float sB[16 * 136]; } l1;
        float sOut[64 * 132];
        float sX[32 * 132];
    } sh;

    const int b    = blockIdx.z;
    const int y    = blockIdx.y;
    const int col0 = blockIdx.x * 128;
    const float* xb = x + (size_t)b * CCH * NSP;
    const int tid = threadIdx.x, lane = tid & 31, wid = tid >> 5;
    const int wr = wid >> 2, wc = wid & 3;
    const int g = lane >> 2, tk = lane & 3;

    if (y == 0) {
        float cf[2][4][4] = {};

        for (int k0 = 0; k0 < CCH; k0 += 16) {
            {
                int r = tid >> 2, kq = (tid & 3) * 4;
                const float* wrow = (r < 32) ? (wk + r * CCH) : (wq + (r - 32) * CCH);
                float4 v = *(const float4*)&wrow[k0 + kq];
                v.x = tf32_rn(v.x); v.y = tf32_rn(v.y);
                v.z = tf32_rn(v.z); v.w = tf32_rn(v.w);
                *(float4*)&sh.l0.sA[r * 20 + kq] = v;
            }
#pragma unroll
            for (int u = 0; u < 2; u++) {
                int idx = tid + u * 256;
                int kr = idx >> 5, nc = (idx & 31) * 4;
                float4 v = *(const float4*)&xb[(size_t)(k0 + kr) * NSP + col0 + nc];
                sh.l0.sB[(nc + 0) * 20 + kr] = tf32_rn(v.x);
                sh.l0.sB[(nc + 1) * 20 + kr] = tf32_rn(v.y);
                sh.l0.sB[(nc + 2) * 20 + kr] = tf32_rn(v.z);
                sh.l0.sB[(nc + 3) * 20 + kr] = tf32_rn(v.w);
            }
            __syncthreads();
#pragma unroll
            for (int ks = 0; ks < 2; ks++) {
                const int ko = ks * 8;
                uint32_t a[2][4], bf[4][2];
#pragma unroll
                for (int i = 0; i < 2; i++) {
                    const int ra = (wr * 32 + i * 16 + g) * 20 + ko + tk;
                    a[i][0] = __float_as_uint(sh.l0.sA[ra]);
                    a[i][1] = __float_as_uint(sh.l0.sA[ra + 8 * 20]);
                    a[i][2] = __float_as_uint(sh.l0.sA[ra + 4]);
                    a[i][3] = __float_as_uint(sh.l0.sA[ra + 8 * 20 + 4]);
                }
#pragma unroll
                for (int j = 0; j < 4; j++) {
                    const int rb = (wc * 32 + j * 8 + g) * 20 + ko + tk;
                    bf[j][0] = __float_as_uint(sh.l0.sB[rb]);
                    bf[j][1] = __float_as_uint(sh.l0.sB[rb + 4]);
                }
#pragma unroll
                for (int i = 0; i < 2; i++)
#pragma unroll
                    for (int j = 0; j < 4; j++) mma_tf32(cf[i][j], a[i], bf[j]);
            }
            __syncthreads();
        }

#pragma unroll
        for (int i = 0; i < 2; i++)
#pragma unroll
            for (int half = 0; half < 2; half++) {
                const int r = wr * 32 + i * 16 + half * 8 + g;
#pragma unroll
                for (int j = 0; j < 4; j++) {
                    const int c = wc * 32 + j * 8 + 2 * tk;
                    sh.sOut[r * 132 + c]     = cf[i][j][half * 2 + 0];
                    sh.sOut[r * 132 + c + 1] = cf[i][j][half * 2 + 1];
                }
            }
        __syncthreads();

        float* kTb = kT + (size_t)b * NSP * CSP;
#pragma unroll
        for (int u = 0; u < 4; u++) {
            int idx = tid + u * 256;
            int nn = idx >> 3, csq = (idx & 7) * 4;
            float4 o;
            o.x = tf32_rn(sh.sOut[(csq + 0) * 132 + nn] + bk[csq + 0]);
            o.y = tf32_rn(sh.sOut[(csq + 1) * 132 + nn] + bk[csq + 1]);
            o.z = tf32_rn(sh.sOut[(csq + 2) * 132 + nn] + bk[csq + 2]);
            o.w = tf32_rn(sh.sOut[(csq + 3) * 132 + nn] + bk[csq + 3]);
            *(float4*)&kTb[(size_t)(col0 + nn) * CSP + csq] = o;
        }

        float* qTb = qT + (size_t)b * NPOOL * CSP;
        const int hp = col0 >> 7;
        {
            int wp = tid >> 3, csq = (tid & 7) * 4;
            float4 o;
            float* oc = &o.x;
#pragma unroll
            for (int t = 0; t < 4; t++) {
                const int cs = csq + t;
                const float* r = &sh.sOut[(32 + cs) * 132];
                float v = fmaxf(fmaxf(r[2 * wp], r[2 * wp + 1]),
                                fmaxf(r[64 + 2 * wp], r[64 + 2 * wp + 1]));
                oc[t] = tf32_rn(v + bq[cs]);
            }
            *(float4*)&qTb[(size_t)(hp * 32 + wp) * CSP + csq] = o;
        }
    } else {
        const int r0 = (y - 1) * 128;
        float cf[4][4][4] = {};

        for (int k0 = 0; k0 < CCH; k0 += 16) {
            {
                int r = tid >> 1, kq = (tid & 1) * 8;
#pragma unroll
                for (int q = 0; q < 2; q++) {
                    float4 v = *(const float4*)&wv[(size_t)(r0 + r) * CCH + k0 + kq + q * 4];
                    v.x = tf32_rn(v.x); v.y = tf32_rn(v.y);
                    v.z = tf32_rn(v.z); v.w = tf32_rn(v.w);
                    *(float4*)&sh.l1.sA[r * 20 + kq + q * 4] = v;
                }
            }
#pragma unroll
            for (int u = 0; u < 2; u++) {
                int idx = tid + u * 256;
                int kr = idx >> 5, nc = (idx & 31) * 4;
                float4 v = *(const float4*)&xb[(size_t)(k0 + kr) * NSP + col0 + nc];
                v.x = tf32_rn(v.x); v.y = tf32_rn(v.y);
                v.z = tf32_rn(v.z); v.w = tf32_rn(v.w);
                *(float4*)&sh.l1.sB[kr * 136 + nc] = v;
            }
            __syncthreads();
#pragma unroll
            for (int ks = 0; ks < 2; ks++) {
                const int ko = ks * 8;
                uint32_t a[4][4], bf[4][2];
#pragma unroll
                for (int i = 0; i < 4; i++) {
                    const int ra = (wr * 64 + i * 16 + g) * 20 + ko + tk;
                    a[i][0] = __float_as_uint(sh.l1.sA[ra]);
                    a[i][1] = __float_as_uint(sh.l1.sA[ra + 8 * 20]);
                    a[i][2] = __float_as_uint(sh.l1.sA[ra + 4]);
                    a[i][3] = __float_as_uint(sh.l1.sA[ra + 8 * 20 + 4]);
                }
#pragma unroll
                for (int j = 0; j < 4; j++) {
                    const int nn = wc * 32 + j * 8 + g;
                    bf[j][0] = __float_as_uint(sh.l1.sB[(ko + tk) * 136 + nn]);
                    bf[j][1] = __float_as_uint(sh.l1.sB[(ko + tk + 4) * 136 + nn]);
                }
#pragma unroll
                for (int i = 0; i < 4; i++)
#pragma unroll
                    for (int j = 0; j < 4; j++) mma_tf32(cf[i][j], a[i], bf[j]);
            }
            __syncthreads();
        }

        float* Cp = vpool + (size_t)b * CCH * NPOOL;
        const int pcb = col0 >> 2;
#pragma unroll 1
        for (int s = 0; s < 4; s++) {
            if (wr == (s >> 1)) {
#pragma unroll
                for (int ii = 0; ii < 2; ii++) {
                    const int i = (s & 1) * 2 + ii;
#pragma unroll
                    for (int half = 0; half < 2; half++) {
                        const int lr = ii * 16 + half * 8 + g;
#pragma unroll
                        for (int j = 0; j < 4; j++) {
                            const int col = wc * 32 + j * 8 + 2 * tk;
                            sh.sX[lr * 132 + col]     = cf[i][j][half * 2 + 0];
                            sh.sX[lr * 132 + col + 1] = cf[i][j][half * 2 + 1];
                        }
                    }
                }
            }
            __syncthreads();
#pragma unroll
            for (int u = 0; u < 4; u++) {
                int po = tid + u * 256;
                int rr = po >> 5, pc = po & 31;
                float v = fmaxf(fmaxf(sh.sX[rr * 132 + 2 * pc], sh.sX[rr * 132 + 2 * pc + 1]),
                                fmaxf(sh.sX[rr * 132 + 64 + 2 * pc], sh.sX[rr * 132 + 64 + 2 * pc + 1]));
                const int r = r0 + s * 32 + rr;
                Cp[(size_t)r * NPOOL + pcb + pc] = tf32_rn(v + bv[r]);
            }
            __syncthreads();
        }
    }
}

// ============ energy via tf32 mma + exp -> bf16 (smem-staged coalesced store) =
__global__ __launch_bounds__(256)
void energy_mma(const float* __restrict__ kTg, const float* __restrict__ qTg,
                __nv_bfloat16* __restrict__ attnh, float* __restrict__ part)
{
    __shared__ union {
        struct { float sA[128 * 36]; float sB[128 * 36]; } ld;
        uint32_t stage[128 * 68];     // bf16x2 tile staging, stride 68 (no conflicts)
    } shE;
    __shared__ float sX[16 * 132];

    const int b  = blockIdx.z;
    const int m0 = blockIdx.y * 128;
    const int n0 = blockIdx.x * 128;
    const float* Ab = kTg + ((size_t)b * NSP + m0) * CSP;
    const float* Bb = qTg + ((size_t)b * NPOOL + n0) * CSP;

    const int tid = threadIdx.x, lane = tid & 31, wid = tid >> 5;
    const int wr = wid >> 2, wc = wid & 3;
    const int g = lane >> 2, tk = lane & 3;

#pragma unroll
    for (int u = 0; u < 4; u++) {
        int idx = tid + u * 256;
        int r = idx >> 3, kq = (idx & 7) * 4;
        *(float4*)&shE.ld.sA[r * 36 + kq] = *(const float4*)&Ab[(size_t)r * CSP + kq];
        *(float4*)&shE.ld.sB[r * 36 + kq] = *(const float4*)&Bb[(size_t)r * CSP + kq];
    }
    __syncthreads();

    float cf[4][4][4] = {};
#pragma unroll
    for (int ks = 0; ks < 4; ks++) {
        const int ko = ks * 8;
        uint32_t a[4][4], bf[4][2];
#pragma unroll
        for (int i = 0; i < 4; i++) {
            const int ra = (wr * 64 + i * 16 + g) * 36 + ko + tk;
            a[i][0] = __float_as_uint(shE.ld.sA[ra]);
            a[i][1] = __float_as_uint(shE.ld.sA[ra + 8 * 36]);
            a[i][2] = __float_as_uint(shE.ld.sA[ra + 4]);
            a[i][3] = __float_as_uint(shE.ld.sA[ra + 8 * 36 + 4]);
        }
#pragma unroll
        for (int j = 0; j < 4; j++) {
            const int rb = (wc * 32 + j * 8 + g) * 36 + ko + tk;
            bf[j][0] = __float_as_uint(shE.ld.sB[rb]);
            bf[j][1] = __float_as_uint(shE.ld.sB[rb + 4]);
        }
#pragma unroll
        for (int i = 0; i < 4; i++)
#pragma unroll
            for (int j = 0; j < 4; j++) mma_tf32(cf[i][j], a[i], bf[j]);
    }
    __syncthreads();   // all fragment reads done — union reuse safe

    // exp -> bf16x2 into staging; colsum unchanged order
    float colsum[4][2] = {};
#pragma unroll
    for (int i = 0; i < 4; i++) {
#pragma unroll
        for (int half = 0; half < 2; half++) {
            const int lr = wr * 64 + i * 16 + half * 8 + g;
#pragma unroll
            for (int j = 0; j < 4; j++) {
                const int lc2 = wc * 16 + j * 4 + tk;   // uint32 index (2 bf16)
                float e0 = __expf(cf[i][j][half * 2 + 0]);
                float e1 = __expf(cf[i][j][half * 2 + 1]);
                colsum[j][0] += e0;
                colsum[j][1] += e1;
                __nv_bfloat162 p2 = __floats2bfloat162_rn(e0, e1);
                shE.stage[lr * 68 + lc2] = *(uint32_t*)&p2;
            }
        }
    }
#pragma unroll
    for (int j = 0; j < 4; j++) {
        const int col = wc * 32 + j * 8 + 2 * tk;
        sX[(wr * 8 + g) * 132 + col]     = colsum[j][0];
        sX[(wr * 8 + g) * 132 + col + 1] = colsum[j][1];
    }
    __syncthreads();

    if (tid < 128) {
        float t = 0.f;
#pragma unroll
        for (int k = 0; k < 16; k++) t += sX[k * 132 + tid];
        part[((size_t)b * 32 + blockIdx.y) * NPOOL + n0 + tid] = t;
    }

    // coalesced writeout: 128 rows x 256B contiguous
    __nv_bfloat16* Cb = attnh + (size_t)b * NSP * NPOOL + (size_t)m0 * NPOOL + n0;
#pragma unroll
    for (int u = 0; u < 8; u++) {
        int idx = tid + u * 256;
        int row = idx >> 4, q = idx & 15;
        uint4 v = *(const uint4*)&shE.stage[row * 68 + q * 4];
        *(uint4*)&Cb[(size_t)row * NPOOL + q * 8] = v;
    }
}

// ================= vprime GEMM (inputs pre-rounded tf32-RN) ============
#define GV_SA 2560
#define GV_SB 2176
__global__ __launch_bounds__(256)
void gemm_v2(const float* __restrict__ A,
             const float* __restrict__ B,
             float* __restrict__ C,
             int M, int N, int K)
{
    __shared__ float sm[2 * GV_SA + 2 * GV_SB];

    const int b  = blockIdx.z;
    const int r0 = blockIdx.y * 128;
    const int n0 = blockIdx.x * 128;
    const float* Ab = A;
    const float* Bb = B + (size_t)b * K * N;

    const int tid = threadIdx.x, lane = tid & 31, wid = tid >> 5;
    const int wr = wid >> 2, wc = wid & 3;
    const int g = lane >> 2, tk = lane & 3;

    const int a_r = tid >> 1, a_q = (tid & 1) * 2;
    const uint32_t smBase = (uint32_t)__cvta_generic_to_shared(sm);

    auto issue = [&](int k0, int s) {
#pragma unroll
        for (int u = 0; u < 2; u++) {
            int q = a_q + u;
            cpa16(smBase + (s * GV_SA + a_r * 20 + q * 4) * 4,
                  &Ab[(size_t)(r0 + a_r) * K + k0 + q * 4]);
        }
#pragma unroll
        for (int u = 0; u < 2; u++) {
            int idx = tid + u * 256;
            int kr = idx >> 5, nc = (idx & 31) * 4;
            cpa16(smBase + (2 * GV_SA + s * GV_SB + kr * 136 + nc) * 4,
                  &Bb[(size_t)(k0 + kr) * N + n0 + nc]);
        }
        asm volatile("cp.async.commit_group;");
    };

    float cf[4][4][4] = {};
    const int NIT = K / 16;

    issue(0, 0);
    for (int kt = 0; kt < NIT; kt++) {
        const int cur = kt & 1;
        if (kt < NIT - 1) {
            issue((kt + 1) * 16, cur ^ 1);
            asm volatile("cp.async.wait_group 1;");
        } else {
            asm volatile("cp.async.wait_group 0;");
        }
        __syncthreads();

        const float* cA = sm + cur * GV_SA;
        const float* cB = sm + 2 * GV_SA + cur * GV_SB;
#pragma unroll
        for (int ks = 0; ks < 2; ks++) {
            const int ko = ks * 8;
            uint32_t a[4][4], bf[4][2];
#pragma unroll
            for (int i = 0; i < 4; i++) {
                const int ra = (wr * 64 + i * 16 + g) * 20 + ko + tk;
                a[i][0] = __float_as_uint(cA[ra]);
                a[i][1] = __float_as_uint(cA[ra + 8 * 20]);
                a[i][2] = __float_as_uint(cA[ra + 4]);
                a[i][3] = __float_as_uint(cA[ra + 8 * 20 + 4]);
            }
#pragma unroll
            for (int j = 0; j < 4; j++) {
                const int nn = wc * 32 + j * 8 + g;
                bf[j][0] = __float_as_uint(cB[(ko + tk) * 136 + nn]);
                bf[j][1] = __float_as_uint(cB[(ko + tk + 4) * 136 + nn]);
            }
#pragma unroll
            for (int i = 0; i < 4; i++)
#pragma unroll
                for (int j = 0; j < 4; j++) mma_tf32(cf[i][j], a[i], bf[j]);
        }
        __syncthreads();
    }

    float* Cb = C + (size_t)b * M * N;
#pragma unroll
    for (int i = 0; i < 4; i++)
#pragma unroll
        for (int half = 0; half < 2; half++) {
            const int r = r0 + wr * 64 + i * 16 + g + half * 8;
            const size_t ro = (size_t)r * N;
#pragma unroll
            for (int j = 0; j < 4; j++) {
                const int c = n0 + wc * 32 + j * 8 + 2 * tk;
                float2 o;
                o.x = cf[i][j][half * 2 + 0];
                o.y = cf[i][j][half * 2 + 1];
                *(float2*)&Cb[ro + c] = o;
            }
        }
}

// ---------------- fused denominator + v'' (same arithmetic order) ------------
// grid (64, 8): y picks a 32-c slice; inv recomputed per slice (cheap).
__global__ void norm_v_k(const float* __restrict__ part,
                         const float* __restrict__ vpr,
                         __nv_bfloat16* __restrict__ vppb)
{
    int idx = blockIdx.x * 256 + threadIdx.x;   // b*NPOOL + np
    int b  = idx >> 10;
    int np = idx & 1023;
    const float* p = part + (size_t)b * 32 * NPOOL + np;
    float s = 0.f;
#pragma unroll
    for (int i = 0; i < 32; i++) s += p[(size_t)i * NPOOL];
    const float inv = 1.f / s;

    const int c0 = blockIdx.y * 32;
    const float* v = vpr + (size_t)b * CCH * NPOOL + np;
    __nv_bfloat16* o = vppb + (size_t)b * CCH * NPOOL + np;
#pragma unroll 8
    for (int c = c0; c < c0 + 32; c++)
        o[(size_t)c * NPOOL] = __float2bfloat16_rn(v[(size_t)c * NPOOL] * inv);
}

// ============ final bf16 mma: full-C tile 256x128, 3-stage cp.async =====
#define FSTRIDE 12
__global__ __launch_bounds__(256)
void final2_k(const __nv_bfloat16* __restrict__ vpp,
              const __nv_bfloat16* __restrict__ pm,
              const float* __restrict__ bo,
              const float* __restrict__ gamma,
              const float* __restrict__ xres,
              float* __restrict__ out)
{
    __shared__ uint32_t uA[3][256 * FSTRIDE];
    __shared__ uint32_t uB[3][128 * FSTRIDE];

    const int tid = threadIdx.x, lane = tid & 31, wid = tid >> 5;
    const int b  = blockIdx.z;
    const int m0 = blockIdx.x * 128;
    const int wr = wid >> 1;
    const int wc = wid & 1;
    const int g = lane >> 2, tk = lane & 3;

    const __nv_bfloat16* Ab = vpp + (size_t)b * CCH * NPOOL;
    const __nv_bfloat16* Bb = pm + ((size_t)b * NSP + m0) * NPOOL;

    const int ar = tid >> 1, acq = tid & 1;
    const int br = tid >> 1;
    uint32_t aDst0 = (uint32_t)__cvta_generic_to_shared(&uA[0][ar * FSTRIDE + acq * 4]);
    uint32_t aDst1 = (uint32_t)__cvta_generic_to_shared(&uA[0][(ar + 128) * FSTRIDE + acq * 4]);
    uint32_t bDst  = (uint32_t)__cvta_generic_to_shared(&uB[0][br * FSTRIDE + (tid & 1) * 4]);
    const uint32_t bufStepA = 256 * FSTRIDE * 4;
    const uint32_t bufStepB = 128 * FSTRIDE * 4;

    float cf[4][8][4] = {};
    const int NIT = NPOOL / 16;

    auto issue = [&](int kt, int s) {
        const int kb = kt * 16;
        cpa16(aDst0 + s * bufStepA, &Ab[(size_t)ar * NPOOL + kb + acq * 8]);
        cpa16(aDst1 + s * bufStepA, &Ab[(size_t)(ar + 128) * NPOOL + kb + acq * 8]);
        cpa16(bDst + s * bufStepB, &Bb[(size_t)br * NPOOL + kb + (tid & 1) * 8]);
        asm volatile("cp.async.commit_group;");
    };

    issue(0, 0);
    issue(1, 1);
    for (int kt = 0; kt < NIT; kt++) {
        const int cur = kt % 3;
        if (kt + 2 < NIT) {
            issue(kt + 2, (kt + 2) % 3);
            asm volatile("cp.async.wait_group 2;");
        } else if (kt + 1 < NIT) {
            asm volatile("cp.async.wait_group 1;");
        } else {
            asm volatile("cp.async.wait_group 0;");
        }
        __syncthreads();

        uint32_t a[4][4], bf[8][2];
#pragma unroll
        for (int i = 0; i < 4; i++) {
            const int ra = (wr * 64 + i * 16 + g) * FSTRIDE + tk;
            a[i][0] = uA[cur][ra];
            a[i][1] = uA[cur][ra + 8 * FSTRIDE];
            a[i][2] = uA[cur][ra + 4];
            a[i][3] = uA[cur][ra + 8 * FSTRIDE + 4];
        }
#pragma unroll
        for (int j = 0; j < 8; j++) {
            const int rb = (wc * 64 + j * 8 + g) * FSTRIDE + tk;
            bf[j][0] = uB[cur][rb];
            bf[j][1] = uB[cur][rb + 4];
        }
#pragma unroll
        for (int i = 0; i < 4; i++)
#pragma unroll
            for (int j = 0; j < 8; j++) mma_bf16(cf[i][j], a[i], bf[j]);
        __syncthreads();
    }

    const float gm = gamma[0];
#pragma unroll
    for (int i = 0; i < 4; i++) {
#pragma unroll
        for (int half = 0; half < 2; half++) {
            const int c = wr * 64 + i * 16 + g + half * 8;
            const float bc = bo[c];
            const size_t ro = ((size_t)b * CCH + c) * NSP;
#pragma unroll
            for (int j = 0; j < 8; j++) {
                const int m = m0 + wc * 64 + j * 8 + 2 * tk;
                float2 xr = *(const float2*)&xres[ro + m];
                float2 o;
                o.x = gm * (cf[i][j][half * 2 + 0] + bc) + xr.x;
                o.y = gm * (cf[i][j][half * 2 + 1] + bc) + xr.y;
                *(float2*)&out[ro + m] = o;
            }
        }
    }
}

// ---------------- launch ----------------
extern "C" void kernel_launch(void* const* d_in, const int* in_sizes, int n_in,
                              void* d_out, int out_size)
{
    const float* x     = (const float*)d_in[0];
    const float* wq    = (const float*)d_in[1];
    const float* bq    = (const float*)d_in[2];
    const float* wk    = (const float*)d_in[3];
    const float* bk    = (const float*)d_in[4];
    const float* wv    = (const float*)d_in[5];
    const float* bv    = (const float*)d_in[6];
    const float* wo    = (const float*)d_in[7];
    const float* bo    = (const float*)d_in[8];
    const float* gamma = (const float*)d_in[9];
    float* out = (float*)d_out;

    float *pkT, *pqT, *pwor, *pvp, *pvpr, *ppart;
    __nv_bfloat16 *pattnh, *pvppb;
    cudaGetSymbolAddress((void**)&pkT,    g_kT);
    cudaGetSymbolAddress((void**)&pqT,    g_qT);
    cudaGetSymbolAddress((void**)&pwor,   g_wor);
    cudaGetSymbolAddress((void**)&pvp,    g_vpool);
    cudaGetSymbolAddress((void**)&pvpr,   g_vprime);
    cudaGetSymbolAddress((void**)&ppart,  g_part);
    cudaGetSymbolAddress((void**)&pattnh, g_attnh);
    cudaGetSymbolAddress((void**)&pvppb,  g_vppb);

    static cudaStream_t s1 = nullptr;
    static cudaEvent_t evFork = nullptr, evQKV = nullptr, evJoin = nullptr;
    if (s1 == nullptr) {
        cudaStreamCreateWithFlags(&s1, cudaStreamNonBlocking);
        cudaEventCreateWithFlags(&evFork, cudaEventDisableTiming);
        cudaEventCreateWithFlags(&evQKV,  cudaEventDisableTiming);
        cudaEventCreateWithFlags(&evJoin, cudaEventDisableTiming);
    }

    cudaEventRecord(evFork, 0);
    cudaStreamWaitEvent(s1, evFork, 0);

    // s1: tiny wo rounding
    round_wo_k<<<(CCH * CCH) / 1024, 256, 0, s1>>>(wo, pwor);

    // main: fused conv_qkv
    {
        dim3 g(NSP / 128, 3, BATCH);
        conv_qkv_mma<<<g, 256>>>(wk, bk, wq, bq, wv, bv, x, pkT, pqT, pvp);
    }
    cudaEventRecord(evQKV, 0);
    cudaStreamWaitEvent(s1, evQKV, 0);

    // s1: vprime (overlaps energy on main)
    {
        dim3 g(NPOOL / 128, CCH / 128, BATCH);
        gemm_v2<<<g, 256, 0, s1>>>(pwor, pvp, pvpr, CCH, NPOOL, CCH);
    }
    cudaEventRecord(evJoin, s1);

    // main: energy (coalesced attn store + partials)
    {
        dim3 g(NPOOL / 128, NSP / 128, BATCH);
        energy_mma<<<g, 256>>>(pkT, pqT, pattnh, ppart);
    }

    // join, fused normalize -> v'' bf16, then final
    cudaStreamWaitEvent(0, evJoin, 0);
    {
        dim3 g(BATCH * NPOOL / 256, CCH / 32);
        norm_v_k<<<g, 256>>>(ppart, pvpr, pvppb);
    }
    {
        dim3 g(NSP / 128, 1, BATCH);
        final2_k<<<g, 256>>>(pvppb, pattnh, bo, gamma, x, out);
    }
}

// round 13
// speedup vs baseline: 1.1486x; 1.0925x over previous
#include <cuda_runtime.h>
#include <cuda_bf16.h>
#include <math.h>
#include <stdint.h>

#define BATCH 16
#define CCH   256
#define NSP   4096   // 64*64
#define CSP   32     // C/8
#define NPOOL 1024   // 32*32

// ---------------- scratch ----------------
__device__ float g_kT[BATCH * NSP * CSP];                    //  8 MB tf32 (B, n, 32)
__device__ float g_qT[BATCH * NPOOL * CSP];                  //  2 MB tf32 (B, np, 32)
__device__ float g_wor[CCH * CCH];                           // 256 KB tf32-RN wo
__device__ float g_vpool[BATCH * CCH * NPOOL];               // 16 MB (tf32-RN values)
__device__ float g_vprime[BATCH * CCH * NPOOL];              // 16 MB
__device__ float g_part[BATCH * 32 * NPOOL];                 //  2 MB
__device__ __nv_bfloat16 g_vppb[BATCH * CCH * NPOOL];        //  8 MB

// ---------------- helpers ----------------
__device__ __forceinline__ float tf32_rn(float v) {
    uint32_t u;
    asm("cvt.rna.tf32.f32 %0, %1;" : "=r"(u) : "f"(v));
    return __uint_as_float(u);
}
__device__ __forceinline__ void mma_tf32(float* c, const uint32_t* a, const uint32_t* b) {
    asm volatile(
        "mma.sync.aligned.m16n8k8.row.col.f32.tf32.tf32.f32 "
        "{%0,%1,%2,%3}, {%4,%5,%6,%7}, {%8,%9}, {%0,%1,%2,%3};"
        : "+f"(c[0]), "+f"(c[1]), "+f"(c[2]), "+f"(c[3])
        : "r"(a[0]), "r"(a[1]), "r"(a[2]), "r"(a[3]), "r"(b[0]), "r"(b[1]));
}
__device__ __forceinline__ void mma_bf16(float* c, const uint32_t* a, const uint32_t* b) {
    asm volatile(
        "mma.sync.aligned.m16n8k16.row.col.f32.bf16.bf16.f32 "
        "{%0,%1,%2,%3}, {%4,%5,%6,%7}, {%8,%9}, {%0,%1,%2,%3};"
        : "+f"(c[0]), "+f"(c[1]), "+f"(c[2]), "+f"(c[3])
        : "r"(a[0]), "r"(a[1]), "r"(a[2]), "r"(a[3]), "r"(b[0]), "r"(b[1]));
}
__device__ __forceinline__ void cpa16(uint32_t dst, const void* src) {
    asm volatile("cp.async.cg.shared.global [%0], [%1], 16;" :: "r"(dst), "l"(src));
}

// ---------------- pre-round wo to tf32-RN ----------------
__global__ void round_wo_k(const float* __restrict__ wo, float* __restrict__ wor)
{
    int i = (blockIdx.x * 256 + threadIdx.x) * 4;
    float4 b = *(const float4*)&wo[i];
    b.x = tf32_rn(b.x); b.y = tf32_rn(b.y); b.z = tf32_rn(b.z); b.w = tf32_rn(b.w);
    *(float4*)&wor[i] = b;
}

// ============ fused conv_q + conv_k + conv_v via tf32 mma (proven) ======
__global__ __launch_bounds__(256)
void conv_qkv_mma(const float* __restrict__ wk, const float* __restrict__ bk,
                  const float* __restrict__ wq, const float* __restrict__ bq,
                  const float* __restrict__ wv, const float* __restrict__ bv,
                  const float* __restrict__ x,
                  float* __restrict__ kT, float* __restrict__ qT,
                  float* __restrict__ vpool)
{
    __shared__ union {
        struct { float sA[64 * 20];  float sB[128 * 20]; } l0;
        struct { float sA[128 * 20]; float sB[16 * 136]; } l1;
        float sOut[64 * 132];
        float sX[32 * 132];
    } sh;

    const int b    = blockIdx.z;
    const int y    = blockIdx.y;
    const int col0 = blockIdx.x * 128;
    const float* xb = x + (size_t)b * CCH * NSP;
    const int tid = threadIdx.x, lane = tid & 31, wid = tid >> 5;
    const int wr = wid >> 2, wc = wid & 3;
    const int g = lane >> 2, tk = lane & 3;

    if (y == 0) {
        float cf[2][4][4] = {};

        for (int k0 = 0; k0 < CCH; k0 += 16) {
            {
                int r = tid >> 2, kq = (tid & 3) * 4;
                const float* wrow = (r < 32) ? (wk + r * CCH) : (wq + (r - 32) * CCH);
                float4 v = *(const float4*)&wrow[k0 + kq];
                v.x = tf32_rn(v.x); v.y = tf32_rn(v.y);
                v.z = tf32_rn(v.z); v.w = tf32_rn(v.w);
                *(float4*)&sh.l0.sA[r * 20 + kq] = v;
            }
#pragma unroll
            for (int u = 0; u < 2; u++) {
                int idx = tid + u * 256;
                int kr = idx >> 5, nc = (idx & 31) * 4;
                float4 v = *(const float4*)&xb[(size_t)(k0 + kr) * NSP + col0 + nc];
                sh.l0.sB[(nc + 0) * 20 + kr] = tf32_rn(v.x);
                sh.l0.sB[(nc + 1) * 20 + kr] = tf32_rn(v.y);
                sh.l0.sB[(nc + 2) * 20 + kr] = tf32_rn(v.z);
                sh.l0.sB[(nc + 3) * 20 + kr] = tf32_rn(v.w);
            }
            __syncthreads();
#pragma unroll
            for (int ks = 0; ks < 2; ks++) {
                const int ko = ks * 8;
                uint32_t a[2][4], bf[4][2];
#pragma unroll
                for (int i = 0; i < 2; i++) {
                    const int ra = (wr * 32 + i * 16 + g) * 20 + ko + tk;
                    a[i][0] = __float_as_uint(sh.l0.sA[ra]);
                    a[i][1] = __float_as_uint(sh.l0.sA[ra + 8 * 20]);
                    a[i][2] = __float_as_uint(sh.l0.sA[ra + 4]);
                    a[i][3] = __float_as_uint(sh.l0.sA[ra + 8 * 20 + 4]);
                }
#pragma unroll
                for (int j = 0; j < 4; j++) {
                    const int rb = (wc * 32 + j * 8 + g) * 20 + ko + tk;
                    bf[j][0] = __float_as_uint(sh.l0.sB[rb]);
                    bf[j][1] = __float_as_uint(sh.l0.sB[rb + 4]);
                }
#pragma unroll
                for (int i = 0; i < 2; i++)
#pragma unroll
                    for (int j = 0; j < 4; j++) mma_tf32(cf[i][j], a[i], bf[j]);
            }
            __syncthreads();
        }

#pragma unroll
        for (int i = 0; i < 2; i++)
#pragma unroll
            for (int half = 0; half < 2; half++) {
                const int r = wr * 32 + i * 16 + half * 8 + g;
#pragma unroll
                for (int j = 0; j < 4; j++) {
                    const int c = wc * 32 + j * 8 + 2 * tk;
                    sh.sOut[r * 132 + c]     = cf[i][j][half * 2 + 0];
                    sh.sOut[r * 132 + c + 1] = cf[i][j][half * 2 + 1];
                }
            }
        __syncthreads();

        float* kTb = kT + (size_t)b * NSP * CSP;
#pragma unroll
        for (int u = 0; u < 4; u++) {
            int idx = tid + u * 256;
            int nn = idx >> 3, csq = (idx & 7) * 4;
            float4 o;
            o.x = tf32_rn(sh.sOut[(csq + 0) * 132 + nn] + bk[csq + 0]);
            o.y = tf32_rn(sh.sOut[(csq + 1) * 132 + nn] + bk[csq + 1]);
            o.z = tf32_rn(sh.sOut[(csq + 2) * 132 + nn] + bk[csq + 2]);
            o.w = tf32_rn(sh.sOut[(csq + 3) * 132 + nn] + bk[csq + 3]);
            *(float4*)&kTb[(size_t)(col0 + nn) * CSP + csq] = o;
        }

        float* qTb = qT + (size_t)b * NPOOL * CSP;
        const int hp = col0 >> 7;
        {
            int wp = tid >> 3, csq = (tid & 7) * 4;
            float4 o;
            float* oc = &o.x;
#pragma unroll
            for (int t = 0; t < 4; t++) {
                const int cs = csq + t;
                const float* r = &sh.sOut[(32 + cs) * 132];
                float v = fmaxf(fmaxf(r[2 * wp], r[2 * wp + 1]),
                                fmaxf(r[64 + 2 * wp], r[64 + 2 * wp + 1]));
                oc[t] = tf32_rn(v + bq[cs]);
            }
            *(float4*)&qTb[(size_t)(hp * 32 + wp) * CSP + csq] = o;
        }
    } else {
        const int r0 = (y - 1) * 128;
        float cf[4][4][4] = {};

        for (int k0 = 0; k0 < CCH; k0 += 16) {
            {
                int r = tid >> 1, kq = (tid & 1) * 8;
#pragma unroll
                for (int q = 0; q < 2; q++) {
                    float4 v = *(const float4*)&wv[(size_t)(r0 + r) * CCH + k0 + kq + q * 4];
                    v.x = tf32_rn(v.x); v.y = tf32_rn(v.y);
                    v.z = tf32_rn(v.z); v.w = tf32_rn(v.w);
                    *(float4*)&sh.l1.sA[r * 20 + kq + q * 4] = v;
                }
            }
#pragma unroll
            for (int u = 0; u < 2; u++) {
                int idx = tid + u * 256;
                int kr = idx >> 5, nc = (idx & 31) * 4;
                float4 v = *(const float4*)&xb[(size_t)(k0 + kr) * NSP + col0 + nc];
                v.x = tf32_rn(v.x); v.y = tf32_rn(v.y);
                v.z = tf32_rn(v.z); v.w = tf32_rn(v.w);
                *(float4*)&sh.l1.sB[kr * 136 + nc] = v;
            }
            __syncthreads();
#pragma unroll
            for (int ks = 0; ks < 2; ks++) {
                const int ko = ks * 8;
                uint32_t a[4][4], bf[4][2];
#pragma unroll
                for (int i = 0; i < 4; i++) {
                    const int ra = (wr * 64 + i * 16 + g) * 20 + ko + tk;
                    a[i][0] = __float_as_uint(sh.l1.sA[ra]);
                    a[i][1] = __float_as_uint(sh.l1.sA[ra + 8 * 20]);
                    a[i][2] = __float_as_uint(sh.l1.sA[ra + 4]);
                    a[i][3] = __float_as_uint(sh.l1.sA[ra + 8 * 20 + 4]);
                }
#pragma unroll
                for (int j = 0; j < 4; j++) {
                    const int nn = wc * 32 + j * 8 + g;
                    bf[j][0] = __float_as_uint(sh.l1.sB[(ko + tk) * 136 + nn]);
                    bf[j][1] = __float_as_uint(sh.l1.sB[(ko + tk + 4) * 136 + nn]);
                }
#pragma unroll
                for (int i = 0; i < 4; i++)
#pragma unroll
                    for (int j = 0; j < 4; j++) mma_tf32(cf[i][j], a[i], bf[j]);
            }
            __syncthreads();
        }

        float* Cp = vpool + (size_t)b * CCH * NPOOL;
        const int pcb = col0 >> 2;
#pragma unroll 1
        for (int s = 0; s < 4; s++) {
            if (wr == (s >> 1)) {
#pragma unroll
                for (int ii = 0; ii < 2; ii++) {
                    const int i = (s & 1) * 2 + ii;
#pragma unroll
                    for (int half = 0; half < 2; half++) {
                        const int lr = ii * 16 + half * 8 + g;
#pragma unroll
                        for (int j = 0; j < 4; j++) {
                            const int col = wc * 32 + j * 8 + 2 * tk;
                            sh.sX[lr * 132 + col]     = cf[i][j][half * 2 + 0];
                            sh.sX[lr * 132 + col + 1] = cf[i][j][half * 2 + 1];
                        }
                    }
                }
            }
            __syncthreads();
#pragma unroll
            for (int u = 0; u < 4; u++) {
                int po = tid + u * 256;
                int rr = po >> 5, pc = po & 31;
                float v = fmaxf(fmaxf(sh.sX[rr * 132 + 2 * pc], sh.sX[rr * 132 + 2 * pc + 1]),
                                fmaxf(sh.sX[rr * 132 + 64 + 2 * pc], sh.sX[rr * 132 + 64 + 2 * pc + 1]));
                const int r = r0 + s * 32 + rr;
                Cp[(size_t)r * NPOOL + pcb + pc] = tf32_rn(v + bv[r]);
            }
            __syncthreads();
        }
    }
}

// ============ pass-1 energy: column sums only (no p store) ====
__global__ __launch_bounds__(256)
void energy_cs(const float* __restrict__ kTg, const float* __restrict__ qTg,
               float* __restrict__ part)
{
    __shared__ float sA[128 * 36];
    __shared__ float sB[128 * 36];
    __shared__ float sX[16 * 132];

    const int b  = blockIdx.z;
    const int m0 = blockIdx.y * 128;
    const int n0 = blockIdx.x * 128;
    const float* Ab = kTg + ((size_t)b * NSP + m0) * CSP;
    const float* Bb = qTg + ((size_t)b * NPOOL + n0) * CSP;

    const int tid = threadIdx.x, lane = tid & 31, wid = tid >> 5;
    const int wr = wid >> 2, wc = wid & 3;
    const int g = lane >> 2, tk = lane & 3;

#pragma unroll
    for (int u = 0; u < 4; u++) {
        int idx = tid + u * 256;
        int r = idx >> 3, kq = (idx & 7) * 4;
        *(float4*)&sA[r * 36 + kq] = *(const float4*)&Ab[(size_t)r * CSP + kq];
        *(float4*)&sB[r * 36 + kq] = *(const float4*)&Bb[(size_t)r * CSP + kq];
    }
    __syncthreads();

    float cf[4][4][4] = {};
#pragma unroll
    for (int ks = 0; ks < 4; ks++) {
        const int ko = ks * 8;
        uint32_t a[4][4], bf[4][2];
#pragma unroll
        for (int i = 0; i < 4; i++) {
            const int ra = (wr * 64 + i * 16 + g) * 36 + ko + tk;
            a[i][0] = __float_as_uint(sA[ra]);
            a[i][1] = __float_as_uint(sA[ra + 8 * 36]);
            a[i][2] = __float_as_uint(sA[ra + 4]);
            a[i][3] = __float_as_uint(sA[ra + 8 * 36 + 4]);
        }
#pragma unroll
        for (int j = 0; j < 4; j++) {
            const int rb = (wc * 32 + j * 8 + g) * 36 + ko + tk;
            bf[j][0] = __float_as_uint(sB[rb]);
            bf[j][1] = __float_as_uint(sB[rb + 4]);
        }
#pragma unroll
        for (int i = 0; i < 4; i++)
#pragma unroll
            for (int j = 0; j < 4; j++) mma_tf32(cf[i][j], a[i], bf[j]);
    }

    // colsum: EXACT order as before (i, half, j; e0 then e1)
    float colsum[4][2] = {};
#pragma unroll
    for (int i = 0; i < 4; i++) {
#pragma unroll
        for (int half = 0; half < 2; half++) {
#pragma unroll
            for (int j = 0; j < 4; j++) {
                float e0 = __expf(cf[i][j][half * 2 + 0]);
                float e1 = __expf(cf[i][j][half * 2 + 1]);
                colsum[j][0] += e0;
                colsum[j][1] += e1;
            }
        }
    }
#pragma unroll
    for (int j = 0; j < 4; j++) {
        const int col = wc * 32 + j * 8 + 2 * tk;
        sX[(wr * 8 + g) * 132 + col]     = colsum[j][0];
        sX[(wr * 8 + g) * 132 + col + 1] = colsum[j][1];
    }
    __syncthreads();
    if (tid < 128) {
        float t = 0.f;
#pragma unroll
        for (int k = 0; k < 16; k++) t += sX[k * 132 + tid];
        part[((size_t)b * 32 + blockIdx.y) * NPOOL + n0 + tid] = t;
    }
}

// ================= vprime GEMM (unchanged) ============
#define GV_SA 2560
#define GV_SB 2176
__global__ __launch_bounds__(256)
void gemm_v2(const float* __restrict__ A,
             const float* __restrict__ B,
             float* __restrict__ C,
             int M, int N, int K)
{
    __shared__ float sm[2 * GV_SA + 2 * GV_SB];

    const int b  = blockIdx.z;
    const int r0 = blockIdx.y * 128;
    const int n0 = blockIdx.x * 128;
    const float* Ab = A;
    const float* Bb = B + (size_t)b * K * N;

    const int tid = threadIdx.x, lane = tid & 31, wid = tid >> 5;
    const int wr = wid >> 2, wc = wid & 3;
    const int g = lane >> 2, tk = lane & 3;

    const int a_r = tid >> 1, a_q = (tid & 1) * 2;
    const uint32_t smBase = (uint32_t)__cvta_generic_to_shared(sm);

    auto issue = [&](int k0, int s) {
#pragma unroll
        for (int u = 0; u < 2; u++) {
            int q = a_q + u;
            cpa16(smBase + (s * GV_SA + a_r * 20 + q * 4) * 4,
                  &Ab[(size_t)(r0 + a_r) * K + k0 + q * 4]);
        }
#pragma unroll
        for (int u = 0; u < 2; u++) {
            int idx = tid + u * 256;
            int kr = idx >> 5, nc = (idx & 31) * 4;
            cpa16(smBase + (2 * GV_SA + s * GV_SB + kr * 136 + nc) * 4,
                  &Bb[(size_t)(k0 + kr) * N + n0 + nc]);
        }
        asm volatile("cp.async.commit_group;");
    };

    float cf[4][4][4] = {};
    const int NIT = K / 16;

    issue(0, 0);
    for (int kt = 0; kt < NIT; kt++) {
        const int cur = kt & 1;
        if (kt < NIT - 1) {
            issue((kt + 1) * 16, cur ^ 1);
            asm volatile("cp.async.wait_group 1;");
        } else {
            asm volatile("cp.async.wait_group 0;");
        }
        __syncthreads();

        const float* cA = sm + cur * GV_SA;
        const float* cB = sm + 2 * GV_SA + cur * GV_SB;
#pragma unroll
        for (int ks = 0; ks < 2; ks++) {
            const int ko = ks * 8;
            uint32_t a[4][4], bf[4][2];
#pragma unroll
            for (int i = 0; i < 4; i++) {
                const int ra = (wr * 64 + i * 16 + g) * 20 + ko + tk;
                a[i][0] = __float_as_uint(cA[ra]);
                a[i][1] = __float_as_uint(cA[ra + 8 * 20]);
                a[i][2] = __float_as_uint(cA[ra + 4]);
                a[i][3] = __float_as_uint(cA[ra + 8 * 20 + 4]);
            }
#pragma unroll
            for (int j = 0; j < 4; j++) {
                const int nn = wc * 32 + j * 8 + g;
                bf[j][0] = __float_as_uint(cB[(ko + tk) * 136 + nn]);
                bf[j][1] = __float_as_uint(cB[(ko + tk + 4) * 136 + nn]);
            }
#pragma unroll
            for (int i = 0; i < 4; i++)
#pragma unroll
                for (int j = 0; j < 4; j++) mma_tf32(cf[i][j], a[i], bf[j]);
        }
        __syncthreads();
    }

    float* Cb = C + (size_t)b * M * N;
#pragma unroll
    for (int i = 0; i < 4; i++)
#pragma unroll
        for (int half = 0; half < 2; half++) {
            const int r = r0 + wr * 64 + i * 16 + g + half * 8;
            const size_t ro = (size_t)r * N;
#pragma unroll
            for (int j = 0; j < 4; j++) {
                const int c = n0 + wc * 32 + j * 8 + 2 * tk;
                float2 o;
                o.x = cf[i][j][half * 2 + 0];
                o.y = cf[i][j][half * 2 + 1];
                *(float2*)&Cb[ro + c] = o;
            }
        }
}

// ---------------- fused denominator + v'' (unchanged arithmetic) ------------
__global__ void norm_v_k(const float* __restrict__ part,
                         const float* __restrict__ vpr,
                         __nv_bfloat16* __restrict__ vppb)
{
    int idx = blockIdx.x * 256 + threadIdx.x;
    int b  = idx >> 10;
    int np = idx & 1023;
    const float* p = part + (size_t)b * 32 * NPOOL + np;
    float s = 0.f;
#pragma unroll
    for (int i = 0; i < 32; i++) s += p[(size_t)i * NPOOL];
    const float inv = 1.f / s;

    const int c0 = blockIdx.y * 32;
    const float* v = vpr + (size_t)b * CCH * NPOOL + np;
    __nv_bfloat16* o = vppb + (size_t)b * CCH * NPOOL + np;
#pragma unroll 8
    for (int c = c0; c < c0 + 32; c++)
        o[(size_t)c * NPOOL] = __float2bfloat16_rn(v[(size_t)c * NPOOL] * inv);
}

// ============ pass-2: fused energy-recompute + exp + attend ===========
// grid (NSP/128, 1, BATCH). Recomputes E tiles (identical values to pass 1),
// exponentiates to bf16 p-stage, contracts with v'' into out accumulators
// with final2's exact fragment mapping and np ordering -> bit-identical out.
#define AT_SKT 0                       // float offsets in dynamic smem
#define AT_SQT (128 * 36)
#define AT_PST (2 * 128 * 36)          // uint32 region starts here
#define AT_VA  (2 * 128 * 36 + 128 * 68)
#define AT_SMEM_BYTES ((2 * 128 * 36 + 128 * 68 + 256 * 68) * 4)   // 141,312

__global__ __launch_bounds__(256)
void attend_k(const float* __restrict__ kTg, const float* __restrict__ qTg,
              const __nv_bfloat16* __restrict__ vpp,
              const float* __restrict__ bo,
              const float* __restrict__ gamma,
              const float* __restrict__ xres,
              float* __restrict__ out)
{
    extern __shared__ float smem[];
    float* sKT = smem + AT_SKT;
    float* sQT = smem + AT_SQT;
    uint32_t* pstage = (uint32_t*)(smem + AT_PST);
    uint32_t* vA = (uint32_t*)(smem + AT_VA);

    const int tid = threadIdx.x, lane = tid & 31, wid = tid >> 5;
    const int b  = blockIdx.z;
    const int m0 = blockIdx.x * 128;
    const int g = lane >> 2, tk = lane & 3;
    // E-phase mapping (energy kernel layout)
    const int wr2 = wid >> 2, wc2 = wid & 3;
    // out-phase mapping (final2 layout)
    const int wr = wid >> 1, wc = wid & 1;

    const float* Akt = kTg + ((size_t)b * NSP + m0) * CSP;
    const __nv_bfloat16* Av = vpp + (size_t)b * CCH * NPOOL;

    // load kT rows (persistent)
#pragma unroll
    for (int u = 0; u < 2; u++) {
        int idx = tid + u * 256;
        int r = idx >> 2, kq = (idx & 3) * 8;
        *(float4*)&sKT[r * 36 + kq]     = *(const float4*)&Akt[(size_t)r * CSP + kq];
        *(float4*)&sKT[r * 36 + kq + 4] = *(const float4*)&Akt[(size_t)r * CSP + kq + 4];
    }

    float cfO[4][8][4] = {};

    for (int np0 = 0; np0 < NPOOL; np0 += 128) {
        __syncthreads();   // protect prior-iteration reads (and first-iter no-op)

        // qT chunk
        const float* Bq = qTg + ((size_t)b * NPOOL + np0) * CSP;
#pragma unroll
        for (int u = 0; u < 2; u++) {
            int idx = tid + u * 256;
            int r = idx >> 2, kq = (idx & 3) * 8;
            *(float4*)&sQT[r * 36 + kq]     = *(const float4*)&Bq[(size_t)r * CSP + kq];
            *(float4*)&sQT[r * 36 + kq + 4] = *(const float4*)&Bq[(size_t)r * CSP + kq + 4];
        }
        // v'' chunk: 256 rows x 128 bf16
#pragma unroll
        for (int u = 0; u < 16; u++) {
            int idx = tid + u * 256;
            int row = idx >> 4, q = idx & 15;
            *(uint4*)&vA[row * 68 + q * 4] =
                *(const uint4*)&Av[(size_t)row * NPOOL + np0 + q * 8];
        }
        __syncthreads();

        // E tile (identical fragments/order to energy kernel)
        float cf2[4][4][4] = {};
#pragma unroll
        for (int ks = 0; ks < 4; ks++) {
            const int ko = ks * 8;
            uint32_t a[4][4], bf[4][2];
#pragma unroll
            for (int i = 0; i < 4; i++) {
                const int ra = (wr2 * 64 + i * 16 + g) * 36 + ko + tk;
                a[i][0] = __float_as_uint(sKT[ra]);
                a[i][1] = __float_as_uint(sKT[ra + 8 * 36]);
                a[i][2] = __float_as_uint(sKT[ra + 4]);
                a[i][3] = __float_as_uint(sKT[ra + 8 * 36 + 4]);
            }
#pragma unroll
            for (int j = 0; j < 4; j++) {
                const int rb = (wc2 * 32 + j * 8 + g) * 36 + ko + tk;
                bf[j][0] = __float_as_uint(sQT[rb]);
                bf[j][1] = __float_as_uint(sQT[rb + 4]);
            }
#pragma unroll
            for (int i = 0; i < 4; i++)
#pragma unroll
                for (int j = 0; j < 4; j++) mma_tf32(cf2[i][j], a[i], bf[j]);
        }

        // exp -> bf16 p-stage (identical values to old attn)
#pragma unroll
        for (int i = 0; i < 4; i++) {
#pragma unroll
            for (int half = 0; half < 2; half++) {
                const int lr = wr2 * 64 + i * 16 + half * 8 + g;
#pragma unroll
                for (int j = 0; j < 4; j++) {
                    const int lc2 = wc2 * 16 + j * 4 + tk;
                    float e0 = __expf(cf2[i][j][half * 2 + 0]);
                    float e1 = __expf(cf2[i][j][half * 2 + 1]);
                    __nv_bfloat162 p2 = __floats2bfloat162_rn(e0, e1);
                    pstage[lr * 68 + lc2] = *(uint32_t*)&p2;
                }
            }
        }
        __syncthreads();

        // out contraction over this np chunk: 8 k-steps of 16 (final2 order)
#pragma unroll
        for (int ks2 = 0; ks2 < 8; ks2++) {
            uint32_t a[4][4], bf[8][2];
#pragma unroll
            for (int i = 0; i < 4; i++) {
                const int ra = (wr * 64 + i * 16 + g) * 68 + ks2 * 8 + tk;
                a[i][0] = vA[ra];
                a[i][1] = vA[ra + 8 * 68];
                a[i][2] = vA[ra + 4];
                a[i][3] = vA[ra + 8 * 68 + 4];
            }
#pragma unroll
            for (int j = 0; j < 8; j++) {
                const int rb = (wc * 64 + j * 8 + g) * 68 + ks2 * 8 + tk;
                bf[j][0] = pstage[rb];
                bf[j][1] = pstage[rb + 4];
            }
#pragma unroll
            for (int i = 0; i < 4; i++)
#pragma unroll
                for (int j = 0; j < 8; j++) mma_bf16(cfO[i][j], a[i], bf[j]);
        }
    }

    // epilogue (identical to final2)
    const float gm = gamma[0];
#pragma unroll
    for (int i = 0; i < 4; i++) {
#pragma unroll
        for (int half = 0; half < 2; half++) {
            const int c = wr * 64 + i * 16 + g + half * 8;
            const float bc = bo[c];
            const size_t ro = ((size_t)b * CCH + c) * NSP;
#pragma unroll
            for (int j = 0; j < 8; j++) {
                const int m = m0 + wc * 64 + j * 8 + 2 * tk;
                float2 xr = *(const float2*)&xres[ro + m];
                float2 o;
                o.x = gm * (cfO[i][j][half * 2 + 0] + bc) + xr.x;
                o.y = gm * (cfO[i][j][half * 2 + 1] + bc) + xr.y;
                *(float2*)&out[ro + m] = o;
            }
        }
    }
}

// ---------------- launch ----------------
extern "C" void kernel_launch(void* const* d_in, const int* in_sizes, int n_in,
                              void* d_out, int out_size)
{
    const float* x     = (const float*)d_in[0];
    const float* wq    = (const float*)d_in[1];
    const float* bq    = (const float*)d_in[2];
    const float* wk    = (const float*)d_in[3];
    const float* bk    = (const float*)d_in[4];
    const float* wv    = (const float*)d_in[5];
    const float* bv    = (const float*)d_in[6];
    const float* wo    = (const float*)d_in[7];
    const float* bo    = (const float*)d_in[8];
    const float* gamma = (const float*)d_in[9];
    float* out = (float*)d_out;

    float *pkT, *pqT, *pwor, *pvp, *pvpr, *ppart;
    __nv_bfloat16 *pvppb;
    cudaGetSymbolAddress((void**)&pkT,    g_kT);
    cudaGetSymbolAddress((void**)&pqT,    g_qT);
    cudaGetSymbolAddress((void**)&pwor,   g_wor);
    cudaGetSymbolAddress((void**)&pvp,    g_vpool);
    cudaGetSymbolAddress((void**)&pvpr,   g_vprime);
    cudaGetSymbolAddress((void**)&ppart,  g_part);
    cudaGetSymbolAddress((void**)&pvppb,  g_vppb);

    static cudaStream_t s1 = nullptr;
    static cudaEvent_t evFork = nullptr, evQKV = nullptr, evJoin = nullptr;
    if (s1 == nullptr) {
        cudaStreamCreateWithFlags(&s1, cudaStreamNonBlocking);
        cudaEventCreateWithFlags(&evFork, cudaEventDisableTiming);
        cudaEventCreateWithFlags(&evQKV,  cudaEventDisableTiming);
        cudaEventCreateWithFlags(&evJoin, cudaEventDisableTiming);
        cudaFuncSetAttribute(attend_k, cudaFuncAttributeMaxDynamicSharedMemorySize,
                             AT_SMEM_BYTES);
    }

    cudaEventRecord(evFork, 0);
    cudaStreamWaitEvent(s1, evFork, 0);

    // s1: tiny wo rounding
    round_wo_k<<<(CCH * CCH) / 1024, 256, 0, s1>>>(wo, pwor);

    // main: fused conv_qkv
    {
        dim3 g(NSP / 128, 3, BATCH);
        conv_qkv_mma<<<g, 256>>>(wk, bk, wq, bq, wv, bv, x, pkT, pqT, pvp);
    }
    cudaEventRecord(evQKV, 0);
    cudaStreamWaitEvent(s1, evQKV, 0);

    // s1: vprime (overlaps energy_cs on main)
    {
        dim3 g(NPOOL / 128, CCH / 128, BATCH);
        gemm_v2<<<g, 256, 0, s1>>>(pwor, pvp, pvpr, CCH, NPOOL, CCH);
    }
    cudaEventRecord(evJoin, s1);

    // main: pass-1 energy (column sums only)
    {
        dim3 g(NPOOL / 128, NSP / 128, BATCH);
        energy_cs<<<g, 256>>>(pkT, pqT, ppart);
    }

    // join, normalize -> v'' bf16, then fused attend
    cudaStreamWaitEvent(0, evJoin, 0);
    {
        dim3 g(BATCH * NPOOL / 256, CCH / 32);
        norm_v_k<<<g, 256>>>(ppart, pvpr, pvppb);
    }
    {
        dim3 g(NSP / 128, 1, BATCH);
        attend_k<<<g, 256, AT_SMEM_BYTES>>>(pkT, pqT, pvppb, bo, gamma, x, out);
    }
}

// round 14
// speedup vs baseline: 1.1665x; 1.0155x over previous
#include <cuda_runtime.h>
#include <cuda_bf16.h>
#include <math.h>
#include <stdint.h>

#define BATCH 16
#define CCH   256
#define NSP   4096   // 64*64
#define CSP   32     // C/8
#define NPOOL 1024   // 32*32

// ---------------- scratch ----------------
__device__ float g_kT[BATCH * NSP * CSP];                    //  8 MB tf32 (B, n, 32)
__device__ float g_qT[BATCH * NPOOL * CSP];                  //  2 MB tf32 (B, np, 32)
__device__ float g_wor[CCH * CCH];                           // 256 KB tf32-RN wo
__device__ float g_vpool[BATCH * CCH * NPOOL];               // 16 MB (tf32-RN values)
__device__ float g_vprime[BATCH * CCH * NPOOL];              // 16 MB
__device__ float g_part[BATCH * 32 * NPOOL];                 //  2 MB
__device__ __nv_bfloat16 g_vppb[BATCH * CCH * NPOOL];        //  8 MB

// ---------------- helpers ----------------
__device__ __forceinline__ float tf32_rn(float v) {
    uint32_t u;
    asm("cvt.rna.tf32.f32 %0, %1;" : "=r"(u) : "f"(v));
    return __uint_as_float(u);
}
__device__ __forceinline__ void mma_tf32(float* c, const uint32_t* a, const uint32_t* b) {
    asm volatile(
        "mma.sync.aligned.m16n8k8.row.col.f32.tf32.tf32.f32 "
        "{%0,%1,%2,%3}, {%4,%5,%6,%7}, {%8,%9}, {%0,%1,%2,%3};"
        : "+f"(c[0]), "+f"(c[1]), "+f"(c[2]), "+f"(c[3])
        : "r"(a[0]), "r"(a[1]), "r"(a[2]), "r"(a[3]), "r"(b[0]), "r"(b[1]));
}
__device__ __forceinline__ void mma_bf16(float* c, const uint32_t* a, const uint32_t* b) {
    asm volatile(
        "mma.sync.aligned.m16n8k16.row.col.f32.bf16.bf16.f32 "
        "{%0,%1,%2,%3}, {%4,%5,%6,%7}, {%8,%9}, {%0,%1,%2,%3};"
        : "+f"(c[0]), "+f"(c[1]), "+f"(c[2]), "+f"(c[3])
        : "r"(a[0]), "r"(a[1]), "r"(a[2]), "r"(a[3]), "r"(b[0]), "r"(b[1]));
}
__device__ __forceinline__ void cpa16(uint32_t dst, const void* src) {
    asm volatile("cp.async.cg.shared.global [%0], [%1], 16;" :: "r"(dst), "l"(src));
}

// ---------------- pre-round wo to tf32-RN ----------------
__global__ void round_wo_k(const float* __restrict__ wo, float* __restrict__ wor)
{
    int i = (blockIdx.x * 256 + threadIdx.x) * 4;
    float4 b = *(const float4*)&wo[i];
    b.x = tf32_rn(b.x); b.y = tf32_rn(b.y); b.z = tf32_rn(b.z); b.w = tf32_rn(b.w);
    *(float4*)&wor[i] = b;
}

// ============ fused conv_q + conv_k + conv_v via tf32 mma (proven) ======
__global__ __launch_bounds__(256)
void conv_qkv_mma(const float* __restrict__ wk, const float* __restrict__ bk,
                  const float* __restrict__ wq, const float* __restrict__ bq,
                  const float* __restrict__ wv, const float* __restrict__ bv,
                  const float* __restrict__ x,
                  float* __restrict__ kT, float* __restrict__ qT,
                  float* __restrict__ vpool)
{
    __shared__ union {
        struct { float sA[64 * 20];  float sB[128 * 20]; } l0;
        struct { float sA[128 * 20]; float sB[16 * 136]; } l1;
        float sOut[64 * 132];
        float sX[32 * 132];
    } sh;

    const int b    = blockIdx.z;
    const int y    = blockIdx.y;
    const int col0 = blockIdx.x * 128;
    const float* xb = x + (size_t)b * CCH * NSP;
    const int tid = threadIdx.x, lane = tid & 31, wid = tid >> 5;
    const int wr = wid >> 2, wc = wid & 3;
    const int g = lane >> 2, tk = lane & 3;

    if (y == 0) {
        float cf[2][4][4] = {};

        for (int k0 = 0; k0 < CCH; k0 += 16) {
            {
                int r = tid >> 2, kq = (tid & 3) * 4;
                const float* wrow = (r < 32) ? (wk + r * CCH) : (wq + (r - 32) * CCH);
                float4 v = *(const float4*)&wrow[k0 + kq];
                v.x = tf32_rn(v.x); v.y = tf32_rn(v.y);
                v.z = tf32_rn(v.z); v.w = tf32_rn(v.w);
                *(float4*)&sh.l0.sA[r * 20 + kq] = v;
            }
#pragma unroll
            for (int u = 0; u < 2; u++) {
                int idx = tid + u * 256;
                int kr = idx >> 5, nc = (idx & 31) * 4;
                float4 v = *(const float4*)&xb[(size_t)(k0 + kr) * NSP + col0 + nc];
                sh.l0.sB[(nc + 0) * 20 + kr] = tf32_rn(v.x);
                sh.l0.sB[(nc + 1) * 20 + kr] = tf32_rn(v.y);
                sh.l0.sB[(nc + 2) * 20 + kr] = tf32_rn(v.z);
                sh.l0.sB[(nc + 3) * 20 + kr] = tf32_rn(v.w);
            }
            __syncthreads();
#pragma unroll
            for (int ks = 0; ks < 2; ks++) {
                const int ko = ks * 8;
                uint32_t a[2][4], bf[4][2];
#pragma unroll
                for (int i = 0; i < 2; i++) {
                    const int ra = (wr * 32 + i * 16 + g) * 20 + ko + tk;
                    a[i][0] = __float_as_uint(sh.l0.sA[ra]);
                    a[i][1] = __float_as_uint(sh.l0.sA[ra + 8 * 20]);
                    a[i][2] = __float_as_uint(sh.l0.sA[ra + 4]);
                    a[i][3] = __float_as_uint(sh.l0.sA[ra + 8 * 20 + 4]);
                }
#pragma unroll
                for (int j = 0; j < 4; j++) {
                    const int rb = (wc * 32 + j * 8 + g) * 20 + ko + tk;
                    bf[j][0] = __float_as_uint(sh.l0.sB[rb]);
                    bf[j][1] = __float_as_uint(sh.l0.sB[rb + 4]);
                }
#pragma unroll
                for (int i = 0; i < 2; i++)
#pragma unroll
                    for (int j = 0; j < 4; j++) mma_tf32(cf[i][j], a[i], bf[j]);
            }
            __syncthreads();
        }

#pragma unroll
        for (int i = 0; i < 2; i++)
#pragma unroll
            for (int half = 0; half < 2; half++) {
                const int r = wr * 32 + i * 16 + half * 8 + g;
#pragma unroll
                for (int j = 0; j < 4; j++) {
                    const int c = wc * 32 + j * 8 + 2 * tk;
                    sh.sOut[r * 132 + c]     = cf[i][j][half * 2 + 0];
                    sh.sOut[r * 132 + c + 1] = cf[i][j][half * 2 + 1];
                }
            }
        __syncthreads();

        float* kTb = kT + (size_t)b * NSP * CSP;
#pragma unroll
        for (int u = 0; u < 4; u++) {
            int idx = tid + u * 256;
            int nn = idx >> 3, csq = (idx & 7) * 4;
            float4 o;
            o.x = tf32_rn(sh.sOut[(csq + 0) * 132 + nn] + bk[csq + 0]);
            o.y = tf32_rn(sh.sOut[(csq + 1) * 132 + nn] + bk[csq + 1]);
            o.z = tf32_rn(sh.sOut[(csq + 2) * 132 + nn] + bk[csq + 2]);
            o.w = tf32_rn(sh.sOut[(csq + 3) * 132 + nn] + bk[csq + 3]);
            *(float4*)&kTb[(size_t)(col0 + nn) * CSP + csq] = o;
        }

        float* qTb = qT + (size_t)b * NPOOL * CSP;
        const int hp = col0 >> 7;
        {
            int wp = tid >> 3, csq = (tid & 7) * 4;
            float4 o;
            float* oc = &o.x;
#pragma unroll
            for (int t = 0; t < 4; t++) {
                const int cs = csq + t;
                const float* r = &sh.sOut[(32 + cs) * 132];
                float v = fmaxf(fmaxf(r[2 * wp], r[2 * wp + 1]),
                                fmaxf(r[64 + 2 * wp], r[64 + 2 * wp + 1]));
                oc[t] = tf32_rn(v + bq[cs]);
            }
            *(float4*)&qTb[(size_t)(hp * 32 + wp) * CSP + csq] = o;
        }
    } else {
        const int r0 = (y - 1) * 128;
        float cf[4][4][4] = {};

        for (int k0 = 0; k0 < CCH; k0 += 16) {
            {
                int r = tid >> 1, kq = (tid & 1) * 8;
#pragma unroll
                for (int q = 0; q < 2; q++) {
                    float4 v = *(const float4*)&wv[(size_t)(r0 + r) * CCH + k0 + kq + q * 4];
                    v.x = tf32_rn(v.x); v.y = tf32_rn(v.y);
                    v.z = tf32_rn(v.z); v.w = tf32_rn(v.w);
                    *(float4*)&sh.l1.sA[r * 20 + kq + q * 4] = v;
                }
            }
#pragma unroll
            for (int u = 0; u < 2; u++) {
                int idx = tid + u * 256;
                int kr = idx >> 5, nc = (idx & 31) * 4;
                float4 v = *(const float4*)&xb[(size_t)(k0 + kr) * NSP + col0 + nc];
                v.x = tf32_rn(v.x); v.y = tf32_rn(v.y);
                v.z = tf32_rn(v.z); v.w = tf32_rn(v.w);
                *(float4*)&sh.l1.sB[kr * 136 + nc] = v;
            }
            __syncthreads();
#pragma unroll
            for (int ks = 0; ks < 2; ks++) {
                const int ko = ks * 8;
                uint32_t a[4][4], bf[4][2];
#pragma unroll
                for (int i = 0; i < 4; i++) {
                    const int ra = (wr * 64 + i * 16 + g) * 20 + ko + tk;
                    a[i][0] = __float_as_uint(sh.l1.sA[ra]);
                    a[i][1] = __float_as_uint(sh.l1.sA[ra + 8 * 20]);
                    a[i][2] = __float_as_uint(sh.l1.sA[ra + 4]);
                    a[i][3] = __float_as_uint(sh.l1.sA[ra + 8 * 20 + 4]);
                }
#pragma unroll
                for (int j = 0; j < 4; j++) {
                    const int nn = wc * 32 + j * 8 + g;
                    bf[j][0] = __float_as_uint(sh.l1.sB[(ko + tk) * 136 + nn]);
                    bf[j][1] = __float_as_uint(sh.l1.sB[(ko + tk + 4) * 136 + nn]);
                }
#pragma unroll
                for (int i = 0; i < 4; i++)
#pragma unroll
                    for (int j = 0; j < 4; j++) mma_tf32(cf[i][j], a[i], bf[j]);
            }
            __syncthreads();
        }

        float* Cp = vpool + (size_t)b * CCH * NPOOL;
        const int pcb = col0 >> 2;
#pragma unroll 1
        for (int s = 0; s < 4; s++) {
            if (wr == (s >> 1)) {
#pragma unroll
                for (int ii = 0; ii < 2; ii++) {
                    const int i = (s & 1) * 2 + ii;
#pragma unroll
                    for (int half = 0; half < 2; half++) {
                        const int lr = ii * 16 + half * 8 + g;
#pragma unroll
                        for (int j = 0; j < 4; j++) {
                            const int col = wc * 32 + j * 8 + 2 * tk;
                            sh.sX[lr * 132 + col]     = cf[i][j][half * 2 + 0];
                            sh.sX[lr * 132 + col + 1] = cf[i][j][half * 2 + 1];
                        }
                    }
                }
            }
            __syncthreads();
#pragma unroll
            for (int u = 0; u < 4; u++) {
                int po = tid + u * 256;
                int rr = po >> 5, pc = po & 31;
                float v = fmaxf(fmaxf(sh.sX[rr * 132 + 2 * pc], sh.sX[rr * 132 + 2 * pc + 1]),
                                fmaxf(sh.sX[rr * 132 + 64 + 2 * pc], sh.sX[rr * 132 + 64 + 2 * pc + 1]));
                const int r = r0 + s * 32 + rr;
                Cp[(size_t)r * NPOOL + pcb + pc] = tf32_rn(v + bv[r]);
            }
            __syncthreads();
        }
    }
}

// ============ pass-1 energy: column sums only ====
__global__ __launch_bounds__(256)
void energy_cs(const float* __restrict__ kTg, const float* __restrict__ qTg,
               float* __restrict__ part)
{
    __shared__ float sA[128 * 36];
    __shared__ float sB[128 * 36];
    __shared__ float sX[16 * 132];

    const int b  = blockIdx.z;
    const int m0 = blockIdx.y * 128;
    const int n0 = blockIdx.x * 128;
    const float* Ab = kTg + ((size_t)b * NSP + m0) * CSP;
    const float* Bb = qTg + ((size_t)b * NPOOL + n0) * CSP;

    const int tid = threadIdx.x, lane = tid & 31, wid = tid >> 5;
    const int wr = wid >> 2, wc = wid & 3;
    const int g = lane >> 2, tk = lane & 3;

#pragma unroll
    for (int u = 0; u < 4; u++) {
        int idx = tid + u * 256;
        int r = idx >> 3, kq = (idx & 7) * 4;
        *(float4*)&sA[r * 36 + kq] = *(const float4*)&Ab[(size_t)r * CSP + kq];
        *(float4*)&sB[r * 36 + kq] = *(const float4*)&Bb[(size_t)r * CSP + kq];
    }
    __syncthreads();

    float cf[4][4][4] = {};
#pragma unroll
    for (int ks = 0; ks < 4; ks++) {
        const int ko = ks * 8;
        uint32_t a[4][4], bf[4][2];
#pragma unroll
        for (int i = 0; i < 4; i++) {
            const int ra = (wr * 64 + i * 16 + g) * 36 + ko + tk;
            a[i][0] = __float_as_uint(sA[ra]);
            a[i][1] = __float_as_uint(sA[ra + 8 * 36]);
            a[i][2] = __float_as_uint(sA[ra + 4]);
            a[i][3] = __float_as_uint(sA[ra + 8 * 36 + 4]);
        }
#pragma unroll
        for (int j = 0; j < 4; j++) {
            const int rb = (wc * 32 + j * 8 + g) * 36 + ko + tk;
            bf[j][0] = __float_as_uint(sB[rb]);
            bf[j][1] = __float_as_uint(sB[rb + 4]);
        }
#pragma unroll
        for (int i = 0; i < 4; i++)
#pragma unroll
            for (int j = 0; j < 4; j++) mma_tf32(cf[i][j], a[i], bf[j]);
    }

    float colsum[4][2] = {};
#pragma unroll
    for (int i = 0; i < 4; i++) {
#pragma unroll
        for (int half = 0; half < 2; half++) {
#pragma unroll
            for (int j = 0; j < 4; j++) {
                float e0 = __expf(cf[i][j][half * 2 + 0]);
                float e1 = __expf(cf[i][j][half * 2 + 1]);
                colsum[j][0] += e0;
                colsum[j][1] += e1;
            }
        }
    }
#pragma unroll
    for (int j = 0; j < 4; j++) {
        const int col = wc * 32 + j * 8 + 2 * tk;
        sX[(wr * 8 + g) * 132 + col]     = colsum[j][0];
        sX[(wr * 8 + g) * 132 + col + 1] = colsum[j][1];
    }
    __syncthreads();
    if (tid < 128) {
        float t = 0.f;
#pragma unroll
        for (int k = 0; k < 16; k++) t += sX[k * 132 + tid];
        part[((size_t)b * 32 + blockIdx.y) * NPOOL + n0 + tid] = t;
    }
}

// ================= vprime GEMM (unchanged) ============
#define GV_SA 2560
#define GV_SB 2176
__global__ __launch_bounds__(256)
void gemm_v2(const float* __restrict__ A,
             const float* __restrict__ B,
             float* __restrict__ C,
             int M, int N, int K)
{
    __shared__ float sm[2 * GV_SA + 2 * GV_SB];

    const int b  = blockIdx.z;
    const int r0 = blockIdx.y * 128;
    const int n0 = blockIdx.x * 128;
    const float* Ab = A;
    const float* Bb = B + (size_t)b * K * N;

    const int tid = threadIdx.x, lane = tid & 31, wid = tid >> 5;
    const int wr = wid >> 2, wc = wid & 3;
    const int g = lane >> 2, tk = lane & 3;

    const int a_r = tid >> 1, a_q = (tid & 1) * 2;
    const uint32_t smBase = (uint32_t)__cvta_generic_to_shared(sm);

    auto issue = [&](int k0, int s) {
#pragma unroll
        for (int u = 0; u < 2; u++) {
            int q = a_q + u;
            cpa16(smBase + (s * GV_SA + a_r * 20 + q * 4) * 4,
                  &Ab[(size_t)(r0 + a_r) * K + k0 + q * 4]);
        }
#pragma unroll
        for (int u = 0; u < 2; u++) {
            int idx = tid + u * 256;
            int kr = idx >> 5, nc = (idx & 31) * 4;
            cpa16(smBase + (2 * GV_SA + s * GV_SB + kr * 136 + nc) * 4,
                  &Bb[(size_t)(k0 + kr) * N + n0 + nc]);
        }
        asm volatile("cp.async.commit_group;");
    };

    float cf[4][4][4] = {};
    const int NIT = K / 16;

    issue(0, 0);
    for (int kt = 0; kt < NIT; kt++) {
        const int cur = kt & 1;
        if (kt < NIT - 1) {
            issue((kt + 1) * 16, cur ^ 1);
            asm volatile("cp.async.wait_group 1;");
        } else {
            asm volatile("cp.async.wait_group 0;");
        }
        __syncthreads();

        const float* cA = sm + cur * GV_SA;
        const float* cB = sm + 2 * GV_SA + cur * GV_SB;
#pragma unroll
        for (int ks = 0; ks < 2; ks++) {
            const int ko = ks * 8;
            uint32_t a[4][4], bf[4][2];
#pragma unroll
            for (int i = 0; i < 4; i++) {
                const int ra = (wr * 64 + i * 16 + g) * 20 + ko + tk;
                a[i][0] = __float_as_uint(cA[ra]);
                a[i][1] = __float_as_uint(cA[ra + 8 * 20]);
                a[i][2] = __float_as_uint(cA[ra + 4]);
                a[i][3] = __float_as_uint(cA[ra + 8 * 20 + 4]);
            }
#pragma unroll
            for (int j = 0; j < 4; j++) {
                const int nn = wc * 32 + j * 8 + g;
                bf[j][0] = __float_as_uint(cB[(ko + tk) * 136 + nn]);
                bf[j][1] = __float_as_uint(cB[(ko + tk + 4) * 136 + nn]);
            }
#pragma unroll
            for (int i = 0; i < 4; i++)
#pragma unroll
                for (int j = 0; j < 4; j++) mma_tf32(cf[i][j], a[i], bf[j]);
        }
        __syncthreads();
    }

    float* Cb = C + (size_t)b * M * N;
#pragma unroll
    for (int i = 0; i < 4; i++)
#pragma unroll
        for (int half = 0; half < 2; half++) {
            const int r = r0 + wr * 64 + i * 16 + g + half * 8;
            const size_t ro = (size_t)r * N;
#pragma unroll
            for (int j = 0; j < 4; j++) {
                const int c = n0 + wc * 32 + j * 8 + 2 * tk;
                float2 o;
                o.x = cf[i][j][half * 2 + 0];
                o.y = cf[i][j][half * 2 + 1];
                *(float2*)&Cb[ro + c] = o;
            }
        }
}

// ---------------- fused denominator + v'' (unchanged arithmetic) ------------
__global__ void norm_v_k(const float* __restrict__ part,
                         const float* __restrict__ vpr,
                         __nv_bfloat16* __restrict__ vppb)
{
    int idx = blockIdx.x * 256 + threadIdx.x;
    int b  = idx >> 10;
    int np = idx & 1023;
    const float* p = part + (size_t)b * 32 * NPOOL + np;
    float s = 0.f;
#pragma unroll
    for (int i = 0; i < 32; i++) s += p[(size_t)i * NPOOL];
    const float inv = 1.f / s;

    const int c0 = blockIdx.y * 32;
    const float* v = vpr + (size_t)b * CCH * NPOOL + np;
    __nv_bfloat16* o = vppb + (size_t)b * CCH * NPOOL + np;
#pragma unroll 8
    for (int c = c0; c < c0 + 32; c++)
        o[(size_t)c * NPOOL] = __float2bfloat16_rn(v[(size_t)c * NPOOL] * inv);
}

// ============ pass-2: pipelined fused attend (np chunk = 64, 2-buffer) =======
// smem (floats): kT 128*36 | qT[2] 64*36 each | pstage 128*36 (u32) | vA[2] 256*36 (u32) each
#define AT2_KT 0
#define AT2_QT 4608
#define AT2_PS 9216
#define AT2_VA 13824
#define AT2_SMEM_BYTES ((13824 + 2 * 9216) * 4)   // 129,024

__global__ __launch_bounds__(256)
void attend_k(const float* __restrict__ kTg, const float* __restrict__ qTg,
              const __nv_bfloat16* __restrict__ vpp,
              const float* __restrict__ bo,
              const float* __restrict__ gamma,
              const float* __restrict__ xres,
              float* __restrict__ out)
{
    extern __shared__ float smem[];
    float* sKT = smem + AT2_KT;
    float* sQT = smem + AT2_QT;                  // [2][64*36]
    uint32_t* pstage = (uint32_t*)(smem + AT2_PS);
    uint32_t* vA = (uint32_t*)(smem + AT2_VA);   // [2][256*36]

    const int tid = threadIdx.x, lane = tid & 31, wid = tid >> 5;
    const int b  = blockIdx.z;
    const int m0 = blockIdx.x * 128;
    const int g = lane >> 2, tk = lane & 3;
    // E-phase mapping: 128 n x 64 np -> wr2 (4 x 32 n), wc2 (2 x 32 np)
    const int wr2 = wid >> 1, wc2 = wid & 1;
    // out-phase mapping (final2 layout): wr (4 x 64 c), wc (2 x 64 m)
    const int wr = wid >> 1, wc = wid & 1;

    const float* Akt = kTg + ((size_t)b * NSP + m0) * CSP;
    const __nv_bfloat16* Av = vpp + (size_t)b * CCH * NPOOL;
    const uint32_t smBase = (uint32_t)__cvta_generic_to_shared(smem);

    // kT rows (persistent, sync load once)
#pragma unroll
    for (int u = 0; u < 2; u++) {
        int idx = tid + u * 256;
        int r = idx >> 2, kq = (idx & 3) * 8;
        *(float4*)&sKT[r * 36 + kq]     = *(const float4*)&Akt[(size_t)r * CSP + kq];
        *(float4*)&sKT[r * 36 + kq + 4] = *(const float4*)&Akt[(size_t)r * CSP + kq + 4];
    }

    // async chunk loader: qT 64x32 fp32 (2 uint4/thr) + vA 256x32 u32 (8 uint4/thr)
    auto issue = [&](int c, int s) {
        const int np0 = c * 64;
        const float* Bq = qTg + ((size_t)b * NPOOL + np0) * CSP;
#pragma unroll
        for (int u = 0; u < 2; u++) {
            int idx = tid + u * 256;
            int r = idx >> 3, kq = (idx & 7) * 4;
            cpa16(smBase + (AT2_QT + s * 64 * 36 + r * 36 + kq) * 4,
                  &Bq[(size_t)r * CSP + kq]);
        }
#pragma unroll
        for (int u = 0; u < 8; u++) {
            int idx = tid + u * 256;
            int row = idx >> 3, q = idx & 7;
            cpa16(smBase + (AT2_VA + s * 256 * 36 + row * 36 + q * 4) * 4,
                  &Av[(size_t)row * NPOOL + np0 + q * 8]);
        }
        asm volatile("cp.async.commit_group;");
    };

    float cfO[4][8][4] = {};

    issue(0, 0);
    issue(1, 1);
    for (int c = 0; c < 16; c++) {
        const int cur = c & 1;
        if (c < 15) asm volatile("cp.async.wait_group 1;");
        else        asm volatile("cp.async.wait_group 0;");
        __syncthreads();

        const float* cQ = sQT + cur * 64 * 36;
        const uint32_t* cV = vA + cur * 256 * 36;

        // E tile 128 x 64 (same k-chain as energy_cs -> identical values)
        float cf2[2][4][4] = {};
#pragma unroll
        for (int ks = 0; ks < 4; ks++) {
            const int ko = ks * 8;
            uint32_t a[2][4], bf[4][2];
#pragma unroll
            for (int i = 0; i < 2; i++) {
                const int ra = (wr2 * 32 + i * 16 + g) * 36 + ko + tk;
                a[i][0] = __float_as_uint(sKT[ra]);
                a[i][1] = __float_as_uint(sKT[ra + 8 * 36]);
                a[i][2] = __float_as_uint(sKT[ra + 4]);
                a[i][3] = __float_as_uint(sKT[ra + 8 * 36 + 4]);
            }
#pragma unroll
            for (int j = 0; j < 4; j++) {
                const int rb = (wc2 * 32 + j * 8 + g) * 36 + ko + tk;
                bf[j][0] = __float_as_uint(cQ[rb]);
                bf[j][1] = __float_as_uint(cQ[rb + 4]);
            }
#pragma unroll
            for (int i = 0; i < 2; i++)
#pragma unroll
                for (int j = 0; j < 4; j++) mma_tf32(cf2[i][j], a[i], bf[j]);
        }

        // exp -> bf16 p-stage
#pragma unroll
        for (int i = 0; i < 2; i++) {
#pragma unroll
            for (int half = 0; half < 2; half++) {
                const int lr = wr2 * 32 + i * 16 + half * 8 + g;
#pragma unroll
                for (int j = 0; j < 4; j++) {
                    const int lc2 = wc2 * 16 + j * 4 + tk;
                    float e0 = __expf(cf2[i][j][half * 2 + 0]);
                    float e1 = __expf(cf2[i][j][half * 2 + 1]);
                    __nv_bfloat162 p2 = __floats2bfloat162_rn(e0, e1);
                    pstage[lr * 36 + lc2] = *(uint32_t*)&p2;
                }
            }
        }
        __syncthreads();

        // out contraction: 4 k-steps of 16 (global np order preserved)
#pragma unroll
        for (int ks2 = 0; ks2 < 4; ks2++) {
            uint32_t a[4][4], bf[8][2];
#pragma unroll
            for (int i = 0; i < 4; i++) {
                const int ra = (wr * 64 + i * 16 + g) * 36 + ks2 * 8 + tk;
                a[i][0] = cV[ra];
                a[i][1] = cV[ra + 8 * 36];
                a[i][2] = cV[ra + 4];
                a[i][3] = cV[ra + 8 * 36 + 4];
            }
#pragma unroll
            for (int j = 0; j < 8; j++) {
                const int rb = (wc * 64 + j * 8 + g) * 36 + ks2 * 8 + tk;
                bf[j][0] = pstage[rb];
                bf[j][1] = pstage[rb + 4];
            }
#pragma unroll
            for (int i = 0; i < 4; i++)
#pragma unroll
                for (int j = 0; j < 8; j++) mma_bf16(cfO[i][j], a[i], bf[j]);
        }
        __syncthreads();   // buffer + pstage reuse safe

        if (c + 2 < 16) issue(c + 2, cur);
    }

    // epilogue (identical to final2)
    const float gm = gamma[0];
#pragma unroll
    for (int i = 0; i < 4; i++) {
#pragma unroll
        for (int half = 0; half < 2; half++) {
            const int c = wr * 64 + i * 16 + g + half * 8;
            const float bc = bo[c];
            const size_t ro = ((size_t)b * CCH + c) * NSP;
#pragma unroll
            for (int j = 0; j < 8; j++) {
                const int m = m0 + wc * 64 + j * 8 + 2 * tk;
                float2 xr = *(const float2*)&xres[ro + m];
                float2 o;
                o.x = gm * (cfO[i][j][half * 2 + 0] + bc) + xr.x;
                o.y = gm * (cfO[i][j][half * 2 + 1] + bc) + xr.y;
                *(float2*)&out[ro + m] = o;
            }
        }
    }
}

// ---------------- launch ----------------
extern "C" void kernel_launch(void* const* d_in, const int* in_sizes, int n_in,
                              void* d_out, int out_size)
{
    const float* x     = (const float*)d_in[0];
    const float* wq    = (const float*)d_in[1];
    const float* bq    = (const float*)d_in[2];
    const float* wk    = (const float*)d_in[3];
    const float* bk    = (const float*)d_in[4];
    const float* wv    = (const float*)d_in[5];
    const float* bv    = (const float*)d_in[6];
    const float* wo    = (const float*)d_in[7];
    const float* bo    = (const float*)d_in[8];
    const float* gamma = (const float*)d_in[9];
    float* out = (float*)d_out;

    float *pkT, *pqT, *pwor, *pvp, *pvpr, *ppart;
    __nv_bfloat16 *pvppb;
    cudaGetSymbolAddress((void**)&pkT,    g_kT);
    cudaGetSymbolAddress((void**)&pqT,    g_qT);
    cudaGetSymbolAddress((void**)&pwor,   g_wor);
    cudaGetSymbolAddress((void**)&pvp,    g_vpool);
    cudaGetSymbolAddress((void**)&pvpr,   g_vprime);
    cudaGetSymbolAddress((void**)&ppart,  g_part);
    cudaGetSymbolAddress((void**)&pvppb,  g_vppb);

    static cudaStream_t s1 = nullptr;
    static cudaEvent_t evFork = nullptr, evQKV = nullptr, evJoin = nullptr;
    if (s1 == nullptr) {
        cudaStreamCreateWithFlags(&s1, cudaStreamNonBlocking);
        cudaEventCreateWithFlags(&evFork, cudaEventDisableTiming);
        cudaEventCreateWithFlags(&evQKV,  cudaEventDisableTiming);
        cudaEventCreateWithFlags(&evJoin, cudaEventDisableTiming);
        cudaFuncSetAttribute(attend_k, cudaFuncAttributeMaxDynamicSharedMemorySize,
                             AT2_SMEM_BYTES);
    }

    cudaEventRecord(evFork, 0);
    cudaStreamWaitEvent(s1, evFork, 0);

    // s1: tiny wo rounding
    round_wo_k<<<(CCH * CCH) / 1024, 256, 0, s1>>>(wo, pwor);

    // main: fused conv_qkv
    {
        dim3 g(NSP / 128, 3, BATCH);
        conv_qkv_mma<<<g, 256>>>(wk, bk, wq, bq, wv, bv, x, pkT, pqT, pvp);
    }
    cudaEventRecord(evQKV, 0);
    cudaStreamWaitEvent(s1, evQKV, 0);

    // s1: vprime (overlaps energy_cs on main)
    {
        dim3 g(NPOOL / 128, CCH / 128, BATCH);
        gemm_v2<<<g, 256, 0, s1>>>(pwor, pvp, pvpr, CCH, NPOOL, CCH);
    }
    cudaEventRecord(evJoin, s1);

    // main: pass-1 energy (column sums only)
    {
        dim3 g(NPOOL / 128, NSP / 128, BATCH);
        energy_cs<<<g, 256>>>(pkT, pqT, ppart);
    }

    // join, normalize -> v'' bf16, then pipelined attend
    cudaStreamWaitEvent(0, evJoin, 0);
    {
        dim3 g(BATCH * NPOOL / 256, CCH / 32);
        norm_v_k<<<g, 256>>>(ppart, pvpr, pvppb);
    }
    {
        dim3 g(NSP / 128, 1, BATCH);
        attend_k<<<g, 256, AT2_SMEM_BYTES>>>(pkT, pqT, pvppb, bo, gamma, x, out);
    }
}

// round 15
// speedup vs baseline: 1.2799x; 1.0972x over previous
#include <cuda_runtime.h>
#include <cuda_bf16.h>
#include <math.h>
#include <stdint.h>

#define BATCH 16
#define CCH   256
#define NSP   4096   // 64*64
#define CSP   32     // C/8
#define NPOOL 1024   // 32*32

// ---------------- scratch ----------------
__device__ float g_kT[BATCH * NSP * CSP];                    //  8 MB tf32 (B, n, 32)
__device__ float g_qT[BATCH * NPOOL * CSP];                  //  2 MB tf32 (B, np, 32)
__device__ float g_wor[CCH * CCH];                           // 256 KB tf32-RN wo
__device__ float g_vpool[BATCH * CCH * NPOOL];               // 16 MB (tf32-RN values)
__device__ float g_vprime[BATCH * CCH * NPOOL];              // 16 MB
__device__ float g_part[BATCH * 32 * NPOOL];                 //  2 MB
__device__ __nv_bfloat16 g_vppb[BATCH * CCH * NPOOL];        //  8 MB

// ---------------- helpers ----------------
__device__ __forceinline__ float tf32_rn(float v) {
    uint32_t u;
    asm("cvt.rna.tf32.f32 %0, %1;" : "=r"(u) : "f"(v));
    return __uint_as_float(u);
}
__device__ __forceinline__ uint32_t tf32u(float v) {
    uint32_t u;
    asm("cvt.rna.tf32.f32 %0, %1;" : "=r"(u) : "f"(v));
    return u;
}
__device__ __forceinline__ void mma_tf32(float* c, const uint32_t* a, const uint32_t* b) {
    asm volatile(
        "mma.sync.aligned.m16n8k8.row.col.f32.tf32.tf32.f32 "
        "{%0,%1,%2,%3}, {%4,%5,%6,%7}, {%8,%9}, {%0,%1,%2,%3};"
        : "+f"(c[0]), "+f"(c[1]), "+f"(c[2]), "+f"(c[3])
        : "r"(a[0]), "r"(a[1]), "r"(a[2]), "r"(a[3]), "r"(b[0]), "r"(b[1]));
}
__device__ __forceinline__ void mma_bf16(float* c, const uint32_t* a, const uint32_t* b) {
    asm volatile(
        "mma.sync.aligned.m16n8k16.row.col.f32.bf16.bf16.f32 "
        "{%0,%1,%2,%3}, {%4,%5,%6,%7}, {%8,%9}, {%0,%1,%2,%3};"
        : "+f"(c[0]), "+f"(c[1]), "+f"(c[2]), "+f"(c[3])
        : "r"(a[0]), "r"(a[1]), "r"(a[2]), "r"(a[3]), "r"(b[0]), "r"(b[1]));
}
__device__ __forceinline__ void cpa16(uint32_t dst, const void* src) {
    asm volatile("cp.async.cg.shared.global [%0], [%1], 16;" :: "r"(dst), "l"(src));
}

// ---------------- pre-round wo to tf32-RN ----------------
__global__ void round_wo_k(const float* __restrict__ wo, float* __restrict__ wor)
{
    int i = (blockIdx.x * 256 + threadIdx.x) * 4;
    float4 b = *(const float4*)&wo[i];
    b.x = tf32_rn(b.x); b.y = tf32_rn(b.y); b.z = tf32_rn(b.z); b.w = tf32_rn(b.w);
    *(float4*)&wor[i] = b;
}

// ============ fused conv_q+k+v, cp.async double-buffered ============
// Raw fp32 staged; tf32-RN applied at fragment read (identical mma operand
// values and accumulation order -> bit-identical outputs).
// A: rows x 16k, stride 20.  B: 16k x 128n natural, stride 136.
#define CV_SA 2560      // 128*20 floats per buffer (y0 uses first 64 rows)
#define CV_SB 2176      // 16*136 floats per buffer
__global__ __launch_bounds__(256)
void conv_qkv_mma(const float* __restrict__ wk, const float* __restrict__ bk,
                  const float* __restrict__ wq, const float* __restrict__ bq,
                  const float* __restrict__ wv, const float* __restrict__ bv,
                  const float* __restrict__ x,
                  float* __restrict__ kT, float* __restrict__ qT,
                  float* __restrict__ vpool)
{
    __shared__ union {
        struct { float sA[2][CV_SA]; float sB[2][CV_SB]; } ld;   // 37.9 KB
        float sOut[64 * 132];
        float sX[32 * 132];
    } sh;

    const int b    = blockIdx.z;
    const int y    = blockIdx.y;
    const int col0 = blockIdx.x * 128;
    const float* xb = x + (size_t)b * CCH * NSP;
    const int tid = threadIdx.x, lane = tid & 31, wid = tid >> 5;
    const int wr = wid >> 2, wc = wid & 3;
    const int g = lane >> 2, tk = lane & 3;

    const uint32_t smBase = (uint32_t)__cvta_generic_to_shared(&sh);
    const uint32_t sbOff  = 2 * CV_SA * 4;   // byte offset of sB region

    // ---- loaders (shared by both paths) ----
    // B: 16 x 128 natural, 2 float4 / thread
    auto issueB = [&](int k0, int s) {
#pragma unroll
        for (int u = 0; u < 2; u++) {
            int idx = tid + u * 256;
            int kr = idx >> 5, nc = (idx & 31) * 4;
            cpa16(smBase + sbOff + (s * CV_SB + kr * 136 + nc) * 4,
                  &xb[(size_t)(k0 + kr) * NSP + col0 + nc]);
        }
    };

    if (y == 0) {
        // A: 64 rows (wk 0..31 | wq 0..31) x 16k, 1 float4 / thread
        auto issueA0 = [&](int k0, int s) {
            int r = tid >> 2, kq = (tid & 3) * 4;
            const float* wrow = (r < 32) ? (wk + r * CCH) : (wq + (r - 32) * CCH);
            cpa16(smBase + (s * CV_SA + r * 20 + kq) * 4, &wrow[k0 + kq]);
        };
        auto issue = [&](int k0, int s) {
            issueA0(k0, s);
            issueB(k0, s);
            asm volatile("cp.async.commit_group;");
        };

        float cf[2][4][4] = {};
        issue(0, 0);
        for (int kt = 0; kt < 16; kt++) {
            const int cur = kt & 1;
            if (kt < 15) { issue((kt + 1) * 16, cur ^ 1);
                           asm volatile("cp.async.wait_group 1;"); }
            else           asm volatile("cp.async.wait_group 0;");
            __syncthreads();

            const float* cA = sh.ld.sA[cur];
            const float* cB = sh.ld.sB[cur];
#pragma unroll
            for (int ks = 0; ks < 2; ks++) {
                const int ko = ks * 8;
                uint32_t a[2][4], bf[4][2];
#pragma unroll
                for (int i = 0; i < 2; i++) {
                    const int ra = (wr * 32 + i * 16 + g) * 20 + ko + tk;
                    a[i][0] = tf32u(cA[ra]);
                    a[i][1] = tf32u(cA[ra + 8 * 20]);
                    a[i][2] = tf32u(cA[ra + 4]);
                    a[i][3] = tf32u(cA[ra + 8 * 20 + 4]);
                }
#pragma unroll
                for (int j = 0; j < 4; j++) {
                    const int nn = wc * 32 + j * 8 + g;
                    bf[j][0] = tf32u(cB[(ko + tk) * 136 + nn]);
                    bf[j][1] = tf32u(cB[(ko + tk + 4) * 136 + nn]);
                }
#pragma unroll
                for (int i = 0; i < 2; i++)
#pragma unroll
                    for (int j = 0; j < 4; j++) mma_tf32(cf[i][j], a[i], bf[j]);
            }
            __syncthreads();
        }

        // epilogue (unchanged numerics)
#pragma unroll
        for (int i = 0; i < 2; i++)
#pragma unroll
            for (int half = 0; half < 2; half++) {
                const int r = wr * 32 + i * 16 + half * 8 + g;
#pragma unroll
                for (int j = 0; j < 4; j++) {
                    const int c = wc * 32 + j * 8 + 2 * tk;
                    sh.sOut[r * 132 + c]     = cf[i][j][half * 2 + 0];
                    sh.sOut[r * 132 + c + 1] = cf[i][j][half * 2 + 1];
                }
            }
        __syncthreads();

        float* kTb = kT + (size_t)b * NSP * CSP;
#pragma unroll
        for (int u = 0; u < 4; u++) {
            int idx = tid + u * 256;
            int nn = idx >> 3, csq = (idx & 7) * 4;
            float4 o;
            o.x = tf32_rn(sh.sOut[(csq + 0) * 132 + nn] + bk[csq + 0]);
            o.y = tf32_rn(sh.sOut[(csq + 1) * 132 + nn] + bk[csq + 1]);
            o.z = tf32_rn(sh.sOut[(csq + 2) * 132 + nn] + bk[csq + 2]);
            o.w = tf32_rn(sh.sOut[(csq + 3) * 132 + nn] + bk[csq + 3]);
            *(float4*)&kTb[(size_t)(col0 + nn) * CSP + csq] = o;
        }

        float* qTb = qT + (size_t)b * NPOOL * CSP;
        const int hp = col0 >> 7;
        {
            int wp = tid >> 3, csq = (tid & 7) * 4;
            float4 o;
            float* oc = &o.x;
#pragma unroll
            for (int t = 0; t < 4; t++) {
                const int cs = csq + t;
                const float* r = &sh.sOut[(32 + cs) * 132];
                float v = fmaxf(fmaxf(r[2 * wp], r[2 * wp + 1]),
                                fmaxf(r[64 + 2 * wp], r[64 + 2 * wp + 1]));
                oc[t] = tf32_rn(v + bq[cs]);
            }
            *(float4*)&qTb[(size_t)(hp * 32 + wp) * CSP + csq] = o;
        }
    } else {
        const int r0 = (y - 1) * 128;
        // A: 128 wv rows x 16k, 2 float4 / thread
        auto issueA1 = [&](int k0, int s) {
            int r = tid >> 1, kq = (tid & 1) * 8;
#pragma unroll
            for (int q = 0; q < 2; q++)
                cpa16(smBase + (s * CV_SA + r * 20 + kq + q * 4) * 4,
                      &wv[(size_t)(r0 + r) * CCH + k0 + kq + q * 4]);
        };
        auto issue = [&](int k0, int s) {
            issueA1(k0, s);
            issueB(k0, s);
            asm volatile("cp.async.commit_group;");
        };

        float cf[4][4][4] = {};
        issue(0, 0);
        for (int kt = 0; kt < 16; kt++) {
            const int cur = kt & 1;
            if (kt < 15) { issue((kt + 1) * 16, cur ^ 1);
                           asm volatile("cp.async.wait_group 1;"); }
            else           asm volatile("cp.async.wait_group 0;");
            __syncthreads();

            const float* cA = sh.ld.sA[cur];
            const float* cB = sh.ld.sB[cur];
#pragma unroll
            for (int ks = 0; ks < 2; ks++) {
                const int ko = ks * 8;
                uint32_t a[4][4], bf[4][2];
#pragma unroll
                for (int i = 0; i < 4; i++) {
                    const int ra = (wr * 64 + i * 16 + g) * 20 + ko + tk;
                    a[i][0] = tf32u(cA[ra]);
                    a[i][1] = tf32u(cA[ra + 8 * 20]);
                    a[i][2] = tf32u(cA[ra + 4]);
                    a[i][3] = tf32u(cA[ra + 8 * 20 + 4]);
                }
#pragma unroll
                for (int j = 0; j < 4; j++) {
                    const int nn = wc * 32 + j * 8 + g;
                    bf[j][0] = tf32u(cB[(ko + tk) * 136 + nn]);
                    bf[j][1] = tf32u(cB[(ko + tk + 4) * 136 + nn]);
                }
#pragma unroll
                for (int i = 0; i < 4; i++)
#pragma unroll
                    for (int j = 0; j < 4; j++) mma_tf32(cf[i][j], a[i], bf[j]);
            }
            __syncthreads();
        }

        // maxpool epilogue (unchanged numerics)
        float* Cp = vpool + (size_t)b * CCH * NPOOL;
        const int pcb = col0 >> 2;
#pragma unroll 1
        for (int s = 0; s < 4; s++) {
            if (wr == (s >> 1)) {
#pragma unroll
                for (int ii = 0; ii < 2; ii++) {
                    const int i = (s & 1) * 2 + ii;
#pragma unroll
                    for (int half = 0; half < 2; half++) {
                        const int lr = ii * 16 + half * 8 + g;
#pragma unroll
                        for (int j = 0; j < 4; j++) {
                            const int col = wc * 32 + j * 8 + 2 * tk;
                            sh.sX[lr * 132 + col]     = cf[i][j][half * 2 + 0];
                            sh.sX[lr * 132 + col + 1] = cf[i][j][half * 2 + 1];
                        }
                    }
                }
            }
            __syncthreads();
#pragma unroll
            for (int u = 0; u < 4; u++) {
                int po = tid + u * 256;
                int rr = po >> 5, pc = po & 31;
                float v = fmaxf(fmaxf(sh.sX[rr * 132 + 2 * pc], sh.sX[rr * 132 + 2 * pc + 1]),
                                fmaxf(sh.sX[rr * 132 + 64 + 2 * pc], sh.sX[rr * 132 + 64 + 2 * pc + 1]));
                const int r = r0 + s * 32 + rr;
                Cp[(size_t)r * NPOOL + pcb + pc] = tf32_rn(v + bv[r]);
            }
            __syncthreads();
        }
    }
}

// ============ pass-1 energy: column sums only (unchanged) ====
__global__ __launch_bounds__(256)
void energy_cs(const float* __restrict__ kTg, const float* __restrict__ qTg,
               float* __restrict__ part)
{
    __shared__ float sA[128 * 36];
    __shared__ float sB[128 * 36];
    __shared__ float sX[16 * 132];

    const int b  = blockIdx.z;
    const int m0 = blockIdx.y * 128;
    const int n0 = blockIdx.x * 128;
    const float* Ab = kTg + ((size_t)b * NSP + m0) * CSP;
    const float* Bb = qTg + ((size_t)b * NPOOL + n0) * CSP;

    const int tid = threadIdx.x, lane = tid & 31, wid = tid >> 5;
    const int wr = wid >> 2, wc = wid & 3;
    const int g = lane >> 2, tk = lane & 3;

#pragma unroll
    for (int u = 0; u < 4; u++) {
        int idx = tid + u * 256;
        int r = idx >> 3, kq = (idx & 7) * 4;
        *(float4*)&sA[r * 36 + kq] = *(const float4*)&Ab[(size_t)r * CSP + kq];
        *(float4*)&sB[r * 36 + kq] = *(const float4*)&Bb[(size_t)r * CSP + kq];
    }
    __syncthreads();

    float cf[4][4][4] = {};
#pragma unroll
    for (int ks = 0; ks < 4; ks++) {
        const int ko = ks * 8;
        uint32_t a[4][4], bf[4][2];
#pragma unroll
        for (int i = 0; i < 4; i++) {
            const int ra = (wr * 64 + i * 16 + g) * 36 + ko + tk;
            a[i][0] = __float_as_uint(sA[ra]);
            a[i][1] = __float_as_uint(sA[ra + 8 * 36]);
            a[i][2] = __float_as_uint(sA[ra + 4]);
            a[i][3] = __float_as_uint(sA[ra + 8 * 36 + 4]);
        }
#pragma unroll
        for (int j = 0; j < 4; j++) {
            const int rb = (wc * 32 + j * 8 + g) * 36 + ko + tk;
            bf[j][0] = __float_as_uint(sB[rb]);
            bf[j][1] = __float_as_uint(sB[rb + 4]);
        }
#pragma unroll
        for (int i = 0; i < 4; i++)
#pragma unroll
            for (int j = 0; j < 4; j++) mma_tf32(cf[i][j], a[i], bf[j]);
    }

    float colsum[4][2] = {};
#pragma unroll
    for (int i = 0; i < 4; i++) {
#pragma unroll
        for (int half = 0; half < 2; half++) {
#pragma unroll
            for (int j = 0; j < 4; j++) {
                float e0 = __expf(cf[i][j][half * 2 + 0]);
                float e1 = __expf(cf[i][j][half * 2 + 1]);
                colsum[j][0] += e0;
                colsum[j][1] += e1;
            }
        }
    }
#pragma unroll
    for (int j = 0; j < 4; j++) {
        const int col = wc * 32 + j * 8 + 2 * tk;
        sX[(wr * 8 + g) * 132 + col]     = colsum[j][0];
        sX[(wr * 8 + g) * 132 + col + 1] = colsum[j][1];
    }
    __syncthreads();
    if (tid < 128) {
        float t = 0.f;
#pragma unroll
        for (int k = 0; k < 16; k++) t += sX[k * 132 + tid];
        part[((size_t)b * 32 + blockIdx.y) * NPOOL + n0 + tid] = t;
    }
}

// ================= vprime GEMM (unchanged) ============
#define GV_SA 2560
#define GV_SB 2176
__global__ __launch_bounds__(256)
void gemm_v2(const float* __restrict__ A,
             const float* __restrict__ B,
             float* __restrict__ C,
             int M, int N, int K)
{
    __shared__ float sm[2 * GV_SA + 2 * GV_SB];

    const int b  = blockIdx.z;
    const int r0 = blockIdx.y * 128;
    const int n0 = blockIdx.x * 128;
    const float* Ab = A;
    const float* Bb = B + (size_t)b * K * N;

    const int tid = threadIdx.x, lane = tid & 31, wid = tid >> 5;
    const int wr = wid >> 2, wc = wid & 3;
    const int g = lane >> 2, tk = lane & 3;

    const int a_r = tid >> 1, a_q = (tid & 1) * 2;
    const uint32_t smBase = (uint32_t)__cvta_generic_to_shared(sm);

    auto issue = [&](int k0, int s) {
#pragma unroll
        for (int u = 0; u < 2; u++) {
            int q = a_q + u;
            cpa16(smBase + (s * GV_SA + a_r * 20 + q * 4) * 4,
                  &Ab[(size_t)(r0 + a_r) * K + k0 + q * 4]);
        }
#pragma unroll
        for (int u = 0; u < 2; u++) {
            int idx = tid + u * 256;
            int kr = idx >> 5, nc = (idx & 31) * 4;
            cpa16(smBase + (2 * GV_SA + s * GV_SB + kr * 136 + nc) * 4,
                  &Bb[(size_t)(k0 + kr) * N + n0 + nc]);
        }
        asm volatile("cp.async.commit_group;");
    };

    float cf[4][4][4] = {};
    const int NIT = K / 16;

    issue(0, 0);
    for (int kt = 0; kt < NIT; kt++) {
        const int cur = kt & 1;
        if (kt < NIT - 1) {
            issue((kt + 1) * 16, cur ^ 1);
            asm volatile("cp.async.wait_group 1;");
        } else {
            asm volatile("cp.async.wait_group 0;");
        }
        __syncthreads();

        const float* cA = sm + cur * GV_SA;
        const float* cB = sm + 2 * GV_SA + cur * GV_SB;
#pragma unroll
        for (int ks = 0; ks < 2; ks++) {
            const int ko = ks * 8;
            uint32_t a[4][4], bf[4][2];
#pragma unroll
            for (int i = 0; i < 4; i++) {
                const int ra = (wr * 64 + i * 16 + g) * 20 + ko + tk;
                a[i][0] = __float_as_uint(cA[ra]);
                a[i][1] = __float_as_uint(cA[ra + 8 * 20]);
                a[i][2] = __float_as_uint(cA[ra + 4]);
                a[i][3] = __float_as_uint(cA[ra + 8 * 20 + 4]);
            }
#pragma unroll
            for (int j = 0; j < 4; j++) {
                const int nn = wc * 32 + j * 8 + g;
                bf[j][0] = __float_as_uint(cB[(ko + tk) * 136 + nn]);
                bf[j][1] = __float_as_uint(cB[(ko + tk + 4) * 136 + nn]);
            }
#pragma unroll
            for (int i = 0; i < 4; i++)
#pragma unroll
                for (int j = 0; j < 4; j++) mma_tf32(cf[i][j], a[i], bf[j]);
        }
        __syncthreads();
    }

    float* Cb = C + (size_t)b * M * N;
#pragma unroll
    for (int i = 0; i < 4; i++)
#pragma unroll
        for (int half = 0; half < 2; half++) {
            const int r = r0 + wr * 64 + i * 16 + g + half * 8;
            const size_t ro = (size_t)r * N;
#pragma unroll
            for (int j = 0; j < 4; j++) {
                const int c = n0 + wc * 32 + j * 8 + 2 * tk;
                float2 o;
                o.x = cf[i][j][half * 2 + 0];
                o.y = cf[i][j][half * 2 + 1];
                *(float2*)&Cb[ro + c] = o;
            }
        }
}

// ---------------- fused denominator + v'' (unchanged) ------------
__global__ void norm_v_k(const float* __restrict__ part,
                         const float* __restrict__ vpr,
                         __nv_bfloat16* __restrict__ vppb)
{
    int idx = blockIdx.x * 256 + threadIdx.x;
    int b  = idx >> 10;
    int np = idx & 1023;
    const float* p = part + (size_t)b * 32 * NPOOL + np;
    float s = 0.f;
#pragma unroll
    for (int i = 0; i < 32; i++) s += p[(size_t)i * NPOOL];
    const float inv = 1.f / s;

    const int c0 = blockIdx.y * 32;
    const float* v = vpr + (size_t)b * CCH * NPOOL + np;
    __nv_bfloat16* o = vppb + (size_t)b * CCH * NPOOL + np;
#pragma unroll 8
    for (int c = c0; c < c0 + 32; c++)
        o[(size_t)c * NPOOL] = __float2bfloat16_rn(v[(size_t)c * NPOOL] * inv);
}

// ============ pass-2: pipelined fused attend (unchanged from R14) =======
#define AT2_KT 0
#define AT2_QT 4608
#define AT2_PS 9216
#define AT2_VA 13824
#define AT2_SMEM_BYTES ((13824 + 2 * 9216) * 4)   // 129,024

__global__ __launch_bounds__(256)
void attend_k(const float* __restrict__ kTg, const float* __restrict__ qTg,
              const __nv_bfloat16* __restrict__ vpp,
              const float* __restrict__ bo,
              const float* __restrict__ gamma,
              const float* __restrict__ xres,
              float* __restrict__ out)
{
    extern __shared__ float smem[];
    float* sKT = smem + AT2_KT;
    float* sQT = smem + AT2_QT;
    uint32_t* pstage = (uint32_t*)(smem + AT2_PS);
    uint32_t* vA = (uint32_t*)(smem + AT2_VA);

    const int tid = threadIdx.x, lane = tid & 31, wid = tid >> 5;
    const int b  = blockIdx.z;
    const int m0 = blockIdx.x * 128;
    const int g = lane >> 2, tk = lane & 3;
    const int wr2 = wid >> 1, wc2 = wid & 1;
    const int wr = wid >> 1, wc = wid & 1;

    const float* Akt = kTg + ((size_t)b * NSP + m0) * CSP;
    const __nv_bfloat16* Av = vpp + (size_t)b * CCH * NPOOL;
    const uint32_t smBase = (uint32_t)__cvta_generic_to_shared(smem);

#pragma unroll
    for (int u = 0; u < 2; u++) {
        int idx = tid + u * 256;
        int r = idx >> 2, kq = (idx & 3) * 8;
        *(float4*)&sKT[r * 36 + kq]     = *(const float4*)&Akt[(size_t)r * CSP + kq];
        *(float4*)&sKT[r * 36 + kq + 4] = *(const float4*)&Akt[(size_t)r * CSP + kq + 4];
    }

    auto issue = [&](int c, int s) {
        const int np0 = c * 64;
        const float* Bq = qTg + ((size_t)b * NPOOL + np0) * CSP;
#pragma unroll
        for (int u = 0; u < 2; u++) {
            int idx = tid + u * 256;
            int r = idx >> 3, kq = (idx & 7) * 4;
            cpa16(smBase + (AT2_QT + s * 64 * 36 + r * 36 + kq) * 4,
                  &Bq[(size_t)r * CSP + kq]);
        }
#pragma unroll
        for (int u = 0; u < 8; u++) {
            int idx = tid + u * 256;
            int row = idx >> 3, q = idx & 7;
            cpa16(smBase + (AT2_VA + s * 256 * 36 + row * 36 + q * 4) * 4,
                  &Av[(size_t)row * NPOOL + np0 + q * 8]);
        }
        asm volatile("cp.async.commit_group;");
    };

    float cfO[4][8][4] = {};

    issue(0, 0);
    issue(1, 1);
    for (int c = 0; c < 16; c++) {
        const int cur = c & 1;
        if (c < 15) asm volatile("cp.async.wait_group 1;");
        else        asm volatile("cp.async.wait_group 0;");
        __syncthreads();

        const float* cQ = sQT + cur * 64 * 36;
        const uint32_t* cV = vA + cur * 256 * 36;

        float cf2[2][4][4] = {};
#pragma unroll
        for (int ks = 0; ks < 4; ks++) {
            const int ko = ks * 8;
            uint32_t a[2][4], bf[4][2];
#pragma unroll
            for (int i = 0; i < 2; i++) {
                const int ra = (wr2 * 32 + i * 16 + g) * 36 + ko + tk;
                a[i][0] = __float_as_uint(sKT[ra]);
                a[i][1] = __float_as_uint(sKT[ra + 8 * 36]);
                a[i][2] = __float_as_uint(sKT[ra + 4]);
                a[i][3] = __float_as_uint(sKT[ra + 8 * 36 + 4]);
            }
#pragma unroll
            for (int j = 0; j < 4; j++) {
                const int rb = (wc2 * 32 + j * 8 + g) * 36 + ko + tk;
                bf[j][0] = __float_as_uint(cQ[rb]);
                bf[j][1] = __float_as_uint(cQ[rb + 4]);
            }
#pragma unroll
            for (int i = 0; i < 2; i++)
#pragma unroll
                for (int j = 0; j < 4; j++) mma_tf32(cf2[i][j], a[i], bf[j]);
        }

#pragma unroll
        for (int i = 0; i < 2; i++) {
#pragma unroll
            for (int half = 0; half < 2; half++) {
                const int lr = wr2 * 32 + i * 16 + half * 8 + g;
#pragma unroll
                for (int j = 0; j < 4; j++) {
                    const int lc2 = wc2 * 16 + j * 4 + tk;
                    float e0 = __expf(cf2[i][j][half * 2 + 0]);
                    float e1 = __expf(cf2[i][j][half * 2 + 1]);
                    __nv_bfloat162 p2 = __floats2bfloat162_rn(e0, e1);
                    pstage[lr * 36 + lc2] = *(uint32_t*)&p2;
                }
            }
        }
        __syncthreads();

#pragma unroll
        for (int ks2 = 0; ks2 < 4; ks2++) {
            uint32_t a[4][4], bf[8][2];
#pragma unroll
            for (int i = 0; i < 4; i++) {
                const int ra = (wr * 64 + i * 16 + g) * 36 + ks2 * 8 + tk;
                a[i][0] = cV[ra];
                a[i][1] = cV[ra + 8 * 36];
                a[i][2] = cV[ra + 4];
                a[i][3] = cV[ra + 8 * 36 + 4];
            }
#pragma unroll
            for (int j = 0; j < 8; j++) {
                const int rb = (wc * 64 + j * 8 + g) * 36 + ks2 * 8 + tk;
                bf[j][0] = pstage[rb];
                bf[j][1] = pstage[rb + 4];
            }
#pragma unroll
            for (int i = 0; i < 4; i++)
#pragma unroll
                for (int j = 0; j < 8; j++) mma_bf16(cfO[i][j], a[i], bf[j]);
        }
        __syncthreads();

        if (c + 2 < 16) issue(c + 2, cur);
    }

    const float gm = gamma[0];
#pragma unroll
    for (int i = 0; i < 4; i++) {
#pragma unroll
        for (int half = 0; half < 2; half++) {
            const int c = wr * 64 + i * 16 + g + half * 8;
            const float bc = bo[c];
            const size_t ro = ((size_t)b * CCH + c) * NSP;
#pragma unroll
            for (int j = 0; j < 8; j++) {
                const int m = m0 + wc * 64 + j * 8 + 2 * tk;
                float2 xr = *(const float2*)&xres[ro + m];
                float2 o;
                o.x = gm * (cfO[i][j][half * 2 + 0] + bc) + xr.x;
                o.y = gm * (cfO[i][j][half * 2 + 1] + bc) + xr.y;
                *(float2*)&out[ro + m] = o;
            }
        }
    }
}

// ---------------- launch ----------------
extern "C" void kernel_launch(void* const* d_in, const int* in_sizes, int n_in,
                              void* d_out, int out_size)
{
    const float* x     = (const float*)d_in[0];
    const float* wq    = (const float*)d_in[1];
    const float* bq    = (const float*)d_in[2];
    const float* wk    = (const float*)d_in[3];
    const float* bk    = (const float*)d_in[4];
    const float* wv    = (const float*)d_in[5];
    const float* bv    = (const float*)d_in[6];
    const float* wo    = (const float*)d_in[7];
    const float* bo    = (const float*)d_in[8];
    const float* gamma = (const float*)d_in[9];
    float* out = (float*)d_out;

    float *pkT, *pqT, *pwor, *pvp, *pvpr, *ppart;
    __nv_bfloat16 *pvppb;
    cudaGetSymbolAddress((void**)&pkT,    g_kT);
    cudaGetSymbolAddress((void**)&pqT,    g_qT);
    cudaGetSymbolAddress((void**)&pwor,   g_wor);
    cudaGetSymbolAddress((void**)&pvp,    g_vpool);
    cudaGetSymbolAddress((void**)&pvpr,   g_vprime);
    cudaGetSymbolAddress((void**)&ppart,  g_part);
    cudaGetSymbolAddress((void**)&pvppb,  g_vppb);

    static cudaStream_t s1 = nullptr;
    static cudaEvent_t evFork = nullptr, evQKV = nullptr, evJoin = nullptr;
    if (s1 == nullptr) {
        cudaStreamCreateWithFlags(&s1, cudaStreamNonBlocking);
        cudaEventCreateWithFlags(&evFork, cudaEventDisableTiming);
        cudaEventCreateWithFlags(&evQKV,  cudaEventDisableTiming);
        cudaEventCreateWithFlags(&evJoin, cudaEventDisableTiming);
        cudaFuncSetAttribute(attend_k, cudaFuncAttributeMaxDynamicSharedMemorySize,
                             AT2_SMEM_BYTES);
    }

    cudaEventRecord(evFork, 0);
    cudaStreamWaitEvent(s1, evFork, 0);

    // s1: tiny wo rounding
    round_wo_k<<<(CCH * CCH) / 1024, 256, 0, s1>>>(wo, pwor);

    // main: fused conv_qkv (cp.async pipelined)
    {
        dim3 g(NSP / 128, 3, BATCH);
        conv_qkv_mma<<<g, 256>>>(wk, bk, wq, bq, wv, bv, x, pkT, pqT, pvp);
    }
    cudaEventRecord(evQKV, 0);
    cudaStreamWaitEvent(s1, evQKV, 0);

    // s1: vprime (overlaps energy_cs on main)
    {
        dim3 g(NPOOL / 128, CCH / 128, BATCH);
        gemm_v2<<<g, 256, 0, s1>>>(pwor, pvp, pvpr, CCH, NPOOL, CCH);
    }
    cudaEventRecord(evJoin, s1);

    // main: pass-1 energy (column sums only)
    {
        dim3 g(NPOOL / 128, NSP / 128, BATCH);
        energy_cs<<<g, 256>>>(pkT, pqT, ppart);
    }

    // join, normalize -> v'' bf16, then pipelined attend
    cudaStreamWaitEvent(0, evJoin, 0);
    {
        dim3 g(BATCH * NPOOL / 256, CCH / 32);
        norm_v_k<<<g, 256>>>(ppart, pvpr, pvppb);
    }
    {
        dim3 g(NSP / 128, 1, BATCH);
        attend_k<<<g, 256, AT2_SMEM_BYTES>>>(pkT, pqT, pvppb, bo, gamma, x, out);
    }
}

// round 16
// speedup vs baseline: 1.3197x; 1.0311x over previous
#include <cuda_runtime.h>
#include <cuda_bf16.h>
#include <math.h>
#include <stdint.h>

#define BATCH 16
#define CCH   256
#define NSP   4096   // 64*64
#define CSP   32     // C/8
#define NPOOL 1024   // 32*32

// ---------------- scratch ----------------
__device__ float g_kT[BATCH * NSP * CSP];                    //  8 MB tf32 (B, n, 32)
__device__ float g_qT[BATCH * NPOOL * CSP];                  //  2 MB tf32 (B, np, 32)
__device__ float g_wor[CCH * CCH];                           // 256 KB tf32-RN wo
__device__ float g_vpool[BATCH * CCH * NPOOL];               // 16 MB (tf32-RN values)
__device__ float g_vprime[BATCH * CCH * NPOOL];              // 16 MB
__device__ float g_part[BATCH * 32 * NPOOL];                 //  2 MB
__device__ __nv_bfloat16 g_vppb[BATCH * CCH * NPOOL];        //  8 MB

// ---------------- helpers ----------------
__device__ __forceinline__ float tf32_rn(float v) {
    uint32_t u;
    asm("cvt.rna.tf32.f32 %0, %1;" : "=r"(u) : "f"(v));
    return __uint_as_float(u);
}
__device__ __forceinline__ uint32_t tf32u(float v) {
    uint32_t u;
    asm("cvt.rna.tf32.f32 %0, %1;" : "=r"(u) : "f"(v));
    return u;
}
__device__ __forceinline__ void mma_tf32(float* c, const uint32_t* a, const uint32_t* b) {
    asm volatile(
        "mma.sync.aligned.m16n8k8.row.col.f32.tf32.tf32.f32 "
        "{%0,%1,%2,%3}, {%4,%5,%6,%7}, {%8,%9}, {%0,%1,%2,%3};"
        : "+f"(c[0]), "+f"(c[1]), "+f"(c[2]), "+f"(c[3])
        : "r"(a[0]), "r"(a[1]), "r"(a[2]), "r"(a[3]), "r"(b[0]), "r"(b[1]));
}
__device__ __forceinline__ void mma_bf16(float* c, const uint32_t* a, const uint32_t* b) {
    asm volatile(
        "mma.sync.aligned.m16n8k16.row.col.f32.bf16.bf16.f32 "
        "{%0,%1,%2,%3}, {%4,%5,%6,%7}, {%8,%9}, {%0,%1,%2,%3};"
        : "+f"(c[0]), "+f"(c[1]), "+f"(c[2]), "+f"(c[3])
        : "r"(a[0]), "r"(a[1]), "r"(a[2]), "r"(a[3]), "r"(b[0]), "r"(b[1]));
}
__device__ __forceinline__ void cpa16(uint32_t dst, const void* src) {
    asm volatile("cp.async.cg.shared.global [%0], [%1], 16;" :: "r"(dst), "l"(src));
}

// ---------------- pre-round wo to tf32-RN ----------------
__global__ void round_wo_k(const float* __restrict__ wo, float* __restrict__ wor)
{
    int i = (blockIdx.x * 256 + threadIdx.x) * 4;
    float4 b = *(const float4*)&wo[i];
    b.x = tf32_rn(b.x); b.y = tf32_rn(b.y); b.z = tf32_rn(b.z); b.w = tf32_rn(b.w);
    *(float4*)&wor[i] = b;
}

#define CV_SA 2560      // 128*20 floats per buffer
#define CV_SB 2176      // 16*136 floats per buffer

// ============ conv_qk: kT + pooled qT (cp.async; tf32-RN at fragment read) ====
__global__ __launch_bounds__(256)
void conv_qk_k(const float* __restrict__ wk, const float* __restrict__ bk,
               const float* __restrict__ wq, const float* __restrict__ bq,
               const float* __restrict__ x,
               float* __restrict__ kT, float* __restrict__ qT)
{
    __shared__ union {
        struct { float sA[2][CV_SA]; float sB[2][CV_SB]; } ld;
        float sOut[64 * 132];
    } sh;

    const int b    = blockIdx.z;
    const int col0 = blockIdx.x * 128;
    const float* xb = x + (size_t)b * CCH * NSP;
    const int tid = threadIdx.x, lane = tid & 31, wid = tid >> 5;
    const int wr = wid >> 2, wc = wid & 3;
    const int g = lane >> 2, tk = lane & 3;

    const uint32_t smBase = (uint32_t)__cvta_generic_to_shared(&sh);
    const uint32_t sbOff  = 2 * CV_SA * 4;

    auto issue = [&](int k0, int s) {
        {
            int r = tid >> 2, kq = (tid & 3) * 4;
            const float* wrow = (r < 32) ? (wk + r * CCH) : (wq + (r - 32) * CCH);
            cpa16(smBase + (s * CV_SA + r * 20 + kq) * 4, &wrow[k0 + kq]);
        }
#pragma unroll
        for (int u = 0; u < 2; u++) {
            int idx = tid + u * 256;
            int kr = idx >> 5, nc = (idx & 31) * 4;
            cpa16(smBase + sbOff + (s * CV_SB + kr * 136 + nc) * 4,
                  &xb[(size_t)(k0 + kr) * NSP + col0 + nc]);
        }
        asm volatile("cp.async.commit_group;");
    };

    float cf[2][4][4] = {};
    issue(0, 0);
    for (int kt = 0; kt < 16; kt++) {
        const int cur = kt & 1;
        if (kt < 15) { issue((kt + 1) * 16, cur ^ 1);
                       asm volatile("cp.async.wait_group 1;"); }
        else           asm volatile("cp.async.wait_group 0;");
        __syncthreads();

        const float* cA = sh.ld.sA[cur];
        const float* cB = sh.ld.sB[cur];
#pragma unroll
        for (int ks = 0; ks < 2; ks++) {
            const int ko = ks * 8;
            uint32_t a[2][4], bf[4][2];
#pragma unroll
            for (int i = 0; i < 2; i++) {
                const int ra = (wr * 32 + i * 16 + g) * 20 + ko + tk;
                a[i][0] = tf32u(cA[ra]);
                a[i][1] = tf32u(cA[ra + 8 * 20]);
                a[i][2] = tf32u(cA[ra + 4]);
                a[i][3] = tf32u(cA[ra + 8 * 20 + 4]);
            }
#pragma unroll
            for (int j = 0; j < 4; j++) {
                const int nn = wc * 32 + j * 8 + g;
                bf[j][0] = tf32u(cB[(ko + tk) * 136 + nn]);
                bf[j][1] = tf32u(cB[(ko + tk + 4) * 136 + nn]);
            }
#pragma unroll
            for (int i = 0; i < 2; i++)
#pragma unroll
                for (int j = 0; j < 4; j++) mma_tf32(cf[i][j], a[i], bf[j]);
        }
        __syncthreads();
    }

#pragma unroll
    for (int i = 0; i < 2; i++)
#pragma unroll
        for (int half = 0; half < 2; half++) {
            const int r = wr * 32 + i * 16 + half * 8 + g;
#pragma unroll
            for (int j = 0; j < 4; j++) {
                const int c = wc * 32 + j * 8 + 2 * tk;
                sh.sOut[r * 132 + c]     = cf[i][j][half * 2 + 0];
                sh.sOut[r * 132 + c + 1] = cf[i][j][half * 2 + 1];
            }
        }
    __syncthreads();

    float* kTb = kT + (size_t)b * NSP * CSP;
#pragma unroll
    for (int u = 0; u < 4; u++) {
        int idx = tid + u * 256;
        int nn = idx >> 3, csq = (idx & 7) * 4;
        float4 o;
        o.x = tf32_rn(sh.sOut[(csq + 0) * 132 + nn] + bk[csq + 0]);
        o.y = tf32_rn(sh.sOut[(csq + 1) * 132 + nn] + bk[csq + 1]);
        o.z = tf32_rn(sh.sOut[(csq + 2) * 132 + nn] + bk[csq + 2]);
        o.w = tf32_rn(sh.sOut[(csq + 3) * 132 + nn] + bk[csq + 3]);
        *(float4*)&kTb[(size_t)(col0 + nn) * CSP + csq] = o;
    }

    float* qTb = qT + (size_t)b * NPOOL * CSP;
    const int hp = col0 >> 7;
    {
        int wp = tid >> 3, csq = (tid & 7) * 4;
        float4 o;
        float* oc = &o.x;
#pragma unroll
        for (int t = 0; t < 4; t++) {
            const int cs = csq + t;
            const float* r = &sh.sOut[(32 + cs) * 132];
            float v = fmaxf(fmaxf(r[2 * wp], r[2 * wp + 1]),
                            fmaxf(r[64 + 2 * wp], r[64 + 2 * wp + 1]));
            oc[t] = tf32_rn(v + bq[cs]);
        }
        *(float4*)&qTb[(size_t)(hp * 32 + wp) * CSP + csq] = o;
    }
}

// ============ conv_v: vpool slices (independent of conv_qk) ====
__global__ __launch_bounds__(256)
void conv_v_k(const float* __restrict__ wv, const float* __restrict__ bv,
              const float* __restrict__ x, float* __restrict__ vpool)
{
    __shared__ union {
        struct { float sA[2][CV_SA]; float sB[2][CV_SB]; } ld;
        float sX[32 * 132];
    } sh;

    const int b    = blockIdx.z;
    const int r0   = blockIdx.y * 128;
    const int col0 = blockIdx.x * 128;
    const float* xb = x + (size_t)b * CCH * NSP;
    const int tid = threadIdx.x, lane = tid & 31, wid = tid >> 5;
    const int wr = wid >> 2, wc = wid & 3;
    const int g = lane >> 2, tk = lane & 3;

    const uint32_t smBase = (uint32_t)__cvta_generic_to_shared(&sh);
    const uint32_t sbOff  = 2 * CV_SA * 4;

    auto issue = [&](int k0, int s) {
        {
            int r = tid >> 1, kq = (tid & 1) * 8;
#pragma unroll
            for (int q = 0; q < 2; q++)
                cpa16(smBase + (s * CV_SA + r * 20 + kq + q * 4) * 4,
                      &wv[(size_t)(r0 + r) * CCH + k0 + kq + q * 4]);
        }
#pragma unroll
        for (int u = 0; u < 2; u++) {
            int idx = tid + u * 256;
            int kr = idx >> 5, nc = (idx & 31) * 4;
            cpa16(smBase + sbOff + (s * CV_SB + kr * 136 + nc) * 4,
                  &xb[(size_t)(k0 + kr) * NSP + col0 + nc]);
        }
        asm volatile("cp.async.commit_group;");
    };

    float cf[4][4][4] = {};
    issue(0, 0);
    for (int kt = 0; kt < 16; kt++) {
        const int cur = kt & 1;
        if (kt < 15) { issue((kt + 1) * 16, cur ^ 1);
                       asm volatile("cp.async.wait_group 1;"); }
        else           asm volatile("cp.async.wait_group 0;");
        __syncthreads();

        const float* cA = sh.ld.sA[cur];
        const float* cB = sh.ld.sB[cur];
#pragma unroll
        for (int ks = 0; ks < 2; ks++) {
            const int ko = ks * 8;
            uint32_t a[4][4], bf[4][2];
#pragma unroll
            for (int i = 0; i < 4; i++) {
                const int ra = (wr * 64 + i * 16 + g) * 20 + ko + tk;
                a[i][0] = tf32u(cA[ra]);
                a[i][1] = tf32u(cA[ra + 8 * 20]);
                a[i][2] = tf32u(cA[ra + 4]);
                a[i][3] = tf32u(cA[ra + 8 * 20 + 4]);
            }
#pragma unroll
            for (int j = 0; j < 4; j++) {
                const int nn = wc * 32 + j * 8 + g;
                bf[j][0] = tf32u(cB[(ko + tk) * 136 + nn]);
                bf[j][1] = tf32u(cB[(ko + tk + 4) * 136 + nn]);
            }
#pragma unroll
            for (int i = 0; i < 4; i++)
#pragma unroll
                for (int j = 0; j < 4; j++) mma_tf32(cf[i][j], a[i], bf[j]);
        }
        __syncthreads();
    }

    float* Cp = vpool + (size_t)b * CCH * NPOOL;
    const int pcb = col0 >> 2;
#pragma unroll 1
    for (int s = 0; s < 4; s++) {
        if (wr == (s >> 1)) {
#pragma unroll
            for (int ii = 0; ii < 2; ii++) {
                const int i = (s & 1) * 2 + ii;
#pragma unroll
                for (int half = 0; half < 2; half++) {
                    const int lr = ii * 16 + half * 8 + g;
#pragma unroll
                    for (int j = 0; j < 4; j++) {
                        const int col = wc * 32 + j * 8 + 2 * tk;
                        sh.sX[lr * 132 + col]     = cf[i][j][half * 2 + 0];
                        sh.sX[lr * 132 + col + 1] = cf[i][j][half * 2 + 1];
                    }
                }
            }
        }
        __syncthreads();
#pragma unroll
        for (int u = 0; u < 4; u++) {
            int po = tid + u * 256;
            int rr = po >> 5, pc = po & 31;
            float v = fmaxf(fmaxf(sh.sX[rr * 132 + 2 * pc], sh.sX[rr * 132 + 2 * pc + 1]),
                            fmaxf(sh.sX[rr * 132 + 64 + 2 * pc], sh.sX[rr * 132 + 64 + 2 * pc + 1]));
            const int r = r0 + s * 32 + rr;
            Cp[(size_t)r * NPOOL + pcb + pc] = tf32_rn(v + bv[r]);
        }
        __syncthreads();
    }
}

// ============ pass-1 energy: column sums only (unchanged) ====
__global__ __launch_bounds__(256)
void energy_cs(const float* __restrict__ kTg, const float* __restrict__ qTg,
               float* __restrict__ part)
{
    __shared__ float sA[128 * 36];
    __shared__ float sB[128 * 36];
    __shared__ float sX[16 * 132];

    const int b  = blockIdx.z;
    const int m0 = blockIdx.y * 128;
    const int n0 = blockIdx.x * 128;
    const float* Ab = kTg + ((size_t)b * NSP + m0) * CSP;
    const float* Bb = qTg + ((size_t)b * NPOOL + n0) * CSP;

    const int tid = threadIdx.x, lane = tid & 31, wid = tid >> 5;
    const int wr = wid >> 2, wc = wid & 3;
    const int g = lane >> 2, tk = lane & 3;

#pragma unroll
    for (int u = 0; u < 4; u++) {
        int idx = tid + u * 256;
        int r = idx >> 3, kq = (idx & 7) * 4;
        *(float4*)&sA[r * 36 + kq] = *(const float4*)&Ab[(size_t)r * CSP + kq];
        *(float4*)&sB[r * 36 + kq] = *(const float4*)&Bb[(size_t)r * CSP + kq];
    }
    __syncthreads();

    float cf[4][4][4] = {};
#pragma unroll
    for (int ks = 0; ks < 4; ks++) {
        const int ko = ks * 8;
        uint32_t a[4][4], bf[4][2];
#pragma unroll
        for (int i = 0; i < 4; i++) {
            const int ra = (wr * 64 + i * 16 + g) * 36 + ko + tk;
            a[i][0] = __float_as_uint(sA[ra]);
            a[i][1] = __float_as_uint(sA[ra + 8 * 36]);
            a[i][2] = __float_as_uint(sA[ra + 4]);
            a[i][3] = __float_as_uint(sA[ra + 8 * 36 + 4]);
        }
#pragma unroll
        for (int j = 0; j < 4; j++) {
            const int rb = (wc * 32 + j * 8 + g) * 36 + ko + tk;
            bf[j][0] = __float_as_uint(sB[rb]);
            bf[j][1] = __float_as_uint(sB[rb + 4]);
        }
#pragma unroll
        for (int i = 0; i < 4; i++)
#pragma unroll
            for (int j = 0; j < 4; j++) mma_tf32(cf[i][j], a[i], bf[j]);
    }

    float colsum[4][2] = {};
#pragma unroll
    for (int i = 0; i < 4; i++) {
#pragma unroll
        for (int half = 0; half < 2; half++) {
#pragma unroll
            for (int j = 0; j < 4; j++) {
                float e0 = __expf(cf[i][j][half * 2 + 0]);
                float e1 = __expf(cf[i][j][half * 2 + 1]);
                colsum[j][0] += e0;
                colsum[j][1] += e1;
            }
        }
    }
#pragma unroll
    for (int j = 0; j < 4; j++) {
        const int col = wc * 32 + j * 8 + 2 * tk;
        sX[(wr * 8 + g) * 132 + col]     = colsum[j][0];
        sX[(wr * 8 + g) * 132 + col + 1] = colsum[j][1];
    }
    __syncthreads();
    if (tid < 128) {
        float t = 0.f;
#pragma unroll
        for (int k = 0; k < 16; k++) t += sX[k * 132 + tid];
        part[((size_t)b * 32 + blockIdx.y) * NPOOL + n0 + tid] = t;
    }
}

// ================= vprime GEMM (unchanged) ============
#define GV_SA 2560
#define GV_SB 2176
__global__ __launch_bounds__(256)
void gemm_v2(const float* __restrict__ A,
             const float* __restrict__ B,
             float* __restrict__ C,
             int M, int N, int K)
{
    __shared__ float sm[2 * GV_SA + 2 * GV_SB];

    const int b  = blockIdx.z;
    const int r0 = blockIdx.y * 128;
    const int n0 = blockIdx.x * 128;
    const float* Ab = A;
    const float* Bb = B + (size_t)b * K * N;

    const int tid = threadIdx.x, lane = tid & 31, wid = tid >> 5;
    const int wr = wid >> 2, wc = wid & 3;
    const int g = lane >> 2, tk = lane & 3;

    const int a_r = tid >> 1, a_q = (tid & 1) * 2;
    const uint32_t smBase = (uint32_t)__cvta_generic_to_shared(sm);

    auto issue = [&](int k0, int s) {
#pragma unroll
        for (int u = 0; u < 2; u++) {
            int q = a_q + u;
            cpa16(smBase + (s * GV_SA + a_r * 20 + q * 4) * 4,
                  &Ab[(size_t)(r0 + a_r) * K + k0 + q * 4]);
        }
#pragma unroll
        for (int u = 0; u < 2; u++) {
            int idx = tid + u * 256;
            int kr = idx >> 5, nc = (idx & 31) * 4;
            cpa16(smBase + (2 * GV_SA + s * GV_SB + kr * 136 + nc) * 4,
                  &Bb[(size_t)(k0 + kr) * N + n0 + nc]);
        }
        asm volatile("cp.async.commit_group;");
    };

    float cf[4][4][4] = {};
    const int NIT = K / 16;

    issue(0, 0);
    for (int kt = 0; kt < NIT; kt++) {
        const int cur = kt & 1;
        if (kt < NIT - 1) {
            issue((kt + 1) * 16, cur ^ 1);
            asm volatile("cp.async.wait_group 1;");
        } else {
            asm volatile("cp.async.wait_group 0;");
        }
        __syncthreads();

        const float* cA = sm + cur * GV_SA;
        const float* cB = sm + 2 * GV_SA + cur * GV_SB;
#pragma unroll
        for (int ks = 0; ks < 2; ks++) {
            const int ko = ks * 8;
            uint32_t a[4][4], bf[4][2];
#pragma unroll
            for (int i = 0; i < 4; i++) {
                const int ra = (wr * 64 + i * 16 + g) * 20 + ko + tk;
                a[i][0] = __float_as_uint(cA[ra]);
                a[i][1] = __float_as_uint(cA[ra + 8 * 20]);
                a[i][2] = __float_as_uint(cA[ra + 4]);
                a[i][3] = __float_as_uint(cA[ra + 8 * 20 + 4]);
            }
#pragma unroll
            for (int j = 0; j < 4; j++) {
                const int nn = wc * 32 + j * 8 + g;
                bf[j][0] = __float_as_uint(cB[(ko + tk) * 136 + nn]);
                bf[j][1] = __float_as_uint(cB[(ko + tk + 4) * 136 + nn]);
            }
#pragma unroll
            for (int i = 0; i < 4; i++)
#pragma unroll
                for (int j = 0; j < 4; j++) mma_tf32(cf[i][j], a[i], bf[j]);
        }
        __syncthreads();
    }

    float* Cb = C + (size_t)b * M * N;
#pragma unroll
    for (int i = 0; i < 4; i++)
#pragma unroll
        for (int half = 0; half < 2; half++) {
            const int r = r0 + wr * 64 + i * 16 + g + half * 8;
            const size_t ro = (size_t)r * N;
#pragma unroll
            for (int j = 0; j < 4; j++) {
                const int c = n0 + wc * 32 + j * 8 + 2 * tk;
                float2 o;
                o.x = cf[i][j][half * 2 + 0];
                o.y = cf[i][j][half * 2 + 1];
                *(float2*)&Cb[ro + c] = o;
            }
        }
}

// ---------------- fused denominator + v'' (unchanged) ------------
__global__ void norm_v_k(const float* __restrict__ part,
                         const float* __restrict__ vpr,
                         __nv_bfloat16* __restrict__ vppb)
{
    int idx = blockIdx.x * 256 + threadIdx.x;
    int b  = idx >> 10;
    int np = idx & 1023;
    const float* p = part + (size_t)b * 32 * NPOOL + np;
    float s = 0.f;
#pragma unroll
    for (int i = 0; i < 32; i++) s += p[(size_t)i * NPOOL];
    const float inv = 1.f / s;

    const int c0 = blockIdx.y * 32;
    const float* v = vpr + (size_t)b * CCH * NPOOL + np;
    __nv_bfloat16* o = vppb + (size_t)b * CCH * NPOOL + np;
#pragma unroll 8
    for (int c = c0; c < c0 + 32; c++)
        o[(size_t)c * NPOOL] = __float2bfloat16_rn(v[(size_t)c * NPOOL] * inv);
}

// ============ pass-2: attend, 3-buffer early-issue pipeline =======
// floats: kT 4608 | qT 3x(64*36)=6912 | pstage 4608 | vA 3x(256*36)=27648
#define AT3_KT 0
#define AT3_QT 4608
#define AT3_PS 11520
#define AT3_VA 16128
#define AT3_SMEM_BYTES ((16128 + 3 * 9216) * 4)   // 175,104

__global__ __launch_bounds__(256)
void attend_k(const float* __restrict__ kTg, const float* __restrict__ qTg,
              const __nv_bfloat16* __restrict__ vpp,
              const float* __restrict__ bo,
              const float* __restrict__ gamma,
              const float* __restrict__ xres,
              float* __restrict__ out)
{
    extern __shared__ float smem[];
    float* sKT = smem + AT3_KT;
    float* sQT = smem + AT3_QT;
    uint32_t* pstage = (uint32_t*)(smem + AT3_PS);
    uint32_t* vA = (uint32_t*)(smem + AT3_VA);

    const int tid = threadIdx.x, lane = tid & 31, wid = tid >> 5;
    const int b  = blockIdx.z;
    const int m0 = blockIdx.x * 128;
    const int g = lane >> 2, tk = lane & 3;
    const int wr2 = wid >> 1, wc2 = wid & 1;
    const int wr = wid >> 1, wc = wid & 1;

    const float* Akt = kTg + ((size_t)b * NSP + m0) * CSP;
    const __nv_bfloat16* Av = vpp + (size_t)b * CCH * NPOOL;
    const uint32_t smBase = (uint32_t)__cvta_generic_to_shared(smem);

#pragma unroll
    for (int u = 0; u < 2; u++) {
        int idx = tid + u * 256;
        int r = idx >> 2, kq = (idx & 3) * 8;
        *(float4*)&sKT[r * 36 + kq]     = *(const float4*)&Akt[(size_t)r * CSP + kq];
        *(float4*)&sKT[r * 36 + kq + 4] = *(const float4*)&Akt[(size_t)r * CSP + kq + 4];
    }

    auto issue = [&](int c, int s) {
        const int np0 = c * 64;
        const float* Bq = qTg + ((size_t)b * NPOOL + np0) * CSP;
#pragma unroll
        for (int u = 0; u < 2; u++) {
            int idx = tid + u * 256;
            int r = idx >> 3, kq = (idx & 7) * 4;
            cpa16(smBase + (AT3_QT + s * 64 * 36 + r * 36 + kq) * 4,
                  &Bq[(size_t)r * CSP + kq]);
        }
#pragma unroll
        for (int u = 0; u < 8; u++) {
            int idx = tid + u * 256;
            int row = idx >> 3, q = idx & 7;
            cpa16(smBase + (AT3_VA + s * 256 * 36 + row * 36 + q * 4) * 4,
                  &Av[(size_t)row * NPOOL + np0 + q * 8]);
        }
        asm volatile("cp.async.commit_group;");
    };

    float cfO[4][8][4] = {};

    issue(0, 0);
    issue(1, 1);
    for (int c = 0; c < 16; c++) {
        const int cur = c % 3;
        // early issue: buffer (c+2)%3 was released by iteration c-1's final sync
        if (c + 2 < 16) {
            issue(c + 2, (c + 2) % 3);
            asm volatile("cp.async.wait_group 2;");
        } else if (c + 1 < 16) {
            asm volatile("cp.async.wait_group 1;");
        } else {
            asm volatile("cp.async.wait_group 0;");
        }
        __syncthreads();

        const float* cQ = sQT + cur * 64 * 36;
        const uint32_t* cV = vA + cur * 256 * 36;

        float cf2[2][4][4] = {};
#pragma unroll
        for (int ks = 0; ks < 4; ks++) {
            const int ko = ks * 8;
            uint32_t a[2][4], bf[4][2];
#pragma unroll
            for (int i = 0; i < 2; i++) {
                const int ra = (wr2 * 32 + i * 16 + g) * 36 + ko + tk;
                a[i][0] = __float_as_uint(sKT[ra]);
                a[i][1] = __float_as_uint(sKT[ra + 8 * 36]);
                a[i][2] = __float_as_uint(sKT[ra + 4]);
                a[i][3] = __float_as_uint(sKT[ra + 8 * 36 + 4]);
            }
#pragma unroll
            for (int j = 0; j < 4; j++) {
                const int rb = (wc2 * 32 + j * 8 + g) * 36 + ko + tk;
                bf[j][0] = __float_as_uint(cQ[rb]);
                bf[j][1] = __float_as_uint(cQ[rb + 4]);
            }
#pragma unroll
            for (int i = 0; i < 2; i++)
#pragma unroll
                for (int j = 0; j < 4; j++) mma_tf32(cf2[i][j], a[i], bf[j]);
        }

#pragma unroll
        for (int i = 0; i < 2; i++) {
#pragma unroll
            for (int half = 0; half < 2; half++) {
                const int lr = wr2 * 32 + i * 16 + half * 8 + g;
#pragma unroll
                for (int j = 0; j < 4; j++) {
                    const int lc2 = wc2 * 16 + j * 4 + tk;
                    float e0 = __expf(cf2[i][j][half * 2 + 0]);
                    float e1 = __expf(cf2[i][j][half * 2 + 1]);
                    __nv_bfloat162 p2 = __floats2bfloat162_rn(e0, e1);
                    pstage[lr * 36 + lc2] = *(uint32_t*)&p2;
                }
            }
        }
        __syncthreads();

#pragma unroll
        for (int ks2 = 0; ks2 < 4; ks2++) {
            uint32_t a[4][4], bf[8][2];
#pragma unroll
            for (int i = 0; i < 4; i++) {
                const int ra = (wr * 64 + i * 16 + g) * 36 + ks2 * 8 + tk;
                a[i][0] = cV[ra];
                a[i][1] = cV[ra + 8 * 36];
                a[i][2] = cV[ra + 4];
                a[i][3] = cV[ra + 8 * 36 + 4];
            }
#pragma unroll
            for (int j = 0; j < 8; j++) {
                const int rb = (wc * 64 + j * 8 + g) * 36 + ks2 * 8 + tk;
                bf[j][0] = pstage[rb];
                bf[j][1] = pstage[rb + 4];
            }
#pragma unroll
            for (int i = 0; i < 4; i++)
#pragma unroll
                for (int j = 0; j < 8; j++) mma_bf16(cfO[i][j], a[i], bf[j]);
        }
        __syncthreads();
    }

    const float gm = gamma[0];
#pragma unroll
    for (int i = 0; i < 4; i++) {
#pragma unroll
        for (int half = 0; half < 2; half++) {
            const int c = wr * 64 + i * 16 + g + half * 8;
            const float bc = bo[c];
            const size_t ro = ((size_t)b * CCH + c) * NSP;
#pragma unroll
            for (int j = 0; j < 8; j++) {
                const int m = m0 + wc * 64 + j * 8 + 2 * tk;
                float2 xr = *(const float2*)&xres[ro + m];
                float2 o;
                o.x = gm * (cfO[i][j][half * 2 + 0] + bc) + xr.x;
                o.y = gm * (cfO[i][j][half * 2 + 1] + bc) + xr.y;
                *(float2*)&out[ro + m] = o;
            }
        }
    }
}

// ---------------- launch ----------------
extern "C" void kernel_launch(void* const* d_in, const int* in_sizes, int n_in,
                              void* d_out, int out_size)
{
    const float* x     = (const float*)d_in[0];
    const float* wq    = (const float*)d_in[1];
    const float* bq    = (const float*)d_in[2];
    const float* wk    = (const float*)d_in[3];
    const float* bk    = (const float*)d_in[4];
    const float* wv    = (const float*)d_in[5];
    const float* bv    = (const float*)d_in[6];
    const float* wo    = (const float*)d_in[7];
    const float* bo    = (const float*)d_in[8];
    const float* gamma = (const float*)d_in[9];
    float* out = (float*)d_out;

    float *pkT, *pqT, *pwor, *pvp, *pvpr, *ppart;
    __nv_bfloat16 *pvppb;
    cudaGetSymbolAddress((void**)&pkT,    g_kT);
    cudaGetSymbolAddress((void**)&pqT,    g_qT);
    cudaGetSymbolAddress((void**)&pwor,   g_wor);
    cudaGetSymbolAddress((void**)&pvp,    g_vpool);
    cudaGetSymbolAddress((void**)&pvpr,   g_vprime);
    cudaGetSymbolAddress((void**)&ppart,  g_part);
    cudaGetSymbolAddress((void**)&pvppb,  g_vppb);

    static cudaStream_t s1 = nullptr;
    static cudaEvent_t evFork = nullptr, evJoin = nullptr;
    if (s1 == nullptr) {
        cudaStreamCreateWithFlags(&s1, cudaStreamNonBlocking);
        cudaEventCreateWithFlags(&evFork, cudaEventDisableTiming);
        cudaEventCreateWithFlags(&evJoin, cudaEventDisableTiming);
        cudaFuncSetAttribute(attend_k, cudaFuncAttributeMaxDynamicSharedMemorySize,
                             AT3_SMEM_BYTES);
    }

    cudaEventRecord(evFork, 0);
    cudaStreamWaitEvent(s1, evFork, 0);

    // s1: V branch runs fully parallel to the QK chain (no dependency)
    round_wo_k<<<(CCH * CCH) / 1024, 256, 0, s1>>>(wo, pwor);
    {   // conv_v: vpool
        dim3 g(NSP / 128, CCH / 128, BATCH);
        conv_v_k<<<g, 256, 0, s1>>>(wv, bv, x, pvp);
    }
    {   // vprime
        dim3 g(NPOOL / 128, CCH / 128, BATCH);
        gemm_v2<<<g, 256, 0, s1>>>(pwor, pvp, pvpr, CCH, NPOOL, CCH);
    }
    cudaEventRecord(evJoin, s1);

    // main: conv_qk -> energy_cs
    {
        dim3 g(NSP / 128, 1, BATCH);
        conv_qk_k<<<g, 256>>>(wk, bk, wq, bq, x, pkT, pqT);
    }
    {
        dim3 g(NPOOL / 128, NSP / 128, BATCH);
        energy_cs<<<g, 256>>>(pkT, pqT, ppart);
    }

    // join, normalize -> v'' bf16, then attend
    cudaStreamWaitEvent(0, evJoin, 0);
    {
        dim3 g(BATCH * NPOOL / 256, CCH / 32);
        norm_v_k<<<g, 256>>>(ppart, pvpr, pvppb);
    }
    {
        dim3 g(NSP / 128, 1, BATCH);
        attend_k<<<g, 256, AT3_SMEM_BYTES>>>(pkT, pqT, pvppb, bo, gamma, x, out);
    }
}

// round 17
// speedup vs baseline: 1.3529x; 1.0252x over previous
#include <cuda_runtime.h>
#include <cuda_bf16.h>
#include <math.h>
#include <stdint.h>

#define BATCH 16
#define CCH   256
#define NSP   4096   // 64*64
#define CSP   32     // C/8
#define NPOOL 1024   // 32*32

// ---------------- scratch ----------------
__device__ float g_kT[BATCH * NSP * CSP];                    //  8 MB tf32 (B, n, 32)
__device__ float g_qT[BATCH * NPOOL * CSP];                  //  2 MB tf32 (B, np, 32)
__device__ float g_wor[CCH * CCH];                           // 256 KB tf32-RN wo
__device__ float g_vpool[BATCH * CCH * NPOOL];               // 16 MB (tf32-RN values)
__device__ float g_vprime[BATCH * CCH * NPOOL];              // 16 MB
__device__ float g_part[BATCH * 32 * NPOOL];                 //  2 MB
__device__ __nv_bfloat16 g_vppb[BATCH * CCH * NPOOL];        //  8 MB

// ---------------- helpers ----------------
__device__ __forceinline__ float tf32_rn(float v) {
    uint32_t u;
    asm("cvt.rna.tf32.f32 %0, %1;" : "=r"(u) : "f"(v));
    return __uint_as_float(u);
}
__device__ __forceinline__ uint32_t tf32u(float v) {
    uint32_t u;
    asm("cvt.rna.tf32.f32 %0, %1;" : "=r"(u) : "f"(v));
    return u;
}
__device__ __forceinline__ void mma_tf32(float* c, const uint32_t* a, const uint32_t* b) {
    asm volatile(
        "mma.sync.aligned.m16n8k8.row.col.f32.tf32.tf32.f32 "
        "{%0,%1,%2,%3}, {%4,%5,%6,%7}, {%8,%9}, {%0,%1,%2,%3};"
        : "+f"(c[0]), "+f"(c[1]), "+f"(c[2]), "+f"(c[3])
        : "r"(a[0]), "r"(a[1]), "r"(a[2]), "r"(a[3]), "r"(b[0]), "r"(b[1]));
}
__device__ __forceinline__ void mma_bf16(float* c, const uint32_t* a, const uint32_t* b) {
    asm volatile(
        "mma.sync.aligned.m16n8k16.row.col.f32.bf16.bf16.f32 "
        "{%0,%1,%2,%3}, {%4,%5,%6,%7}, {%8,%9}, {%0,%1,%2,%3};"
        : "+f"(c[0]), "+f"(c[1]), "+f"(c[2]), "+f"(c[3])
        : "r"(a[0]), "r"(a[1]), "r"(a[2]), "r"(a[3]), "r"(b[0]), "r"(b[1]));
}
__device__ __forceinline__ void cpa16(uint32_t dst, const void* src) {
    asm volatile("cp.async.cg.shared.global [%0], [%1], 16;" :: "r"(dst), "l"(src));
}

// ---------------- pre-round wo to tf32-RN ----------------
__global__ void round_wo_k(const float* __restrict__ wo, float* __restrict__ wor)
{
    int i = (blockIdx.x * 256 + threadIdx.x) * 4;
    float4 b = *(const float4*)&wo[i];
    b.x = tf32_rn(b.x); b.y = tf32_rn(b.y); b.z = tf32_rn(b.z); b.w = tf32_rn(b.w);
    *(float4*)&wor[i] = b;
}

#define CV_SA 2560      // 128*20 floats per buffer
#define CV_SB 2176      // 16*136 floats per buffer

// ============ conv_qk: kT + pooled qT (cp.async; tf32-RN at fragment read) ====
__global__ __launch_bounds__(256)
void conv_qk_k(const float* __restrict__ wk, const float* __restrict__ bk,
               const float* __restrict__ wq, const float* __restrict__ bq,
               const float* __restrict__ x,
               float* __restrict__ kT, float* __restrict__ qT)
{
    __shared__ union {
        struct { float sA[2][CV_SA]; float sB[2][CV_SB]; } ld;
        float sOut[64 * 132];
    } sh;

    const int b    = blockIdx.z;
    const int col0 = blockIdx.x * 128;
    const float* xb = x + (size_t)b * CCH * NSP;
    const int tid = threadIdx.x, lane = tid & 31, wid = tid >> 5;
    const int wr = wid >> 2, wc = wid & 3;
    const int g = lane >> 2, tk = lane & 3;

    const uint32_t smBase = (uint32_t)__cvta_generic_to_shared(&sh);
    const uint32_t sbOff  = 2 * CV_SA * 4;

    auto issue = [&](int k0, int s) {
        {
            int r = tid >> 2, kq = (tid & 3) * 4;
            const float* wrow = (r < 32) ? (wk + r * CCH) : (wq + (r - 32) * CCH);
            cpa16(smBase + (s * CV_SA + r * 20 + kq) * 4, &wrow[k0 + kq]);
        }
#pragma unroll
        for (int u = 0; u < 2; u++) {
            int idx = tid + u * 256;
            int kr = idx >> 5, nc = (idx & 31) * 4;
            cpa16(smBase + sbOff + (s * CV_SB + kr * 136 + nc) * 4,
                  &xb[(size_t)(k0 + kr) * NSP + col0 + nc]);
        }
        asm volatile("cp.async.commit_group;");
    };

    float cf[2][4][4] = {};
    issue(0, 0);
    for (int kt = 0; kt < 16; kt++) {
        const int cur = kt & 1;
        if (kt < 15) { issue((kt + 1) * 16, cur ^ 1);
                       asm volatile("cp.async.wait_group 1;"); }
        else           asm volatile("cp.async.wait_group 0;");
        __syncthreads();

        const float* cA = sh.ld.sA[cur];
        const float* cB = sh.ld.sB[cur];
#pragma unroll
        for (int ks = 0; ks < 2; ks++) {
            const int ko = ks * 8;
            uint32_t a[2][4], bf[4][2];
#pragma unroll
            for (int i = 0; i < 2; i++) {
                const int ra = (wr * 32 + i * 16 + g) * 20 + ko + tk;
                a[i][0] = tf32u(cA[ra]);
                a[i][1] = tf32u(cA[ra + 8 * 20]);
                a[i][2] = tf32u(cA[ra + 4]);
                a[i][3] = tf32u(cA[ra + 8 * 20 + 4]);
            }
#pragma unroll
            for (int j = 0; j < 4; j++) {
                const int nn = wc * 32 + j * 8 + g;
                bf[j][0] = tf32u(cB[(ko + tk) * 136 + nn]);
                bf[j][1] = tf32u(cB[(ko + tk + 4) * 136 + nn]);
            }
#pragma unroll
            for (int i = 0; i < 2; i++)
#pragma unroll
                for (int j = 0; j < 4; j++) mma_tf32(cf[i][j], a[i], bf[j]);
        }
        __syncthreads();
    }

#pragma unroll
    for (int i = 0; i < 2; i++)
#pragma unroll
        for (int half = 0; half < 2; half++) {
            const int r = wr * 32 + i * 16 + half * 8 + g;
#pragma unroll
            for (int j = 0; j < 4; j++) {
                const int c = wc * 32 + j * 8 + 2 * tk;
                sh.sOut[r * 132 + c]     = cf[i][j][half * 2 + 0];
                sh.sOut[r * 132 + c + 1] = cf[i][j][half * 2 + 1];
            }
        }
    __syncthreads();

    float* kTb = kT + (size_t)b * NSP * CSP;
#pragma unroll
    for (int u = 0; u < 4; u++) {
        int idx = tid + u * 256;
        int nn = idx >> 3, csq = (idx & 7) * 4;
        float4 o;
        o.x = tf32_rn(sh.sOut[(csq + 0) * 132 + nn] + bk[csq + 0]);
        o.y = tf32_rn(sh.sOut[(csq + 1) * 132 + nn] + bk[csq + 1]);
        o.z = tf32_rn(sh.sOut[(csq + 2) * 132 + nn] + bk[csq + 2]);
        o.w = tf32_rn(sh.sOut[(csq + 3) * 132 + nn] + bk[csq + 3]);
        *(float4*)&kTb[(size_t)(col0 + nn) * CSP + csq] = o;
    }

    float* qTb = qT + (size_t)b * NPOOL * CSP;
    const int hp = col0 >> 7;
    {
        int wp = tid >> 3, csq = (tid & 7) * 4;
        float4 o;
        float* oc = &o.x;
#pragma unroll
        for (int t = 0; t < 4; t++) {
            const int cs = csq + t;
            const float* r = &sh.sOut[(32 + cs) * 132];
            float v = fmaxf(fmaxf(r[2 * wp], r[2 * wp + 1]),
                            fmaxf(r[64 + 2 * wp], r[64 + 2 * wp + 1]));
            oc[t] = tf32_rn(v + bq[cs]);
        }
        *(float4*)&qTb[(size_t)(hp * 32 + wp) * CSP + csq] = o;
    }
}

// ============ conv_v: vpool slices (independent of conv_qk) ====
__global__ __launch_bounds__(256)
void conv_v_k(const float* __restrict__ wv, const float* __restrict__ bv,
              const float* __restrict__ x, float* __restrict__ vpool)
{
    __shared__ union {
        struct { float sA[2][CV_SA]; float sB[2][CV_SB]; } ld;
        float sX[32 * 132];
    } sh;

    const int b    = blockIdx.z;
    const int r0   = blockIdx.y * 128;
    const int col0 = blockIdx.x * 128;
    const float* xb = x + (size_t)b * CCH * NSP;
    const int tid = threadIdx.x, lane = tid & 31, wid = tid >> 5;
    const int wr = wid >> 2, wc = wid & 3;
    const int g = lane >> 2, tk = lane & 3;

    const uint32_t smBase = (uint32_t)__cvta_generic_to_shared(&sh);
    const uint32_t sbOff  = 2 * CV_SA * 4;

    auto issue = [&](int k0, int s) {
        {
            int r = tid >> 1, kq = (tid & 1) * 8;
#pragma unroll
            for (int q = 0; q < 2; q++)
                cpa16(smBase + (s * CV_SA + r * 20 + kq + q * 4) * 4,
                      &wv[(size_t)(r0 + r) * CCH + k0 + kq + q * 4]);
        }
#pragma unroll
        for (int u = 0; u < 2; u++) {
            int idx = tid + u * 256;
            int kr = idx >> 5, nc = (idx & 31) * 4;
            cpa16(smBase + sbOff + (s * CV_SB + kr * 136 + nc) * 4,
                  &xb[(size_t)(k0 + kr) * NSP + col0 + nc]);
        }
        asm volatile("cp.async.commit_group;");
    };

    float cf[4][4][4] = {};
    issue(0, 0);
    for (int kt = 0; kt < 16; kt++) {
        const int cur = kt & 1;
        if (kt < 15) { issue((kt + 1) * 16, cur ^ 1);
                       asm volatile("cp.async.wait_group 1;"); }
        else           asm volatile("cp.async.wait_group 0;");
        __syncthreads();

        const float* cA = sh.ld.sA[cur];
        const float* cB = sh.ld.sB[cur];
#pragma unroll
        for (int ks = 0; ks < 2; ks++) {
            const int ko = ks * 8;
            uint32_t a[4][4], bf[4][2];
#pragma unroll
            for (int i = 0; i < 4; i++) {
                const int ra = (wr * 64 + i * 16 + g) * 20 + ko + tk;
                a[i][0] = tf32u(cA[ra]);
                a[i][1] = tf32u(cA[ra + 8 * 20]);
                a[i][2] = tf32u(cA[ra + 4]);
                a[i][3] = tf32u(cA[ra + 8 * 20 + 4]);
            }
#pragma unroll
            for (int j = 0; j < 4; j++) {
                const int nn = wc * 32 + j * 8 + g;
                bf[j][0] = tf32u(cB[(ko + tk) * 136 + nn]);
                bf[j][1] = tf32u(cB[(ko + tk + 4) * 136 + nn]);
            }
#pragma unroll
            for (int i = 0; i < 4; i++)
#pragma unroll
                for (int j = 0; j < 4; j++) mma_tf32(cf[i][j], a[i], bf[j]);
        }
        __syncthreads();
    }

    float* Cp = vpool + (size_t)b * CCH * NPOOL;
    const int pcb = col0 >> 2;
#pragma unroll 1
    for (int s = 0; s < 4; s++) {
        if (wr == (s >> 1)) {
#pragma unroll
            for (int ii = 0; ii < 2; ii++) {
                const int i = (s & 1) * 2 + ii;
#pragma unroll
                for (int half = 0; half < 2; half++) {
                    const int lr = ii * 16 + half * 8 + g;
#pragma unroll
                    for (int j = 0; j < 4; j++) {
                        const int col = wc * 32 + j * 8 + 2 * tk;
                        sh.sX[lr * 132 + col]     = cf[i][j][half * 2 + 0];
                        sh.sX[lr * 132 + col + 1] = cf[i][j][half * 2 + 1];
                    }
                }
            }
        }
        __syncthreads();
#pragma unroll
        for (int u = 0; u < 4; u++) {
            int po = tid + u * 256;
            int rr = po >> 5, pc = po & 31;
            float v = fmaxf(fmaxf(sh.sX[rr * 132 + 2 * pc], sh.sX[rr * 132 + 2 * pc + 1]),
                            fmaxf(sh.sX[rr * 132 + 64 + 2 * pc], sh.sX[rr * 132 + 64 + 2 * pc + 1]));
            const int r = r0 + s * 32 + rr;
            Cp[(size_t)r * NPOOL + pcb + pc] = tf32_rn(v + bv[r]);
        }
        __syncthreads();
    }
}

// ============ pass-1 energy: column sums only (unchanged) ====
__global__ __launch_bounds__(256)
void energy_cs(const float* __restrict__ kTg, const float* __restrict__ qTg,
               float* __restrict__ part)
{
    __shared__ float sA[128 * 36];
    __shared__ float sB[128 * 36];
    __shared__ float sX[16 * 132];

    const int b  = blockIdx.z;
    const int m0 = blockIdx.y * 128;
    const int n0 = blockIdx.x * 128;
    const float* Ab = kTg + ((size_t)b * NSP + m0) * CSP;
    const float* Bb = qTg + ((size_t)b * NPOOL + n0) * CSP;

    const int tid = threadIdx.x, lane = tid & 31, wid = tid >> 5;
    const int wr = wid >> 2, wc = wid & 3;
    const int g = lane >> 2, tk = lane & 3;

#pragma unroll
    for (int u = 0; u < 4; u++) {
        int idx = tid + u * 256;
        int r = idx >> 3, kq = (idx & 7) * 4;
        *(float4*)&sA[r * 36 + kq] = *(const float4*)&Ab[(size_t)r * CSP + kq];
        *(float4*)&sB[r * 36 + kq] = *(const float4*)&Bb[(size_t)r * CSP + kq];
    }
    __syncthreads();

    float cf[4][4][4] = {};
#pragma unroll
    for (int ks = 0; ks < 4; ks++) {
        const int ko = ks * 8;
        uint32_t a[4][4], bf[4][2];
#pragma unroll
        for (int i = 0; i < 4; i++) {
            const int ra = (wr * 64 + i * 16 + g) * 36 + ko + tk;
            a[i][0] = __float_as_uint(sA[ra]);
            a[i][1] = __float_as_uint(sA[ra + 8 * 36]);
            a[i][2] = __float_as_uint(sA[ra + 4]);
            a[i][3] = __float_as_uint(sA[ra + 8 * 36 + 4]);
        }
#pragma unroll
        for (int j = 0; j < 4; j++) {
            const int rb = (wc * 32 + j * 8 + g) * 36 + ko + tk;
            bf[j][0] = __float_as_uint(sB[rb]);
            bf[j][1] = __float_as_uint(sB[rb + 4]);
        }
#pragma unroll
        for (int i = 0; i < 4; i++)
#pragma unroll
            for (int j = 0; j < 4; j++) mma_tf32(cf[i][j], a[i], bf[j]);
    }

    float colsum[4][2] = {};
#pragma unroll
    for (int i = 0; i < 4; i++) {
#pragma unroll
        for (int half = 0; half < 2; half++) {
#pragma unroll
            for (int j = 0; j < 4; j++) {
                float e0 = __expf(cf[i][j][half * 2 + 0]);
                float e1 = __expf(cf[i][j][half * 2 + 1]);
                colsum[j][0] += e0;
                colsum[j][1] += e1;
            }
        }
    }
#pragma unroll
    for (int j = 0; j < 4; j++) {
        const int col = wc * 32 + j * 8 + 2 * tk;
        sX[(wr * 8 + g) * 132 + col]     = colsum[j][0];
        sX[(wr * 8 + g) * 132 + col + 1] = colsum[j][1];
    }
    __syncthreads();
    if (tid < 128) {
        float t = 0.f;
#pragma unroll
        for (int k = 0; k < 16; k++) t += sX[k * 132 + tid];
        part[((size_t)b * 32 + blockIdx.y) * NPOOL + n0 + tid] = t;
    }
}

// ================= vprime GEMM (unchanged) ============
#define GV_SA 2560
#define GV_SB 2176
__global__ __launch_bounds__(256)
void gemm_v2(const float* __restrict__ A,
             const float* __restrict__ B,
             float* __restrict__ C,
             int M, int N, int K)
{
    __shared__ float sm[2 * GV_SA + 2 * GV_SB];

    const int b  = blockIdx.z;
    const int r0 = blockIdx.y * 128;
    const int n0 = blockIdx.x * 128;
    const float* Ab = A;
    const float* Bb = B + (size_t)b * K * N;

    const int tid = threadIdx.x, lane = tid & 31, wid = tid >> 5;
    const int wr = wid >> 2, wc = wid & 3;
    const int g = lane >> 2, tk = lane & 3;

    const int a_r = tid >> 1, a_q = (tid & 1) * 2;
    const uint32_t smBase = (uint32_t)__cvta_generic_to_shared(sm);

    auto issue = [&](int k0, int s) {
#pragma unroll
        for (int u = 0; u < 2; u++) {
            int q = a_q + u;
            cpa16(smBase + (s * GV_SA + a_r * 20 + q * 4) * 4,
                  &Ab[(size_t)(r0 + a_r) * K + k0 + q * 4]);
        }
#pragma unroll
        for (int u = 0; u < 2; u++) {
            int idx = tid + u * 256;
            int kr = idx >> 5, nc = (idx & 31) * 4;
            cpa16(smBase + (2 * GV_SA + s * GV_SB + kr * 136 + nc) * 4,
                  &Bb[(size_t)(k0 + kr) * N + n0 + nc]);
        }
        asm volatile("cp.async.commit_group;");
    };

    float cf[4][4][4] = {};
    const int NIT = K / 16;

    issue(0, 0);
    for (int kt = 0; kt < NIT; kt++) {
        const int cur = kt & 1;
        if (kt < NIT - 1) {
            issue((kt + 1) * 16, cur ^ 1);
            asm volatile("cp.async.wait_group 1;");
        } else {
            asm volatile("cp.async.wait_group 0;");
        }
        __syncthreads();

        const float* cA = sm + cur * GV_SA;
        const float* cB = sm + 2 * GV_SA + cur * GV_SB;
#pragma unroll
        for (int ks = 0; ks < 2; ks++) {
            const int ko = ks * 8;
            uint32_t a[4][4], bf[4][2];
#pragma unroll
            for (int i = 0; i < 4; i++) {
                const int ra = (wr * 64 + i * 16 + g) * 20 + ko + tk;
                a[i][0] = __float_as_uint(cA[ra]);
                a[i][1] = __float_as_uint(cA[ra + 8 * 20]);
                a[i][2] = __float_as_uint(cA[ra + 4]);
                a[i][3] = __float_as_uint(cA[ra + 8 * 20 + 4]);
            }
#pragma unroll
            for (int j = 0; j < 4; j++) {
                const int nn = wc * 32 + j * 8 + g;
                bf[j][0] = __float_as_uint(cB[(ko + tk) * 136 + nn]);
                bf[j][1] = __float_as_uint(cB[(ko + tk + 4) * 136 + nn]);
            }
#pragma unroll
            for (int i = 0; i < 4; i++)
#pragma unroll
                for (int j = 0; j < 4; j++) mma_tf32(cf[i][j], a[i], bf[j]);
        }
        __syncthreads();
    }

    float* Cb = C + (size_t)b * M * N;
#pragma unroll
    for (int i = 0; i < 4; i++)
#pragma unroll
        for (int half = 0; half < 2; half++) {
            const int r = r0 + wr * 64 + i * 16 + g + half * 8;
            const size_t ro = (size_t)r * N;
#pragma unroll
            for (int j = 0; j < 4; j++) {
                const int c = n0 + wc * 32 + j * 8 + 2 * tk;
                float2 o;
                o.x = cf[i][j][half * 2 + 0];
                o.y = cf[i][j][half * 2 + 1];
                *(float2*)&Cb[ro + c] = o;
            }
        }
}

// ---------------- fused denominator + v'' (unchanged) ------------
__global__ void norm_v_k(const float* __restrict__ part,
                         const float* __restrict__ vpr,
                         __nv_bfloat16* __restrict__ vppb)
{
    int idx = blockIdx.x * 256 + threadIdx.x;
    int b  = idx >> 10;
    int np = idx & 1023;
    const float* p = part + (size_t)b * 32 * NPOOL + np;
    float s = 0.f;
#pragma unroll
    for (int i = 0; i < 32; i++) s += p[(size_t)i * NPOOL];
    const float inv = 1.f / s;

    const int c0 = blockIdx.y * 32;
    const float* v = vpr + (size_t)b * CCH * NPOOL + np;
    __nv_bfloat16* o = vppb + (size_t)b * CCH * NPOOL + np;
#pragma unroll 8
    for (int c = c0; c < c0 + 32; c++)
        o[(size_t)c * NPOOL] = __float2bfloat16_rn(v[(size_t)c * NPOOL] * inv);
}

// ============ pass-2: attend, m-tile 64, 2 CTAs/SM =======
// floats: kT 64*36=2304 | qT 2x2304 | pstage 2304 (u32) | vA 2x(256*36)=18432 (u32)
#define AT4_KT 0
#define AT4_QT 2304
#define AT4_PS 6912
#define AT4_VA 9216
#define AT4_SMEM_BYTES ((9216 + 2 * 9216) * 4)   // 110,592

__global__ __launch_bounds__(256, 2)
void attend_k(const float* __restrict__ kTg, const float* __restrict__ qTg,
              const __nv_bfloat16* __restrict__ vpp,
              const float* __restrict__ bo,
              const float* __restrict__ gamma,
              const float* __restrict__ xres,
              float* __restrict__ out)
{
    extern __shared__ float smem[];
    float* sKT = smem + AT4_KT;
    float* sQT = smem + AT4_QT;                  // [2][64*36]
    uint32_t* pstage = (uint32_t*)(smem + AT4_PS);
    uint32_t* vA = (uint32_t*)(smem + AT4_VA);   // [2][256*36]

    const int tid = threadIdx.x, lane = tid & 31, wid = tid >> 5;
    const int b  = blockIdx.z;
    const int m0 = blockIdx.x * 64;
    const int g = lane >> 2, tk = lane & 3;
    // E-phase: 64 n-rows x 64 np -> wr2 (4 x 16 n), wc2 (2 x 32 np)
    const int wr2 = wid >> 1, wc2 = wid & 1;
    // out-phase: 256 c x 64 m -> wr (4 x 64 c), wc (2 x 32 m)
    const int wr = wid >> 1, wc = wid & 1;

    const float* Akt = kTg + ((size_t)b * NSP + m0) * CSP;
    const __nv_bfloat16* Av = vpp + (size_t)b * CCH * NPOOL;
    const uint32_t smBase = (uint32_t)__cvta_generic_to_shared(smem);

    // kT rows (persistent): 64 x 32 = 512 float4, 2 per thread
    {
        int r = tid >> 2, kq = (tid & 3) * 8;
        *(float4*)&sKT[r * 36 + kq]     = *(const float4*)&Akt[(size_t)r * CSP + kq];
        *(float4*)&sKT[r * 36 + kq + 4] = *(const float4*)&Akt[(size_t)r * CSP + kq + 4];
    }

    auto issue = [&](int c, int s) {
        const int np0 = c * 64;
        const float* Bq = qTg + ((size_t)b * NPOOL + np0) * CSP;
#pragma unroll
        for (int u = 0; u < 2; u++) {
            int idx = tid + u * 256;
            int r = idx >> 3, kq = (idx & 7) * 4;
            cpa16(smBase + (AT4_QT + s * 64 * 36 + r * 36 + kq) * 4,
                  &Bq[(size_t)r * CSP + kq]);
        }
#pragma unroll
        for (int u = 0; u < 8; u++) {
            int idx = tid + u * 256;
            int row = idx >> 3, q = idx & 7;
            cpa16(smBase + (AT4_VA + s * 256 * 36 + row * 36 + q * 4) * 4,
                  &Av[(size_t)row * NPOOL + np0 + q * 8]);
        }
        asm volatile("cp.async.commit_group;");
    };

    float cfO[4][4][4] = {};

    issue(0, 0);
    for (int c = 0; c < 16; c++) {
        const int cur = c & 1;
        if (c < 15) { issue(c + 1, cur ^ 1);
                      asm volatile("cp.async.wait_group 1;"); }
        else          asm volatile("cp.async.wait_group 0;");
        __syncthreads();

        const float* cQ = sQT + cur * 64 * 36;
        const uint32_t* cV = vA + cur * 256 * 36;

        // E tile 64 x 64 (same k-chain -> identical values)
        float cf2[4][4] = {};
#pragma unroll
        for (int ks = 0; ks < 4; ks++) {
            const int ko = ks * 8;
            uint32_t a[4], bf[4][2];
            {
                const int ra = (wr2 * 16 + g) * 36 + ko + tk;
                a[0] = __float_as_uint(sKT[ra]);
                a[1] = __float_as_uint(sKT[ra + 8 * 36]);
                a[2] = __float_as_uint(sKT[ra + 4]);
                a[3] = __float_as_uint(sKT[ra + 8 * 36 + 4]);
            }
#pragma unroll
            for (int j = 0; j < 4; j++) {
                const int rb = (wc2 * 32 + j * 8 + g) * 36 + ko + tk;
                bf[j][0] = __float_as_uint(cQ[rb]);
                bf[j][1] = __float_as_uint(cQ[rb + 4]);
            }
#pragma unroll
            for (int j = 0; j < 4; j++) mma_tf32(cf2[j], a, bf[j]);
        }

        // exp -> bf16 p-stage
#pragma unroll
        for (int half = 0; half < 2; half++) {
            const int lr = wr2 * 16 + half * 8 + g;
#pragma unroll
            for (int j = 0; j < 4; j++) {
                const int lc2 = wc2 * 16 + j * 4 + tk;
                float e0 = __expf(cf2[j][half * 2 + 0]);
                float e1 = __expf(cf2[j][half * 2 + 1]);
                __nv_bfloat162 p2 = __floats2bfloat162_rn(e0, e1);
                pstage[lr * 36 + lc2] = *(uint32_t*)&p2;
            }
        }
        __syncthreads();

        // out contraction: 4 k-steps of 16 (global np order preserved)
#pragma unroll
        for (int ks2 = 0; ks2 < 4; ks2++) {
            uint32_t a[4][4], bf[4][2];
#pragma unroll
            for (int i = 0; i < 4; i++) {
                const int ra = (wr * 64 + i * 16 + g) * 36 + ks2 * 8 + tk;
                a[i][0] = cV[ra];
                a[i][1] = cV[ra + 8 * 36];
                a[i][2] = cV[ra + 4];
                a[i][3] = cV[ra + 8 * 36 + 4];
            }
#pragma unroll
            for (int j = 0; j < 4; j++) {
                const int rb = (wc * 32 + j * 8 + g) * 36 + ks2 * 8 + tk;
                bf[j][0] = pstage[rb];
                bf[j][1] = pstage[rb + 4];
            }
#pragma unroll
            for (int i = 0; i < 4; i++)
#pragma unroll
                for (int j = 0; j < 4; j++) mma_bf16(cfO[i][j], a[i], bf[j]);
        }
        __syncthreads();
    }

    // epilogue (same per-element math as before)
    const float gm = gamma[0];
#pragma unroll
    for (int i = 0; i < 4; i++) {
#pragma unroll
        for (int half = 0; half < 2; half++) {
            const int c = wr * 64 + i * 16 + g + half * 8;
            const float bc = bo[c];
            const size_t ro = ((size_t)b * CCH + c) * NSP;
#pragma unroll
            for (int j = 0; j < 4; j++) {
                const int m = m0 + wc * 32 + j * 8 + 2 * tk;
                float2 xr = *(const float2*)&xres[ro + m];
                float2 o;
                o.x = gm * (cfO[i][j][half * 2 + 0] + bc) + xr.x;
                o.y = gm * (cfO[i][j][half * 2 + 1] + bc) + xr.y;
                *(float2*)&out[ro + m] = o;
            }
        }
    }
}

// ---------------- launch ----------------
extern "C" void kernel_launch(void* const* d_in, const int* in_sizes, int n_in,
                              void* d_out, int out_size)
{
    const float* x     = (const float*)d_in[0];
    const float* wq    = (const float*)d_in[1];
    const float* bq    = (const float*)d_in[2];
    const float* wk    = (const float*)d_in[3];
    const float* bk    = (const float*)d_in[4];
    const float* wv    = (const float*)d_in[5];
    const float* bv    = (const float*)d_in[6];
    const float* wo    = (const float*)d_in[7];
    const float* bo    = (const float*)d_in[8];
    const float* gamma = (const float*)d_in[9];
    float* out = (float*)d_out;

    float *pkT, *pqT, *pwor, *pvp, *pvpr, *ppart;
    __nv_bfloat16 *pvppb;
    cudaGetSymbolAddress((void**)&pkT,    g_kT);
    cudaGetSymbolAddress((void**)&pqT,    g_qT);
    cudaGetSymbolAddress((void**)&pwor,   g_wor);
    cudaGetSymbolAddress((void**)&pvp,    g_vpool);
    cudaGetSymbolAddress((void**)&pvpr,   g_vprime);
    cudaGetSymbolAddress((void**)&ppart,  g_part);
    cudaGetSymbolAddress((void**)&pvppb,  g_vppb);

    static cudaStream_t s1 = nullptr;
    static cudaEvent_t evFork = nullptr, evJoin = nullptr;
    if (s1 == nullptr) {
        cudaStreamCreateWithFlags(&s1, cudaStreamNonBlocking);
        cudaEventCreateWithFlags(&evFork, cudaEventDisableTiming);
        cudaEventCreateWithFlags(&evJoin, cudaEventDisableTiming);
        cudaFuncSetAttribute(attend_k, cudaFuncAttributeMaxDynamicSharedMemorySize,
                             AT4_SMEM_BYTES);
    }

    cudaEventRecord(evFork, 0);
    cudaStreamWaitEvent(s1, evFork, 0);

    // s1: V branch runs fully parallel to the QK chain
    round_wo_k<<<(CCH * CCH) / 1024, 256, 0, s1>>>(wo, pwor);
    {   // conv_v: vpool
        dim3 g(NSP / 128, CCH / 128, BATCH);
        conv_v_k<<<g, 256, 0, s1>>>(wv, bv, x, pvp);
    }
    {   // vprime
        dim3 g(NPOOL / 128, CCH / 128, BATCH);
        gemm_v2<<<g, 256, 0, s1>>>(pwor, pvp, pvpr, CCH, NPOOL, CCH);
    }
    cudaEventRecord(evJoin, s1);

    // main: conv_qk -> energy_cs
    {
        dim3 g(NSP / 128, 1, BATCH);
        conv_qk_k<<<g, 256>>>(wk, bk, wq, bq, x, pkT, pqT);
    }
    {
        dim3 g(NPOOL / 128, NSP / 128, BATCH);
        energy_cs<<<g, 256>>>(pkT, pqT, ppart);
    }

    // join, normalize -> v'' bf16, then attend (m-tile 64, 2 CTAs/SM)
    cudaStreamWaitEvent(0, evJoin, 0);
    {
        dim3 g(BATCH * NPOOL / 256, CCH / 32);
        norm_v_k<<<g, 256>>>(ppart, pvpr, pvppb);
    }
    {
        dim3 g(NSP / 64, 1, BATCH);
        attend_k<<<g, 256, AT4_SMEM_BYTES>>>(pkT, pqT, pvppb, bo, gamma, x, out);
    }
}